// round 2
// baseline (speedup 1.0000x reference)
#include <cuda_runtime.h>
#include <cstddef>

// Problem constants
#define BB   8
#define SS   1024
#define DD   1024
#define HH   16
#define DKK  64
// SCALE = sqrt(64)*2 = 16
#define INV_SCALE (1.0f/16.0f)

// ---------------- scratch (no cudaMalloc allowed) ----------------
__device__ float g_Q[BB*HH*SS*DKK];       // 8.4M floats, [B,H,S,dk]
__device__ float g_K[BB*HH*SS*DKK];
__device__ float g_V[BB*HH*SS*DKK];
__device__ float g_Ctx[BB*SS*DD];         // context back in [B,S,D]
__device__ float g_attn[(size_t)BB*HH*SS*SS]; // fallback if attn not in d_out

// ============================================================
// SGEMM:  C[m,n] = sum_k A[m,k] * W[n,k]   (A: [8192,1024], W: [1024,1024])
// mode 0/1/2: scatter into g_Q/g_K/g_V as [B,H,S,dk]
// mode 3:     A := g_Ctx, write plain row-major to Cout
// ============================================================
__global__ __launch_bounds__(256) void sgemm_nt(const float* __restrict__ Ain,
                                                const float* __restrict__ W,
                                                float* __restrict__ Cout,
                                                int mode)
{
    __shared__ float As[8][128];
    __shared__ float Bs[8][128];

    const float* A = (mode == 3) ? g_Ctx : Ain;

    int tid = threadIdx.x;
    int bm = blockIdx.y * 128;
    int bn = blockIdx.x * 128;

    int lr  = tid >> 1;          // 0..127
    int lc  = (tid & 1) * 4;     // 0 or 4

    const float* Aptr = A + (size_t)(bm + lr) * 1024 + lc;
    const float* Wptr = W + (size_t)(bn + lr) * 1024 + lc;

    int ty = tid >> 4;           // 0..15
    int tx = tid & 15;           // 0..15

    float acc[8][8];
#pragma unroll
    for (int i = 0; i < 8; i++)
#pragma unroll
        for (int j = 0; j < 8; j++) acc[i][j] = 0.0f;

    for (int kt = 0; kt < 1024; kt += 8) {
        float4 a4 = *(const float4*)(Aptr + kt);
        float4 b4 = *(const float4*)(Wptr + kt);
        __syncthreads();
        As[lc+0][lr] = a4.x; As[lc+1][lr] = a4.y; As[lc+2][lr] = a4.z; As[lc+3][lr] = a4.w;
        Bs[lc+0][lr] = b4.x; Bs[lc+1][lr] = b4.y; Bs[lc+2][lr] = b4.z; Bs[lc+3][lr] = b4.w;
        __syncthreads();
#pragma unroll
        for (int k = 0; k < 8; k++) {
            float ar[8], br[8];
#pragma unroll
            for (int i = 0; i < 8; i++) ar[i] = As[k][ty*8 + i];
#pragma unroll
            for (int j = 0; j < 8; j++) br[j] = Bs[k][tx*8 + j];
#pragma unroll
            for (int i = 0; i < 8; i++)
#pragma unroll
                for (int j = 0; j < 8; j++) acc[i][j] += ar[i] * br[j];
        }
    }

    // epilogue
#pragma unroll
    for (int i = 0; i < 8; i++) {
        int m  = bm + ty*8 + i;
        int n0 = bn + tx*8;
        float4 v0 = make_float4(acc[i][0], acc[i][1], acc[i][2], acc[i][3]);
        float4 v1 = make_float4(acc[i][4], acc[i][5], acc[i][6], acc[i][7]);
        if (mode == 3) {
            float4* dst = (float4*)(Cout + (size_t)m * 1024 + n0);
            dst[0] = v0; dst[1] = v1;
        } else {
            float* base = (mode == 0) ? g_Q : (mode == 1) ? g_K : g_V;
            int b = m >> 10, s = m & 1023;
            int h = n0 >> 6, dk = n0 & 63;
            float4* dst = (float4*)(base + (((size_t)(b*HH + h) * SS + s) * DKK + dk));
            dst[0] = v0; dst[1] = v1;
        }
    }
}

// ============================================================
// Scores + clip + causal mask + softmax -> attn (normalized) to global.
// One block = 32 query rows of one (b,h). 256 threads: 32 rows x 8 lanes.
// Full score row (1024) kept in dynamic smem; causal skips upper-tri compute.
// ============================================================
__global__ __launch_bounds__(256) void attn_scores(float* __restrict__ attn)
{
    extern __shared__ float smem[];
    float* sc = smem;                 // [32][1032]
    float* sK = smem + 32 * 1032;     // [64][68]

    int tid  = threadIdx.x;
    int r    = tid >> 3;              // 0..31
    int lane = tid & 7;               // 0..7
    int bh   = blockIdx.y;            // 0..127
    int row0 = blockIdx.x * 32;
    int qr   = row0 + r;

    // cache Q row in registers
    const float* qrow = g_Q + ((size_t)bh * SS + qr) * DKK;
    float qreg[64];
#pragma unroll
    for (int d4 = 0; d4 < 16; d4++) {
        float4 v = ((const float4*)qrow)[d4];
        qreg[d4*4+0] = v.x; qreg[d4*4+1] = v.y; qreg[d4*4+2] = v.z; qreg[d4*4+3] = v.w;
    }

    const float* Kbase = g_K + (size_t)bh * SS * DKK;
    int ktmax = (row0 + 31) >> 6;     // last K tile needed (causal)

    for (int kt = 0; kt <= ktmax; kt++) {
        __syncthreads();
        // stage 64x64 K tile
        {
            int lr = tid >> 2;            // 0..63
            int lc = (tid & 3) * 16;      // 0,16,32,48
            const float* src = Kbase + (size_t)(kt*64 + lr) * DKK + lc;
            float* dst = sK + lr * 68 + lc;
#pragma unroll
            for (int i = 0; i < 4; i++) {
                float4 v = *(const float4*)(src + 4*i);
                dst[4*i+0] = v.x; dst[4*i+1] = v.y; dst[4*i+2] = v.z; dst[4*i+3] = v.w;
            }
        }
        __syncthreads();

        float acc[8] = {0,0,0,0,0,0,0,0};
#pragma unroll
        for (int d = 0; d < 64; d++) {
            float qd = qreg[d];
#pragma unroll
            for (int j = 0; j < 8; j++)
                acc[j] += qd * sK[(lane + 8*j) * 68 + d];
        }
#pragma unroll
        for (int j = 0; j < 8; j++) {
            int c = kt*64 + lane + 8*j;
            float v = fminf(fmaxf(acc[j] * INV_SCALE, -30.0f), 30.0f);
            if (c > qr) v = -1.0e9f;
            sc[r*1032 + c] = v;
        }
    }

    // softmax over c in [0, qr]  (8 lanes per row; no cross-thread smem deps)
    float m = -1.0e30f;
    for (int c = lane; c <= qr; c += 8) m = fmaxf(m, sc[r*1032 + c]);
#pragma unroll
    for (int o = 4; o; o >>= 1) m = fmaxf(m, __shfl_xor_sync(0xffffffffu, m, o));

    float s = 0.0f;
    for (int c = lane; c <= qr; c += 8) {
        float e = __expf(sc[r*1032 + c] - m);
        sc[r*1032 + c] = e;
        s += e;
    }
#pragma unroll
    for (int o = 4; o; o >>= 1) s += __shfl_xor_sync(0xffffffffu, s, o);
    float inv = 1.0f / s;

    float* arow = attn + ((size_t)bh * SS + qr) * SS;
    for (int c = lane; c < 1024; c += 8)
        arow[c] = (c <= qr) ? sc[r*1032 + c] * inv : 0.0f;
}

// ============================================================
// context = attn @ V  per (b,h); causal -> only k-tiles <= row tile.
// Block: 64 rows x 64 dk output tile. Writes g_Ctx in [B,S,D] layout.
// ============================================================
__global__ __launch_bounds__(256) void attn_v(const float* __restrict__ attn)
{
    __shared__ float sA[64][65];
    __shared__ float sV[64][65];

    int bh = blockIdx.y;
    int rt = blockIdx.x;                // row tile
    int tid = threadIdx.x;
    int ty = tid >> 4, tx = tid & 15;

    const float* Arow = attn + ((size_t)bh * SS + rt*64) * SS;
    const float* Vb   = g_V + (size_t)bh * SS * DKK;

    float acc[4][4];
#pragma unroll
    for (int i = 0; i < 4; i++)
#pragma unroll
        for (int j = 0; j < 4; j++) acc[i][j] = 0.0f;

    for (int kt = 0; kt <= rt; kt++) {
        __syncthreads();
        {
            int lr = tid >> 2;
            int lc = (tid & 3) * 16;
            const float* as = Arow + (size_t)lr * SS + kt*64 + lc;
            const float* vs = Vb + (size_t)(kt*64 + lr) * DKK + lc;
#pragma unroll
            for (int i = 0; i < 4; i++) {
                float4 a = *(const float4*)(as + 4*i);
                sA[lr][lc+4*i+0] = a.x; sA[lr][lc+4*i+1] = a.y;
                sA[lr][lc+4*i+2] = a.z; sA[lr][lc+4*i+3] = a.w;
                float4 v = *(const float4*)(vs + 4*i);
                sV[lr][lc+4*i+0] = v.x; sV[lr][lc+4*i+1] = v.y;
                sV[lr][lc+4*i+2] = v.z; sV[lr][lc+4*i+3] = v.w;
            }
        }
        __syncthreads();
#pragma unroll
        for (int k = 0; k < 64; k++) {
            float a[4], v[4];
#pragma unroll
            for (int i = 0; i < 4; i++) a[i] = sA[ty*4+i][k];
#pragma unroll
            for (int j = 0; j < 4; j++) v[j] = sV[k][tx*4+j];
#pragma unroll
            for (int i = 0; i < 4; i++)
#pragma unroll
                for (int j = 0; j < 4; j++) acc[i][j] += a[i] * v[j];
        }
    }

    int b = bh >> 4, h = bh & 15;
#pragma unroll
    for (int i = 0; i < 4; i++) {
        float4 v = make_float4(acc[i][0], acc[i][1], acc[i][2], acc[i][3]);
        *(float4*)(g_Ctx + ((size_t)b * SS + rt*64 + ty*4 + i) * DD + h*DKK + tx*4) = v;
    }
}

// ============================================================
extern "C" void kernel_launch(void* const* d_in, const int* in_sizes, int n_in,
                              void* d_out, int out_size)
{
    (void)in_sizes; (void)n_in;
    const float* q  = (const float*)d_in[0];
    const float* k  = (const float*)d_in[1];
    const float* v  = (const float*)d_in[2];
    // d_in[3] = mask (int32 tril) — causal structure applied analytically
    const float* Wq = (const float*)d_in[4];
    const float* Wk = (const float*)d_in[5];
    const float* Wv = (const float*)d_in[6];
    const float* Wo = (const float*)d_in[7];
    float* out = (float*)d_out;

    const size_t OUTE  = (size_t)BB * SS * DD;            // 8,388,608
    const size_t ATTNE = (size_t)BB * HH * SS * SS;       // 134,217,728

    float* attn_ptr;
    bool write_out = true;
    size_t osz = (size_t)out_size;
    if (osz >= OUTE + ATTNE) {
        attn_ptr = out + OUTE;                 // (output, attn) concatenated
    } else if (osz == ATTNE) {
        attn_ptr = out;                        // attn only
        write_out = false;
    } else {
        void* p = nullptr;
        cudaGetSymbolAddress(&p, g_attn);      // output only; attn to scratch
        attn_ptr = (float*)p;
    }

    dim3 gg(8, 64);    // N/128, M/128
    sgemm_nt<<<gg, 256>>>(q, Wq, nullptr, 0);
    sgemm_nt<<<gg, 256>>>(k, Wk, nullptr, 1);
    sgemm_nt<<<gg, 256>>>(v, Wv, nullptr, 2);

    size_t smem = (size_t)(32*1032 + 64*68) * sizeof(float);   // 149,504 B
    cudaFuncSetAttribute(attn_scores, cudaFuncAttributeMaxDynamicSharedMemorySize, (int)smem);
    attn_scores<<<dim3(32, 128), 256, smem>>>(attn_ptr);

    attn_v<<<dim3(16, 128), 256>>>(attn_ptr);

    if (write_out)
        sgemm_nt<<<gg, 256>>>(nullptr, Wo, out, 3);
}

// round 5
// speedup vs baseline: 1.5144x; 1.5144x over previous
#include <cuda_runtime.h>
#include <cuda_bf16.h>
#include <cstdint>
#include <cstddef>

// Problem constants
#define BB   8
#define SS   1024
#define DD   1024
#define HH   16
#define DKK  64
#define INV_SCALE (1.0f/16.0f)   // SCALE = sqrt(64)*2 = 16

// ---------------- scratch (no cudaMalloc allowed) ----------------
__device__ __nv_bfloat16 g_Xhi[3u*8388608u];   // input splits q,k,v
__device__ __nv_bfloat16 g_Xlo[3u*8388608u];
__device__ __nv_bfloat16 g_Whi_[4u*1048576u];  // weight splits Wq,Wk,Wv,Wo
__device__ __nv_bfloat16 g_Wlo_[4u*1048576u];
__device__ float g_Q[BB*HH*SS*DKK];            // [B,H,S,dk] fp32
__device__ float g_K[BB*HH*SS*DKK];
__device__ float g_V[BB*HH*SS*DKK];
__device__ __nv_bfloat16 g_Chi[BB*SS*DD];      // ctx splits [B,S,D]
__device__ __nv_bfloat16 g_Clo[BB*SS*DD];
__device__ float g_attn[(size_t)BB*HH*SS*SS];  // fallback

__device__ __forceinline__ uint32_t s2u(const void* p) {
    return (uint32_t)__cvta_generic_to_shared(p);
}

// ================= split kernel =================
__global__ void split_kernel(const float* __restrict__ src, int n4, int kind, int slot)
{
    int i = blockIdx.x * blockDim.x + threadIdx.x;
    if (i >= n4) return;
    __nv_bfloat16* hi; __nv_bfloat16* lo;
    if (kind == 0) { hi = g_Xhi + (size_t)slot * 8388608u; lo = g_Xlo + (size_t)slot * 8388608u; }
    else           { hi = g_Whi_ + (size_t)slot * 1048576u; lo = g_Wlo_ + (size_t)slot * 1048576u; }
    float4 v = ((const float4*)src)[i];
    __nv_bfloat162 h01, h23, l01, l23;
    h01.x = __float2bfloat16(v.x); l01.x = __float2bfloat16(v.x - __bfloat162float(h01.x));
    h01.y = __float2bfloat16(v.y); l01.y = __float2bfloat16(v.y - __bfloat162float(h01.y));
    h23.x = __float2bfloat16(v.z); l23.x = __float2bfloat16(v.z - __bfloat162float(h23.x));
    h23.y = __float2bfloat16(v.w); l23.y = __float2bfloat16(v.w - __bfloat162float(h23.y));
    ((__nv_bfloat162*)hi)[i*2]   = h01; ((__nv_bfloat162*)hi)[i*2+1] = h23;
    ((__nv_bfloat162*)lo)[i*2]   = l01; ((__nv_bfloat162*)lo)[i*2+1] = l23;
}

// ================= HMMA (mma.sync) GEMM =================
// C[8192,1024] = Ahi·Whi^T + Ahi·Wlo^T + Alo·Whi^T  (bf16, fp32 accum)
// mode 0/1/2: A = input split slot, scatter fp32 to g_Q/g_K/g_V [B,H,S,dk]
// mode 3:     A = ctx split, write fp32 row-major to Cout
//
// CTA tile 128x128, BK=32, double-buffered smem, 80B row pitch
// (conflict-free for ldmatrix: row starts mod 32 words all distinct).
// 8 warps: warp grid 2(m) x 4(n), warp tile 64x32.

#define PITCH   80            // bytes per smem row (32 bf16 + 8 pad)
#define T_AHI   0
#define T_ALO   10240
#define T_WHI   20480
#define T_WLO   30720
#define STAGE_SZ 40960
#define GEMM_SMEM (2*STAGE_SZ)   // 81920 B

__device__ __forceinline__ void ldsm4(uint32_t* r, uint32_t addr) {
    asm volatile("ldmatrix.sync.aligned.m8n8.x4.shared.b16 {%0,%1,%2,%3}, [%4];"
                 : "=r"(r[0]), "=r"(r[1]), "=r"(r[2]), "=r"(r[3]) : "r"(addr));
}
__device__ __forceinline__ void mma16816(float* d, const uint32_t* a,
                                         uint32_t b0, uint32_t b1) {
    asm volatile("mma.sync.aligned.m16n8k16.row.col.f32.bf16.bf16.f32 "
        "{%0,%1,%2,%3}, {%4,%5,%6,%7}, {%8,%9}, {%0,%1,%2,%3};"
        : "+f"(d[0]), "+f"(d[1]), "+f"(d[2]), "+f"(d[3])
        : "r"(a[0]), "r"(a[1]), "r"(a[2]), "r"(a[3]), "r"(b0), "r"(b1));
}

__global__ __launch_bounds__(256) void mma_gemm(float* __restrict__ Cout, int mode)
{
    extern __shared__ __align__(128) char sm[];
    uint32_t sb = s2u(sm);

    int tid  = threadIdx.x;
    int wid  = tid >> 5, lane = tid & 31;
    int bm   = blockIdx.y * 128, bn = blockIdx.x * 128;
    int wm   = (wid & 1) * 64;        // warp m offset in CTA tile
    int wn   = (wid >> 1) * 32;       // warp n offset

    const __nv_bfloat16* Ah = (mode < 3) ? (g_Xhi + (size_t)mode * 8388608u) : g_Chi;
    const __nv_bfloat16* Al = (mode < 3) ? (g_Xlo + (size_t)mode * 8388608u) : g_Clo;
    const __nv_bfloat16* Wh = g_Whi_ + (size_t)mode * 1048576u;
    const __nv_bfloat16* Wl = g_Wlo_ + (size_t)mode * 1048576u;

    // global->smem mapping: 128 rows x 4 uint4 per tile; thread does 2 chunks/tile
    int c0 = tid, c1 = tid + 256;
    int r0 = c0 >> 2, q0 = c0 & 3;
    int r1 = c1 >> 2, q1 = c1 & 3;

    const __nv_bfloat16* gAh0 = Ah + (size_t)(bm + r0) * 1024 + q0 * 8;
    const __nv_bfloat16* gAh1 = Ah + (size_t)(bm + r1) * 1024 + q1 * 8;
    const __nv_bfloat16* gAl0 = Al + (size_t)(bm + r0) * 1024 + q0 * 8;
    const __nv_bfloat16* gAl1 = Al + (size_t)(bm + r1) * 1024 + q1 * 8;
    const __nv_bfloat16* gWh0 = Wh + (size_t)(bn + r0) * 1024 + q0 * 8;
    const __nv_bfloat16* gWh1 = Wh + (size_t)(bn + r1) * 1024 + q1 * 8;
    const __nv_bfloat16* gWl0 = Wl + (size_t)(bn + r0) * 1024 + q0 * 8;
    const __nv_bfloat16* gWl1 = Wl + (size_t)(bn + r1) * 1024 + q1 * 8;

    uint32_t sd0 = (uint32_t)(r0 * PITCH + q0 * 16);
    uint32_t sd1 = (uint32_t)(r1 * PITCH + q1 * 16);

    // ldmatrix per-lane base offsets
    // A frag (16x16): lanes 0-15 rows m0..m0+15 @k0; lanes 16-31 same rows @k0+8
    uint32_t offA = (uint32_t)((wm + (lane & 15)) * PITCH + (lane >> 4) * 16);
    // B x4 = frags (n0,k0),(n0,k8),(n0+8,k0),(n0+8,k8)
    uint32_t offB = (uint32_t)((wn + ((lane >> 4) & 1) * 8 + (lane & 7)) * PITCH
                               + ((lane >> 3) & 1) * 16);

    float acc[4][4][4];
#pragma unroll
    for (int i = 0; i < 4; i++)
#pragma unroll
        for (int j = 0; j < 4; j++)
#pragma unroll
            for (int t = 0; t < 4; t++) acc[i][j][t] = 0.0f;

    // prologue: load k-tile 0 into stage 0
    {
        char* st = sm;
        *(uint4*)(st + T_AHI + sd0) = *(const uint4*)gAh0;
        *(uint4*)(st + T_AHI + sd1) = *(const uint4*)gAh1;
        *(uint4*)(st + T_ALO + sd0) = *(const uint4*)gAl0;
        *(uint4*)(st + T_ALO + sd1) = *(const uint4*)gAl1;
        *(uint4*)(st + T_WHI + sd0) = *(const uint4*)gWh0;
        *(uint4*)(st + T_WHI + sd1) = *(const uint4*)gWh1;
        *(uint4*)(st + T_WLO + sd0) = *(const uint4*)gWl0;
        *(uint4*)(st + T_WLO + sd1) = *(const uint4*)gWl1;
    }

    for (int kt = 0; kt < 32; kt++) {
        __syncthreads();
        int s = kt & 1;
        uint32_t stg = sb + (uint32_t)s * STAGE_SZ;

        // fetch next k-tile into registers (overlap with compute)
        uint4 fAh0, fAh1, fAl0, fAl1, fWh0, fWh1, fWl0, fWl1;
        if (kt + 1 < 32) {
            size_t ko = (size_t)(kt + 1) * 32;
            fAh0 = *(const uint4*)(gAh0 + ko); fAh1 = *(const uint4*)(gAh1 + ko);
            fAl0 = *(const uint4*)(gAl0 + ko); fAl1 = *(const uint4*)(gAl1 + ko);
            fWh0 = *(const uint4*)(gWh0 + ko); fWh1 = *(const uint4*)(gWh1 + ko);
            fWl0 = *(const uint4*)(gWl0 + ko); fWl1 = *(const uint4*)(gWl1 + ko);
        }

#pragma unroll
        for (int kk = 0; kk < 2; kk++) {          // two k16 steps
            uint32_t k2 = (uint32_t)(kk * 32);    // 16 bf16 = 32 bytes
            uint32_t ah[4][4], al[4][4], bh[2][4], bl[2][4];
#pragma unroll
            for (int mf = 0; mf < 4; mf++) {
                ldsm4(ah[mf], stg + T_AHI + offA + mf * (16 * PITCH) + k2);
                ldsm4(al[mf], stg + T_ALO + offA + mf * (16 * PITCH) + k2);
            }
#pragma unroll
            for (int nf2 = 0; nf2 < 2; nf2++) {
                ldsm4(bh[nf2], stg + T_WHI + offB + nf2 * (16 * PITCH) + k2);
                ldsm4(bl[nf2], stg + T_WLO + offB + nf2 * (16 * PITCH) + k2);
            }
#pragma unroll
            for (int mf = 0; mf < 4; mf++)
#pragma unroll
                for (int nf = 0; nf < 4; nf++) {
                    int n2 = nf >> 1, hi = (nf & 1) * 2;
                    mma16816(acc[mf][nf], ah[mf], bh[n2][hi], bh[n2][hi + 1]);
                    mma16816(acc[mf][nf], ah[mf], bl[n2][hi], bl[n2][hi + 1]);
                    mma16816(acc[mf][nf], al[mf], bh[n2][hi], bh[n2][hi + 1]);
                }
        }

        if (kt + 1 < 32) {
            char* st = sm + (s ^ 1) * STAGE_SZ;
            *(uint4*)(st + T_AHI + sd0) = fAh0; *(uint4*)(st + T_AHI + sd1) = fAh1;
            *(uint4*)(st + T_ALO + sd0) = fAl0; *(uint4*)(st + T_ALO + sd1) = fAl1;
            *(uint4*)(st + T_WHI + sd0) = fWh0; *(uint4*)(st + T_WHI + sd1) = fWh1;
            *(uint4*)(st + T_WLO + sd0) = fWl0; *(uint4*)(st + T_WLO + sd1) = fWl1;
        }
    }

    // epilogue: C frag: d0,d1 -> (row l/4, col (l%4)*2), d2,d3 -> row+8
    int lr = lane >> 2, lc = (lane & 3) * 2;
#pragma unroll
    for (int mf = 0; mf < 4; mf++)
#pragma unroll
        for (int nf = 0; nf < 4; nf++) {
            int r = bm + wm + mf * 16 + lr;
            int c = bn + wn + nf * 8 + lc;
            float2 v0 = make_float2(acc[mf][nf][0], acc[mf][nf][1]);
            float2 v1 = make_float2(acc[mf][nf][2], acc[mf][nf][3]);
            if (mode == 3) {
                *(float2*)(Cout + (size_t)r * 1024 + c)       = v0;
                *(float2*)(Cout + (size_t)(r + 8) * 1024 + c) = v1;
            } else {
                float* base = (mode == 0) ? g_Q : (mode == 1) ? g_K : g_V;
                int h = c >> 6, dk = c & 63;
                int b0i = r >> 10, s0 = r & 1023;
                int b1i = (r + 8) >> 10, s1 = (r + 8) & 1023;
                *(float2*)(base + (((size_t)(b0i*HH + h) * SS + s0) << 6) + dk) = v0;
                *(float2*)(base + (((size_t)(b1i*HH + h) * SS + s1) << 6) + dk) = v1;
            }
        }
}

// ================= scores + softmax -> attn =================
// block = 16 query rows of one (b,h); 256 threads = 16 rows x 16 lanes.
__global__ __launch_bounds__(256) void attn_scores(float* __restrict__ attn)
{
    extern __shared__ float smem[];
    float* sc = smem;                  // [16][1032]
    float* sK = smem + 16 * 1032;      // [64][68]

    int tid  = threadIdx.x;
    int r    = tid >> 4;               // 0..15
    int lane = tid & 15;               // 0..15
    int bh   = blockIdx.y;
    int row0 = blockIdx.x * 16;
    int qr   = row0 + r;

    const float* qrow = g_Q + ((size_t)bh * SS + qr) * DKK;
    float4 q4[16];
#pragma unroll
    for (int d4 = 0; d4 < 16; d4++) q4[d4] = ((const float4*)qrow)[d4];

    const float* Kb = g_K + (size_t)bh * SS * DKK;
    int ktmax = (row0 + 15) >> 6;

    for (int kt = 0; kt <= ktmax; kt++) {
        __syncthreads();
        {   // stage 64x64 K tile
            int lr = tid >> 2;
            int lc = (tid & 3) * 16;
            const float* src = Kb + (size_t)(kt*64 + lr) * DKK + lc;
#pragma unroll
            for (int i = 0; i < 4; i++)
                *(float4*)&sK[lr*68 + lc + 4*i] = ((const float4*)src)[i];
        }
        __syncthreads();

        float acc[4] = {0, 0, 0, 0};
        const float4* sK4 = (const float4*)sK;
#pragma unroll
        for (int d4 = 0; d4 < 16; d4++) {
            float4 q = q4[d4];
#pragma unroll
            for (int j = 0; j < 4; j++) {
                float4 kv = sK4[(lane + 16*j) * 17 + d4];
                acc[j] = fmaf(q.x, kv.x, fmaf(q.y, kv.y, fmaf(q.z, kv.z, fmaf(q.w, kv.w, acc[j]))));
            }
        }
#pragma unroll
        for (int j = 0; j < 4; j++) {
            int c = kt*64 + lane + 16*j;
            float v = fminf(fmaxf(acc[j] * INV_SCALE, -30.0f), 30.0f);
            if (c > qr) v = -1.0e9f;
            sc[r*1032 + c] = v;
        }
    }

    // softmax over [0, qr]; 16 lanes per row
    float mx = -1.0e30f;
    for (int c = lane; c <= qr; c += 16) mx = fmaxf(mx, sc[r*1032 + c]);
#pragma unroll
    for (int o = 8; o; o >>= 1) mx = fmaxf(mx, __shfl_xor_sync(0xffffffffu, mx, o));

    float s = 0.0f;
    for (int c = lane; c <= qr; c += 16) {
        float e = __expf(sc[r*1032 + c] - mx);
        sc[r*1032 + c] = e;
        s += e;
    }
#pragma unroll
    for (int o = 8; o; o >>= 1) s += __shfl_xor_sync(0xffffffffu, s, o);
    float inv = 1.0f / s;

    float* arow = attn + ((size_t)bh * SS + qr) * SS;
    for (int t = lane; t < 256; t += 16) {
        int c = t * 4;
        float4 v;
        v.x = (c+0 <= qr) ? sc[r*1032 + c+0] * inv : 0.0f;
        v.y = (c+1 <= qr) ? sc[r*1032 + c+1] * inv : 0.0f;
        v.z = (c+2 <= qr) ? sc[r*1032 + c+2] * inv : 0.0f;
        v.w = (c+3 <= qr) ? sc[r*1032 + c+3] * inv : 0.0f;
        ((float4*)arow)[t] = v;
    }
}

// ================= context = attn @ V; split ctx to bf16 hi/lo =================
// block: 128 rows x 64 dk of one (b,h). 256 threads = 16x16; thread: 8 rows x 4 cols
__global__ __launch_bounds__(256) void attn_v(const float* __restrict__ attn)
{
    extern __shared__ float sm2[];
    float* sAT = sm2;              // [64][132] transposed attn tile
    float* sV  = sm2 + 64*132;     // [64][68]

    int bh  = blockIdx.y;
    int rt  = blockIdx.x;          // 0..7
    int tid = threadIdx.x;
    int ty = tid >> 4, tx = tid & 15;

    const float* Ab = attn + ((size_t)bh * SS + rt*128) * SS;
    const float* Vb = g_V + (size_t)bh * SS * DKK;

    float acc[8][4];
#pragma unroll
    for (int i = 0; i < 8; i++)
#pragma unroll
        for (int j = 0; j < 4; j++) acc[i][j] = 0.0f;

    int ktmax = rt*2 + 1;
    for (int kt = 0; kt <= ktmax; kt++) {
        __syncthreads();
        {   // load attn 128x64 transposed
            int m  = tid & 127;
            int kc = (tid >> 7) * 32;
            const float* src = Ab + (size_t)m * SS + kt*64 + kc;
#pragma unroll
            for (int i = 0; i < 8; i++) {
                float4 a = ((const float4*)src)[i];
                int k = kc + i*4;
                sAT[(k+0)*132 + m] = a.x; sAT[(k+1)*132 + m] = a.y;
                sAT[(k+2)*132 + m] = a.z; sAT[(k+3)*132 + m] = a.w;
            }
        }
        {   // load V 64x64
            int lr = tid >> 2;
            int lc = (tid & 3) * 16;
            const float* src = Vb + (size_t)(kt*64 + lr) * DKK + lc;
#pragma unroll
            for (int i = 0; i < 4; i++)
                *(float4*)&sV[lr*68 + lc + 4*i] = ((const float4*)src)[i];
        }
        __syncthreads();
#pragma unroll
        for (int k = 0; k < 64; k++) {
            float4 a0 = *(float4*)&sAT[k*132 + ty*8];
            float4 a1 = *(float4*)&sAT[k*132 + ty*8 + 4];
            float4 v  = *(float4*)&sV[k*68 + tx*4];
            float av[8] = {a0.x, a0.y, a0.z, a0.w, a1.x, a1.y, a1.z, a1.w};
#pragma unroll
            for (int i = 0; i < 8; i++) {
                acc[i][0] = fmaf(av[i], v.x, acc[i][0]);
                acc[i][1] = fmaf(av[i], v.y, acc[i][1]);
                acc[i][2] = fmaf(av[i], v.z, acc[i][2]);
                acc[i][3] = fmaf(av[i], v.w, acc[i][3]);
            }
        }
    }

    // epilogue: split ctx into bf16 hi/lo at [B,S,D]
    int b = bh >> 4, h = bh & 15;
#pragma unroll
    for (int i = 0; i < 8; i++) {
        int m = rt*128 + ty*8 + i;
        size_t off = ((size_t)b * SS + m) * DD + h*DKK + tx*4;
        __nv_bfloat162 h01, h23, l01, l23;
        h01.x = __float2bfloat16(acc[i][0]); l01.x = __float2bfloat16(acc[i][0] - __bfloat162float(h01.x));
        h01.y = __float2bfloat16(acc[i][1]); l01.y = __float2bfloat16(acc[i][1] - __bfloat162float(h01.y));
        h23.x = __float2bfloat16(acc[i][2]); l23.x = __float2bfloat16(acc[i][2] - __bfloat162float(h23.x));
        h23.y = __float2bfloat16(acc[i][3]); l23.y = __float2bfloat16(acc[i][3] - __bfloat162float(h23.y));
        *(__nv_bfloat162*)(g_Chi + off)     = h01;
        *(__nv_bfloat162*)(g_Chi + off + 2) = h23;
        *(__nv_bfloat162*)(g_Clo + off)     = l01;
        *(__nv_bfloat162*)(g_Clo + off + 2) = l23;
    }
}

// ============================================================
extern "C" void kernel_launch(void* const* d_in, const int* in_sizes, int n_in,
                              void* d_out, int out_size)
{
    (void)in_sizes; (void)n_in;
    const float* q  = (const float*)d_in[0];
    const float* k  = (const float*)d_in[1];
    const float* v  = (const float*)d_in[2];
    const float* Wq = (const float*)d_in[4];
    const float* Wk = (const float*)d_in[5];
    const float* Wv = (const float*)d_in[6];
    const float* Wo = (const float*)d_in[7];
    float* out = (float*)d_out;

    const size_t OUTE  = (size_t)BB * SS * DD;        // 8,388,608
    const size_t ATTNE = (size_t)BB * HH * SS * SS;   // 134,217,728

    float* attn_ptr;
    bool write_out = true;
    size_t osz = (size_t)out_size;
    if (osz >= OUTE + ATTNE) {
        attn_ptr = out + OUTE;
    } else if (osz == ATTNE) {
        attn_ptr = out;
        write_out = false;
    } else {
        void* p = nullptr;
        cudaGetSymbolAddress(&p, g_attn);
        attn_ptr = (float*)p;
    }

    // 1. bf16 splits
    split_kernel<<<2097152/256, 256>>>(q, 2097152, 0, 0);
    split_kernel<<<2097152/256, 256>>>(k, 2097152, 0, 1);
    split_kernel<<<2097152/256, 256>>>(v, 2097152, 0, 2);
    split_kernel<<<262144/256, 256>>>(Wq, 262144, 1, 0);
    split_kernel<<<262144/256, 256>>>(Wk, 262144, 1, 1);
    split_kernel<<<262144/256, 256>>>(Wv, 262144, 1, 2);
    split_kernel<<<262144/256, 256>>>(Wo, 262144, 1, 3);

    // 2. projections on HMMA tensor cores
    cudaFuncSetAttribute(mma_gemm, cudaFuncAttributeMaxDynamicSharedMemorySize, GEMM_SMEM);
    dim3 gg(8, 64);
    mma_gemm<<<gg, 256, GEMM_SMEM>>>(nullptr, 0);
    mma_gemm<<<gg, 256, GEMM_SMEM>>>(nullptr, 1);
    mma_gemm<<<gg, 256, GEMM_SMEM>>>(nullptr, 2);

    // 3. scores + softmax
    size_t smem_sc = (size_t)(16*1032 + 64*68) * sizeof(float);  // 83,456
    cudaFuncSetAttribute(attn_scores, cudaFuncAttributeMaxDynamicSharedMemorySize, (int)smem_sc);
    attn_scores<<<dim3(64, 128), 256, smem_sc>>>(attn_ptr);

    // 4. context (+ bf16 split epilogue)
    size_t smem_av = (size_t)(64*132 + 64*68) * sizeof(float);   // 51,200
    cudaFuncSetAttribute(attn_v, cudaFuncAttributeMaxDynamicSharedMemorySize, (int)smem_av);
    attn_v<<<dim3(8, 128), 256, smem_av>>>(attn_ptr);

    // 5. output projection on HMMA tensor cores
    if (write_out)
        mma_gemm<<<gg, 256, GEMM_SMEM>>>(out, 3);
}

// round 6
// speedup vs baseline: 2.0238x; 1.3364x over previous
#include <cuda_runtime.h>
#include <cuda_bf16.h>
#include <cstdint>
#include <cstddef>

// Problem constants
#define BB   8
#define SS   1024
#define DD   1024
#define HH   16
#define DKK  64
#define INV_SCALE (1.0f/16.0f)   // SCALE = sqrt(64)*2 = 16

// ---------------- scratch (no cudaMalloc allowed) ----------------
__device__ __nv_bfloat16 g_Xhi[3u*8388608u];   // input splits q,k,v
__device__ __nv_bfloat16 g_Xlo[3u*8388608u];
__device__ __nv_bfloat16 g_Whi_[4u*1048576u];  // weight splits Wq,Wk,Wv,Wo
__device__ __nv_bfloat16 g_Wlo_[4u*1048576u];
__device__ __nv_bfloat16 g_Qhi[BB*HH*SS*DKK];  // [B,H,S,dk] bf16 splits
__device__ __nv_bfloat16 g_Qlo[BB*HH*SS*DKK];
__device__ __nv_bfloat16 g_Khi[BB*HH*SS*DKK];
__device__ __nv_bfloat16 g_Klo[BB*HH*SS*DKK];
__device__ float g_V[BB*HH*SS*DKK];            // [B,H,S,dk] fp32
__device__ __nv_bfloat16 g_Chi[BB*SS*DD];      // ctx splits [B,S,D]
__device__ __nv_bfloat16 g_Clo[BB*SS*DD];
__device__ float g_attn[(size_t)BB*HH*SS*SS];  // fallback

__device__ __forceinline__ uint32_t s2u(const void* p) {
    return (uint32_t)__cvta_generic_to_shared(p);
}
#define CP_ASYNC16(dst, src) \
    asm volatile("cp.async.cg.shared.global [%0], [%1], 16;" :: "r"(dst), "l"(src))
#define CP_COMMIT() asm volatile("cp.async.commit_group;" ::: "memory")
#define CP_WAIT(n)  asm volatile("cp.async.wait_group %0;" :: "n"(n) : "memory")

__device__ __forceinline__ void ldsm4(uint32_t* r, uint32_t addr) {
    asm volatile("ldmatrix.sync.aligned.m8n8.x4.shared.b16 {%0,%1,%2,%3}, [%4];"
                 : "=r"(r[0]), "=r"(r[1]), "=r"(r[2]), "=r"(r[3]) : "r"(addr));
}
__device__ __forceinline__ void mma16816(float* d, const uint32_t* a,
                                         uint32_t b0, uint32_t b1) {
    asm volatile("mma.sync.aligned.m16n8k16.row.col.f32.bf16.bf16.f32 "
        "{%0,%1,%2,%3}, {%4,%5,%6,%7}, {%8,%9}, {%0,%1,%2,%3};"
        : "+f"(d[0]), "+f"(d[1]), "+f"(d[2]), "+f"(d[3])
        : "r"(a[0]), "r"(a[1]), "r"(a[2]), "r"(a[3]), "r"(b0), "r"(b1));
}

// ================= split kernel =================
__global__ void split_kernel(const float* __restrict__ src, int n4, int kind, int slot)
{
    int i = blockIdx.x * blockDim.x + threadIdx.x;
    if (i >= n4) return;
    __nv_bfloat16* hi; __nv_bfloat16* lo;
    if (kind == 0) { hi = g_Xhi + (size_t)slot * 8388608u; lo = g_Xlo + (size_t)slot * 8388608u; }
    else           { hi = g_Whi_ + (size_t)slot * 1048576u; lo = g_Wlo_ + (size_t)slot * 1048576u; }
    float4 v = ((const float4*)src)[i];
    __nv_bfloat162 h01, h23, l01, l23;
    h01.x = __float2bfloat16(v.x); l01.x = __float2bfloat16(v.x - __bfloat162float(h01.x));
    h01.y = __float2bfloat16(v.y); l01.y = __float2bfloat16(v.y - __bfloat162float(h01.y));
    h23.x = __float2bfloat16(v.z); l23.x = __float2bfloat16(v.z - __bfloat162float(h23.x));
    h23.y = __float2bfloat16(v.w); l23.y = __float2bfloat16(v.w - __bfloat162float(h23.y));
    ((__nv_bfloat162*)hi)[i*2]   = h01; ((__nv_bfloat162*)hi)[i*2+1] = h23;
    ((__nv_bfloat162*)lo)[i*2]   = l01; ((__nv_bfloat162*)lo)[i*2+1] = l23;
}

// ================= HMMA GEMM, cp.async 4-stage pipeline =================
// C = Ahi·Whi^T + Ahi·Wlo^T + Alo·Whi^T (bf16, fp32 accum)
// mode 0: -> g_Qhi/g_Qlo (bf16 split)   mode 1: -> g_Khi/g_Klo
// mode 2: -> g_V fp32                   mode 3: ctx -> Cout fp32
#define PITCH    80
#define T_AHI    0
#define T_ALO    10240
#define T_WHI    20480
#define T_WLO    30720
#define STAGE_SZ 40960
#define N_STAGES 4
#define GEMM_SMEM (N_STAGES*STAGE_SZ)   // 163840 B

__global__ __launch_bounds__(256) void mma_gemm(float* __restrict__ Cout, int mode)
{
    extern __shared__ __align__(128) char sm[];
    uint32_t sb = s2u(sm);

    int tid  = threadIdx.x;
    int wid  = tid >> 5, lane = tid & 31;
    int bm   = blockIdx.y * 128, bn = blockIdx.x * 128;
    int wm   = (wid & 1) * 64;
    int wn   = (wid >> 1) * 32;

    const __nv_bfloat16* Ah = (mode < 3) ? (g_Xhi + (size_t)mode * 8388608u) : g_Chi;
    const __nv_bfloat16* Al = (mode < 3) ? (g_Xlo + (size_t)mode * 8388608u) : g_Clo;
    const __nv_bfloat16* Wh = g_Whi_ + (size_t)mode * 1048576u;
    const __nv_bfloat16* Wl = g_Wlo_ + (size_t)mode * 1048576u;

    // each thread copies 2 16B chunks per tile: c0=tid, c1=tid+256 (128 rows x 4 quads)
    int c0 = tid, c1 = tid + 256;
    int r0 = c0 >> 2, q0 = c0 & 3;
    int r1 = c1 >> 2, q1 = c1 & 3;
    const __nv_bfloat16* gAh0 = Ah + (size_t)(bm + r0) * 1024 + q0 * 8;
    const __nv_bfloat16* gAh1 = Ah + (size_t)(bm + r1) * 1024 + q1 * 8;
    const __nv_bfloat16* gAl0 = Al + (size_t)(bm + r0) * 1024 + q0 * 8;
    const __nv_bfloat16* gAl1 = Al + (size_t)(bm + r1) * 1024 + q1 * 8;
    const __nv_bfloat16* gWh0 = Wh + (size_t)(bn + r0) * 1024 + q0 * 8;
    const __nv_bfloat16* gWh1 = Wh + (size_t)(bn + r1) * 1024 + q1 * 8;
    const __nv_bfloat16* gWl0 = Wl + (size_t)(bn + r0) * 1024 + q0 * 8;
    const __nv_bfloat16* gWl1 = Wl + (size_t)(bn + r1) * 1024 + q1 * 8;
    uint32_t sd0 = (uint32_t)(r0 * PITCH + q0 * 16);
    uint32_t sd1 = (uint32_t)(r1 * PITCH + q1 * 16);

    uint32_t offA = (uint32_t)((wm + (lane & 15)) * PITCH + (lane >> 4) * 16);
    uint32_t offB = (uint32_t)((wn + ((lane >> 4) & 1) * 8 + (lane & 7)) * PITCH
                               + ((lane >> 3) & 1) * 16);

    float acc[4][4][4];
#pragma unroll
    for (int i = 0; i < 4; i++)
#pragma unroll
        for (int j = 0; j < 4; j++)
#pragma unroll
            for (int t = 0; t < 4; t++) acc[i][j][t] = 0.0f;

    auto issue_stage = [&](int kt, int s) {
        uint32_t st = sb + (uint32_t)s * STAGE_SZ;
        size_t ko = (size_t)kt * 32;
        CP_ASYNC16(st + T_AHI + sd0, gAh0 + ko); CP_ASYNC16(st + T_AHI + sd1, gAh1 + ko);
        CP_ASYNC16(st + T_ALO + sd0, gAl0 + ko); CP_ASYNC16(st + T_ALO + sd1, gAl1 + ko);
        CP_ASYNC16(st + T_WHI + sd0, gWh0 + ko); CP_ASYNC16(st + T_WHI + sd1, gWh1 + ko);
        CP_ASYNC16(st + T_WLO + sd0, gWl0 + ko); CP_ASYNC16(st + T_WLO + sd1, gWl1 + ko);
    };

    // prologue: stages 0..2
    issue_stage(0, 0); CP_COMMIT();
    issue_stage(1, 1); CP_COMMIT();
    issue_stage(2, 2); CP_COMMIT();

    for (int kt = 0; kt < 32; kt++) {
        int s = kt & 3;
        CP_WAIT(2);
        __syncthreads();
        if (kt + 3 < 32) issue_stage(kt + 3, (kt + 3) & 3);
        CP_COMMIT();                     // always commit (empty groups keep count)

        uint32_t stg = sb + (uint32_t)s * STAGE_SZ;
#pragma unroll
        for (int kk = 0; kk < 2; kk++) {
            uint32_t k2 = (uint32_t)(kk * 32);
            uint32_t ah[4][4], al[4][4], bhf[2][4], blf[2][4];
#pragma unroll
            for (int mf = 0; mf < 4; mf++) {
                ldsm4(ah[mf], stg + T_AHI + offA + mf * (16 * PITCH) + k2);
                ldsm4(al[mf], stg + T_ALO + offA + mf * (16 * PITCH) + k2);
            }
#pragma unroll
            for (int nf2 = 0; nf2 < 2; nf2++) {
                ldsm4(bhf[nf2], stg + T_WHI + offB + nf2 * (16 * PITCH) + k2);
                ldsm4(blf[nf2], stg + T_WLO + offB + nf2 * (16 * PITCH) + k2);
            }
#pragma unroll
            for (int mf = 0; mf < 4; mf++)
#pragma unroll
                for (int nf = 0; nf < 4; nf++) {
                    int n2 = nf >> 1, hi = (nf & 1) * 2;
                    mma16816(acc[mf][nf], ah[mf], bhf[n2][hi], bhf[n2][hi + 1]);
                    mma16816(acc[mf][nf], ah[mf], blf[n2][hi], blf[n2][hi + 1]);
                    mma16816(acc[mf][nf], al[mf], bhf[n2][hi], bhf[n2][hi + 1]);
                }
        }
    }

    // epilogue
    int lr = lane >> 2, lc = (lane & 3) * 2;
#pragma unroll
    for (int mf = 0; mf < 4; mf++)
#pragma unroll
        for (int nf = 0; nf < 4; nf++) {
            int r = bm + wm + mf * 16 + lr;
            int c = bn + wn + nf * 8 + lc;
            float2 v0 = make_float2(acc[mf][nf][0], acc[mf][nf][1]);
            float2 v1 = make_float2(acc[mf][nf][2], acc[mf][nf][3]);
            if (mode == 3) {
                *(float2*)(Cout + (size_t)r * 1024 + c)       = v0;
                *(float2*)(Cout + (size_t)(r + 8) * 1024 + c) = v1;
            } else {
                int h = c >> 6, dk = c & 63;
                int b0i = r >> 10, s0 = r & 1023;
                int b1i = (r + 8) >> 10, s1 = (r + 8) & 1023;
                size_t o0 = (((size_t)(b0i*HH + h) * SS + s0) << 6) + dk;
                size_t o1 = (((size_t)(b1i*HH + h) * SS + s1) << 6) + dk;
                if (mode == 2) {
                    *(float2*)(g_V + o0) = v0;
                    *(float2*)(g_V + o1) = v1;
                } else {
                    __nv_bfloat16* ghi = (mode == 0) ? g_Qhi : g_Khi;
                    __nv_bfloat16* glo = (mode == 0) ? g_Qlo : g_Klo;
                    __nv_bfloat162 h0, l0, h1, l1;
                    h0.x = __float2bfloat16(v0.x); l0.x = __float2bfloat16(v0.x - __bfloat162float(h0.x));
                    h0.y = __float2bfloat16(v0.y); l0.y = __float2bfloat16(v0.y - __bfloat162float(h0.y));
                    h1.x = __float2bfloat16(v1.x); l1.x = __float2bfloat16(v1.x - __bfloat162float(h1.x));
                    h1.y = __float2bfloat16(v1.y); l1.y = __float2bfloat16(v1.y - __bfloat162float(h1.y));
                    *(__nv_bfloat162*)(ghi + o0) = h0; *(__nv_bfloat162*)(glo + o0) = l0;
                    *(__nv_bfloat162*)(ghi + o1) = h1; *(__nv_bfloat162*)(glo + o1) = l1;
                }
            }
        }
}

// ================= scores on HMMA + softmax -> attn =================
// block = 32 q-rows of one (b,h); 8 warps (2m x 4n), n-tiles of 64 keys,
// 3-term bf16-split scores, K double-buffered via cp.async.
#define SCP 1032
#define QK_PITCH 144
#define SC_BYTES (32*SCP*4)          // 132096
#define QT_SZ    (32*QK_PITCH)       // 4608
#define KST_SZ   (2*64*QK_PITCH)     // 18432 per stage (hi+lo)
#define SCORES_SMEM (SC_BYTES + 2*QT_SZ + 2*KST_SZ)   // 178176

__global__ __launch_bounds__(256) void attn_scores(float* __restrict__ attn)
{
    extern __shared__ __align__(128) char smraw[];
    float* sc = (float*)smraw;
    uint32_t sb = s2u(smraw);
    uint32_t sQh = sb + SC_BYTES;
    uint32_t sQl = sQh + QT_SZ;
    uint32_t sK  = sQl + QT_SZ;      // stage s at sK + s*KST_SZ; Khi at 0, Klo at 9216

    int tid  = threadIdx.x;
    int wid  = tid >> 5, lane = tid & 31;
    int bh   = blockIdx.y;
    int row0 = blockIdx.x * 32;
    int wm   = (wid & 1) * 16;
    int wn   = (wid >> 1) * 16;

    const __nv_bfloat16* Qh = g_Qhi + ((size_t)bh * SS + row0) * DKK;
    const __nv_bfloat16* Ql = g_Qlo + ((size_t)bh * SS + row0) * DKK;
    const __nv_bfloat16* Kh = g_Khi + (size_t)bh * SS * DKK;
    const __nv_bfloat16* Kl = g_Klo + (size_t)bh * SS * DKK;

    // load Q tile (32 rows x 64 bf16, hi+lo): 256 chunks each, 1 per thread
    {
        int r = tid >> 3, q = tid & 7;
        uint32_t d = (uint32_t)(r * QK_PITCH + q * 16);
        *(uint4*)(smraw + (sQh - sb) + d) = *(const uint4*)(Qh + (size_t)r * 64 + q * 8);
        *(uint4*)(smraw + (sQl - sb) + d) = *(const uint4*)(Ql + (size_t)r * 64 + q * 8);
    }

    int ntmax = (row0 + 31) >> 6;

    auto issue_K = [&](int nt, int st) {
        uint32_t kb = sK + (uint32_t)st * KST_SZ;
#pragma unroll
        for (int i = 0; i < 2; i++) {
            int c = i * 256 + tid;           // 0..511
            int r = c >> 3, q = c & 7;
            const __nv_bfloat16* srcH = Kh + (size_t)(nt * 64 + r) * 64 + q * 8;
            const __nv_bfloat16* srcL = Kl + (size_t)(nt * 64 + r) * 64 + q * 8;
            uint32_t d = (uint32_t)(r * QK_PITCH + q * 16);
            CP_ASYNC16(kb + d, srcH);
            CP_ASYNC16(kb + 9216 + d, srcL);
        }
    };

    issue_K(0, 0); CP_COMMIT();

    uint32_t offA = (uint32_t)((wm + (lane & 15)) * QK_PITCH + (lane >> 4) * 16);
    uint32_t offB = (uint32_t)((wn + ((lane >> 4) & 1) * 8 + (lane & 7)) * QK_PITCH
                               + ((lane >> 3) & 1) * 16);
    int lr = lane >> 2, lc = (lane & 3) * 2;

    for (int nt = 0; nt <= ntmax; nt++) {
        int st = nt & 1;
        CP_WAIT(0);
        __syncthreads();
        if (nt + 1 <= ntmax) issue_K(nt + 1, st ^ 1);
        CP_COMMIT();

        uint32_t kb = sK + (uint32_t)st * KST_SZ;
        float acc[2][4];
#pragma unroll
        for (int nf = 0; nf < 2; nf++)
#pragma unroll
            for (int t = 0; t < 4; t++) acc[nf][t] = 0.0f;

#pragma unroll
        for (int kk = 0; kk < 4; kk++) {
            uint32_t k2 = (uint32_t)(kk * 32);
            uint32_t ah[4], al[4], bhf[4], blf[4];
            ldsm4(ah, sQh + offA + k2);
            ldsm4(al, sQl + offA + k2);
            ldsm4(bhf, kb + offB + k2);
            ldsm4(blf, kb + 9216 + offB + k2);
#pragma unroll
            for (int nf = 0; nf < 2; nf++) {
                int hi = nf * 2;
                mma16816(acc[nf], ah, bhf[hi], bhf[hi + 1]);
                mma16816(acc[nf], ah, blf[hi], blf[hi + 1]);
                mma16816(acc[nf], al, bhf[hi], bhf[hi + 1]);
            }
        }

        // scale, clip, causal mask, store to score rows
#pragma unroll
        for (int nf = 0; nf < 2; nf++)
#pragma unroll
            for (int half = 0; half < 2; half++) {
                int row = wm + lr + half * 8;
                int qr  = row0 + row;
                int c   = nt * 64 + wn + nf * 8 + lc;
                float v0 = fminf(fmaxf(acc[nf][half*2+0] * INV_SCALE, -30.0f), 30.0f);
                float v1 = fminf(fmaxf(acc[nf][half*2+1] * INV_SCALE, -30.0f), 30.0f);
                if (c     > qr) v0 = -1.0e9f;
                if (c + 1 > qr) v1 = -1.0e9f;
                sc[row * SCP + c]     = v0;
                sc[row * SCP + c + 1] = v1;
            }
        __syncthreads();
    }

    // softmax: 32 rows x 8 lanes
    int r = tid >> 3, lane8 = tid & 7;
    int qr = row0 + r;
    float mx = -1.0e30f;
    for (int c = lane8; c <= qr; c += 8) mx = fmaxf(mx, sc[r*SCP + c]);
#pragma unroll
    for (int o = 4; o; o >>= 1) mx = fmaxf(mx, __shfl_xor_sync(0xffffffffu, mx, o));

    float s = 0.0f;
    for (int c = lane8; c <= qr; c += 8) {
        float e = __expf(sc[r*SCP + c] - mx);
        sc[r*SCP + c] = e;
        s += e;
    }
#pragma unroll
    for (int o = 4; o; o >>= 1) s += __shfl_xor_sync(0xffffffffu, s, o);
    float inv = 1.0f / s;

    float* arow = attn + ((size_t)bh * SS + qr) * SS;
    for (int t = lane8; t < 256; t += 8) {
        int c = t * 4;
        float4 v;
        v.x = (c+0 <= qr) ? sc[r*SCP + c+0] * inv : 0.0f;
        v.y = (c+1 <= qr) ? sc[r*SCP + c+1] * inv : 0.0f;
        v.z = (c+2 <= qr) ? sc[r*SCP + c+2] * inv : 0.0f;
        v.w = (c+3 <= qr) ? sc[r*SCP + c+3] * inv : 0.0f;
        ((float4*)arow)[t] = v;
    }
}

// ================= context = attn @ V; split ctx to bf16 hi/lo =================
__global__ __launch_bounds__(256) void attn_v(const float* __restrict__ attn)
{
    extern __shared__ float sm2[];
    float* sAT = sm2;              // [64][132] transposed attn tile
    float* sV  = sm2 + 64*132;     // [64][68]

    int bh  = blockIdx.y;
    int rt  = blockIdx.x;          // 0..7
    int tid = threadIdx.x;
    int ty = tid >> 4, tx = tid & 15;

    const float* Ab = attn + ((size_t)bh * SS + rt*128) * SS;
    const float* Vb = g_V + (size_t)bh * SS * DKK;

    float acc[8][4];
#pragma unroll
    for (int i = 0; i < 8; i++)
#pragma unroll
        for (int j = 0; j < 4; j++) acc[i][j] = 0.0f;

    int ktmax = rt*2 + 1;
    for (int kt = 0; kt <= ktmax; kt++) {
        __syncthreads();
        {   // load attn 128x64 transposed
            int m  = tid & 127;
            int kc = (tid >> 7) * 32;
            const float* src = Ab + (size_t)m * SS + kt*64 + kc;
#pragma unroll
            for (int i = 0; i < 8; i++) {
                float4 a = ((const float4*)src)[i];
                int k = kc + i*4;
                sAT[(k+0)*132 + m] = a.x; sAT[(k+1)*132 + m] = a.y;
                sAT[(k+2)*132 + m] = a.z; sAT[(k+3)*132 + m] = a.w;
            }
        }
        {   // load V 64x64
            int lr = tid >> 2;
            int lc = (tid & 3) * 16;
            const float* src = Vb + (size_t)(kt*64 + lr) * DKK + lc;
#pragma unroll
            for (int i = 0; i < 4; i++)
                *(float4*)&sV[lr*68 + lc + 4*i] = ((const float4*)src)[i];
        }
        __syncthreads();
#pragma unroll
        for (int k = 0; k < 64; k++) {
            float4 a0 = *(float4*)&sAT[k*132 + ty*8];
            float4 a1 = *(float4*)&sAT[k*132 + ty*8 + 4];
            float4 v  = *(float4*)&sV[k*68 + tx*4];
            float av[8] = {a0.x, a0.y, a0.z, a0.w, a1.x, a1.y, a1.z, a1.w};
#pragma unroll
            for (int i = 0; i < 8; i++) {
                acc[i][0] = fmaf(av[i], v.x, acc[i][0]);
                acc[i][1] = fmaf(av[i], v.y, acc[i][1]);
                acc[i][2] = fmaf(av[i], v.z, acc[i][2]);
                acc[i][3] = fmaf(av[i], v.w, acc[i][3]);
            }
        }
    }

    int b = bh >> 4, h = bh & 15;
#pragma unroll
    for (int i = 0; i < 8; i++) {
        int m = rt*128 + ty*8 + i;
        size_t off = ((size_t)b * SS + m) * DD + h*DKK + tx*4;
        __nv_bfloat162 h01, h23, l01, l23;
        h01.x = __float2bfloat16(acc[i][0]); l01.x = __float2bfloat16(acc[i][0] - __bfloat162float(h01.x));
        h01.y = __float2bfloat16(acc[i][1]); l01.y = __float2bfloat16(acc[i][1] - __bfloat162float(h01.y));
        h23.x = __float2bfloat16(acc[i][2]); l23.x = __float2bfloat16(acc[i][2] - __bfloat162float(h23.x));
        h23.y = __float2bfloat16(acc[i][3]); l23.y = __float2bfloat16(acc[i][3] - __bfloat162float(h23.y));
        *(__nv_bfloat162*)(g_Chi + off)     = h01;
        *(__nv_bfloat162*)(g_Chi + off + 2) = h23;
        *(__nv_bfloat162*)(g_Clo + off)     = l01;
        *(__nv_bfloat162*)(g_Clo + off + 2) = l23;
    }
}

// ============================================================
extern "C" void kernel_launch(void* const* d_in, const int* in_sizes, int n_in,
                              void* d_out, int out_size)
{
    (void)in_sizes; (void)n_in;
    const float* q  = (const float*)d_in[0];
    const float* k  = (const float*)d_in[1];
    const float* v  = (const float*)d_in[2];
    const float* Wq = (const float*)d_in[4];
    const float* Wk = (const float*)d_in[5];
    const float* Wv = (const float*)d_in[6];
    const float* Wo = (const float*)d_in[7];
    float* out = (float*)d_out;

    const size_t OUTE  = (size_t)BB * SS * DD;        // 8,388,608
    const size_t ATTNE = (size_t)BB * HH * SS * SS;   // 134,217,728

    float* attn_ptr;
    bool write_out = true;
    size_t osz = (size_t)out_size;
    if (osz >= OUTE + ATTNE) {
        attn_ptr = out + OUTE;
    } else if (osz == ATTNE) {
        attn_ptr = out;
        write_out = false;
    } else {
        void* p = nullptr;
        cudaGetSymbolAddress(&p, g_attn);
        attn_ptr = (float*)p;
    }

    // 1. bf16 splits
    split_kernel<<<2097152/256, 256>>>(q, 2097152, 0, 0);
    split_kernel<<<2097152/256, 256>>>(k, 2097152, 0, 1);
    split_kernel<<<2097152/256, 256>>>(v, 2097152, 0, 2);
    split_kernel<<<262144/256, 256>>>(Wq, 262144, 1, 0);
    split_kernel<<<262144/256, 256>>>(Wk, 262144, 1, 1);
    split_kernel<<<262144/256, 256>>>(Wv, 262144, 1, 2);
    split_kernel<<<262144/256, 256>>>(Wo, 262144, 1, 3);

    // 2. projections (HMMA, cp.async pipeline)
    cudaFuncSetAttribute(mma_gemm, cudaFuncAttributeMaxDynamicSharedMemorySize, GEMM_SMEM);
    dim3 gg(8, 64);
    mma_gemm<<<gg, 256, GEMM_SMEM>>>(nullptr, 0);
    mma_gemm<<<gg, 256, GEMM_SMEM>>>(nullptr, 1);
    mma_gemm<<<gg, 256, GEMM_SMEM>>>(nullptr, 2);

    // 3. scores on HMMA + softmax
    cudaFuncSetAttribute(attn_scores, cudaFuncAttributeMaxDynamicSharedMemorySize, SCORES_SMEM);
    attn_scores<<<dim3(32, 128), 256, SCORES_SMEM>>>(attn_ptr);

    // 4. context (+ bf16 split epilogue)
    size_t smem_av = (size_t)(64*132 + 64*68) * sizeof(float);   // 51,200
    cudaFuncSetAttribute(attn_v, cudaFuncAttributeMaxDynamicSharedMemorySize, (int)smem_av);
    attn_v<<<dim3(8, 128), 256, smem_av>>>(attn_ptr);

    // 5. output projection
    if (write_out)
        mma_gemm<<<gg, 256, GEMM_SMEM>>>(out, 3);
}

// round 7
// speedup vs baseline: 2.4325x; 1.2019x over previous
#include <cuda_runtime.h>
#include <cuda_bf16.h>
#include <cstdint>
#include <cstddef>

// Problem constants
#define BB   8
#define SS   1024
#define DD   1024
#define HH   16
#define DKK  64
#define INV_SCALE (1.0f/16.0f)   // SCALE = sqrt(64)*2 = 16

// ---------------- scratch (no cudaMalloc allowed) ----------------
__device__ __nv_bfloat16 g_Xhi[3u*8388608u];   // input splits q,k,v
__device__ __nv_bfloat16 g_Xlo[3u*8388608u];
__device__ __nv_bfloat16 g_Whi_[4u*1048576u];  // weight splits Wq,Wk,Wv,Wo
__device__ __nv_bfloat16 g_Wlo_[4u*1048576u];
__device__ __nv_bfloat16 g_Qhi[BB*HH*SS*DKK];  // [B,H,S,dk] bf16 splits
__device__ __nv_bfloat16 g_Qlo[BB*HH*SS*DKK];
__device__ __nv_bfloat16 g_Khi[BB*HH*SS*DKK];
__device__ __nv_bfloat16 g_Klo[BB*HH*SS*DKK];
__device__ __nv_bfloat16 g_Vhi[BB*HH*SS*DKK];
__device__ __nv_bfloat16 g_Vlo[BB*HH*SS*DKK];
__device__ __nv_bfloat16 g_Chi[BB*SS*DD];      // ctx splits [B,S,D]
__device__ __nv_bfloat16 g_Clo[BB*SS*DD];
__device__ float g_attn[(size_t)BB*HH*SS*SS];  // fallback

__device__ __forceinline__ uint32_t s2u(const void* p) {
    return (uint32_t)__cvta_generic_to_shared(p);
}
#define CP_ASYNC16(dst, src) \
    asm volatile("cp.async.cg.shared.global [%0], [%1], 16;" :: "r"(dst), "l"(src))
#define CP_COMMIT() asm volatile("cp.async.commit_group;" ::: "memory")
#define CP_WAIT(n)  asm volatile("cp.async.wait_group %0;" :: "n"(n) : "memory")

__device__ __forceinline__ void ldsm4(uint32_t* r, uint32_t addr) {
    asm volatile("ldmatrix.sync.aligned.m8n8.x4.shared.b16 {%0,%1,%2,%3}, [%4];"
                 : "=r"(r[0]), "=r"(r[1]), "=r"(r[2]), "=r"(r[3]) : "r"(addr));
}
__device__ __forceinline__ void ldsm4t(uint32_t* r, uint32_t addr) {
    asm volatile("ldmatrix.sync.aligned.m8n8.x4.trans.shared.b16 {%0,%1,%2,%3}, [%4];"
                 : "=r"(r[0]), "=r"(r[1]), "=r"(r[2]), "=r"(r[3]) : "r"(addr));
}
__device__ __forceinline__ void mma16816(float* d, const uint32_t* a,
                                         uint32_t b0, uint32_t b1) {
    asm volatile("mma.sync.aligned.m16n8k16.row.col.f32.bf16.bf16.f32 "
        "{%0,%1,%2,%3}, {%4,%5,%6,%7}, {%8,%9}, {%0,%1,%2,%3};"
        : "+f"(d[0]), "+f"(d[1]), "+f"(d[2]), "+f"(d[3])
        : "r"(a[0]), "r"(a[1]), "r"(a[2]), "r"(a[3]), "r"(b0), "r"(b1));
}
__device__ __forceinline__ void split2(float x, float y, uint32_t& h, uint32_t& l) {
    __nv_bfloat162 hh, ll;
    hh.x = __float2bfloat16(x); ll.x = __float2bfloat16(x - __bfloat162float(hh.x));
    hh.y = __float2bfloat16(y); ll.y = __float2bfloat16(y - __bfloat162float(hh.y));
    h = *(uint32_t*)&hh; l = *(uint32_t*)&ll;
}

// ================= split kernels (batched) =================
__global__ void split_x(const float* __restrict__ q, const float* __restrict__ k,
                        const float* __restrict__ v)
{
    int slot = blockIdx.y;
    const float* src = (slot == 0) ? q : (slot == 1) ? k : v;
    int i = blockIdx.x * blockDim.x + threadIdx.x;          // < 2097152
    __nv_bfloat16* hi = g_Xhi + (size_t)slot * 8388608u;
    __nv_bfloat16* lo = g_Xlo + (size_t)slot * 8388608u;
    float4 f = ((const float4*)src)[i];
    uint32_t h01, l01, h23, l23;
    split2(f.x, f.y, h01, l01);
    split2(f.z, f.w, h23, l23);
    ((uint32_t*)hi)[i*2] = h01; ((uint32_t*)hi)[i*2+1] = h23;
    ((uint32_t*)lo)[i*2] = l01; ((uint32_t*)lo)[i*2+1] = l23;
}
__global__ void split_w(const float* __restrict__ wq, const float* __restrict__ wk,
                        const float* __restrict__ wv, const float* __restrict__ wo)
{
    int slot = blockIdx.y;
    const float* src = (slot == 0) ? wq : (slot == 1) ? wk : (slot == 2) ? wv : wo;
    int i = blockIdx.x * blockDim.x + threadIdx.x;          // < 262144
    __nv_bfloat16* hi = g_Whi_ + (size_t)slot * 1048576u;
    __nv_bfloat16* lo = g_Wlo_ + (size_t)slot * 1048576u;
    float4 f = ((const float4*)src)[i];
    uint32_t h01, l01, h23, l23;
    split2(f.x, f.y, h01, l01);
    split2(f.z, f.w, h23, l23);
    ((uint32_t*)hi)[i*2] = h01; ((uint32_t*)hi)[i*2+1] = h23;
    ((uint32_t*)lo)[i*2] = l01; ((uint32_t*)lo)[i*2+1] = l23;
}

// ================= HMMA GEMM, cp.async 4-stage pipeline =================
// C = Ahi·Whi^T + Ahi·Wlo^T + Alo·Whi^T (bf16, fp32 accum)
// mode 0/1/2: -> bf16 splits g_{Q,K,V}{hi,lo} [B,H,S,dk]
// mode 3:     ctx -> Cout fp32 row-major
#define PITCH    80
#define T_AHI    0
#define T_ALO    10240
#define T_WHI    20480
#define T_WLO    30720
#define STAGE_SZ 40960
#define N_STAGES 4
#define GEMM_SMEM (N_STAGES*STAGE_SZ)   // 163840 B

__global__ __launch_bounds__(256) void mma_gemm(float* __restrict__ Cout, int mode)
{
    extern __shared__ __align__(128) char sm[];
    uint32_t sb = s2u(sm);

    int tid  = threadIdx.x;
    int wid  = tid >> 5, lane = tid & 31;
    int bm   = blockIdx.y * 128, bn = blockIdx.x * 128;
    int wm   = (wid & 1) * 64;
    int wn   = (wid >> 1) * 32;

    const __nv_bfloat16* Ah = (mode < 3) ? (g_Xhi + (size_t)mode * 8388608u) : g_Chi;
    const __nv_bfloat16* Al = (mode < 3) ? (g_Xlo + (size_t)mode * 8388608u) : g_Clo;
    const __nv_bfloat16* Wh = g_Whi_ + (size_t)mode * 1048576u;
    const __nv_bfloat16* Wl = g_Wlo_ + (size_t)mode * 1048576u;

    int c0 = tid, c1 = tid + 256;
    int r0 = c0 >> 2, q0 = c0 & 3;
    int r1 = c1 >> 2, q1 = c1 & 3;
    const __nv_bfloat16* gAh0 = Ah + (size_t)(bm + r0) * 1024 + q0 * 8;
    const __nv_bfloat16* gAh1 = Ah + (size_t)(bm + r1) * 1024 + q1 * 8;
    const __nv_bfloat16* gAl0 = Al + (size_t)(bm + r0) * 1024 + q0 * 8;
    const __nv_bfloat16* gAl1 = Al + (size_t)(bm + r1) * 1024 + q1 * 8;
    const __nv_bfloat16* gWh0 = Wh + (size_t)(bn + r0) * 1024 + q0 * 8;
    const __nv_bfloat16* gWh1 = Wh + (size_t)(bn + r1) * 1024 + q1 * 8;
    const __nv_bfloat16* gWl0 = Wl + (size_t)(bn + r0) * 1024 + q0 * 8;
    const __nv_bfloat16* gWl1 = Wl + (size_t)(bn + r1) * 1024 + q1 * 8;
    uint32_t sd0 = (uint32_t)(r0 * PITCH + q0 * 16);
    uint32_t sd1 = (uint32_t)(r1 * PITCH + q1 * 16);

    uint32_t offA = (uint32_t)((wm + (lane & 15)) * PITCH + (lane >> 4) * 16);
    uint32_t offB = (uint32_t)((wn + ((lane >> 4) & 1) * 8 + (lane & 7)) * PITCH
                               + ((lane >> 3) & 1) * 16);

    float acc[4][4][4];
#pragma unroll
    for (int i = 0; i < 4; i++)
#pragma unroll
        for (int j = 0; j < 4; j++)
#pragma unroll
            for (int t = 0; t < 4; t++) acc[i][j][t] = 0.0f;

    auto issue_stage = [&](int kt, int s) {
        uint32_t st = sb + (uint32_t)s * STAGE_SZ;
        size_t ko = (size_t)kt * 32;
        CP_ASYNC16(st + T_AHI + sd0, gAh0 + ko); CP_ASYNC16(st + T_AHI + sd1, gAh1 + ko);
        CP_ASYNC16(st + T_ALO + sd0, gAl0 + ko); CP_ASYNC16(st + T_ALO + sd1, gAl1 + ko);
        CP_ASYNC16(st + T_WHI + sd0, gWh0 + ko); CP_ASYNC16(st + T_WHI + sd1, gWh1 + ko);
        CP_ASYNC16(st + T_WLO + sd0, gWl0 + ko); CP_ASYNC16(st + T_WLO + sd1, gWl1 + ko);
    };

    issue_stage(0, 0); CP_COMMIT();
    issue_stage(1, 1); CP_COMMIT();
    issue_stage(2, 2); CP_COMMIT();

    for (int kt = 0; kt < 32; kt++) {
        int s = kt & 3;
        CP_WAIT(2);
        __syncthreads();
        if (kt + 3 < 32) issue_stage(kt + 3, (kt + 3) & 3);
        CP_COMMIT();

        uint32_t stg = sb + (uint32_t)s * STAGE_SZ;
#pragma unroll
        for (int kk = 0; kk < 2; kk++) {
            uint32_t k2 = (uint32_t)(kk * 32);
            uint32_t ah[4][4], al[4][4], bhf[2][4], blf[2][4];
#pragma unroll
            for (int mf = 0; mf < 4; mf++) {
                ldsm4(ah[mf], stg + T_AHI + offA + mf * (16 * PITCH) + k2);
                ldsm4(al[mf], stg + T_ALO + offA + mf * (16 * PITCH) + k2);
            }
#pragma unroll
            for (int nf2 = 0; nf2 < 2; nf2++) {
                ldsm4(bhf[nf2], stg + T_WHI + offB + nf2 * (16 * PITCH) + k2);
                ldsm4(blf[nf2], stg + T_WLO + offB + nf2 * (16 * PITCH) + k2);
            }
#pragma unroll
            for (int mf = 0; mf < 4; mf++)
#pragma unroll
                for (int nf = 0; nf < 4; nf++) {
                    int n2 = nf >> 1, hi = (nf & 1) * 2;
                    mma16816(acc[mf][nf], ah[mf], bhf[n2][hi], bhf[n2][hi + 1]);
                    mma16816(acc[mf][nf], ah[mf], blf[n2][hi], blf[n2][hi + 1]);
                    mma16816(acc[mf][nf], al[mf], bhf[n2][hi], bhf[n2][hi + 1]);
                }
        }
    }

    int lr = lane >> 2, lc = (lane & 3) * 2;
#pragma unroll
    for (int mf = 0; mf < 4; mf++)
#pragma unroll
        for (int nf = 0; nf < 4; nf++) {
            int r = bm + wm + mf * 16 + lr;
            int c = bn + wn + nf * 8 + lc;
            float2 v0 = make_float2(acc[mf][nf][0], acc[mf][nf][1]);
            float2 v1 = make_float2(acc[mf][nf][2], acc[mf][nf][3]);
            if (mode == 3) {
                *(float2*)(Cout + (size_t)r * 1024 + c)       = v0;
                *(float2*)(Cout + (size_t)(r + 8) * 1024 + c) = v1;
            } else {
                int h = c >> 6, dk = c & 63;
                int b0i = r >> 10, s0 = r & 1023;
                int b1i = (r + 8) >> 10, s1 = (r + 8) & 1023;
                size_t o0 = (((size_t)(b0i*HH + h) * SS + s0) << 6) + dk;
                size_t o1 = (((size_t)(b1i*HH + h) * SS + s1) << 6) + dk;
                __nv_bfloat16* ghi = (mode == 0) ? g_Qhi : (mode == 1) ? g_Khi : g_Vhi;
                __nv_bfloat16* glo = (mode == 0) ? g_Qlo : (mode == 1) ? g_Klo : g_Vlo;
                uint32_t h0, l0, h1, l1;
                split2(v0.x, v0.y, h0, l0);
                split2(v1.x, v1.y, h1, l1);
                *(uint32_t*)(ghi + o0) = h0; *(uint32_t*)(glo + o0) = l0;
                *(uint32_t*)(ghi + o1) = h1; *(uint32_t*)(glo + o1) = l1;
            }
        }
}

// ================= scores on HMMA + softmax -> attn =================
#define SCP 1032
#define QK_PITCH 144
#define SC_BYTES (32*SCP*4)          // 132096
#define QT_SZ    (32*QK_PITCH)       // 4608
#define KST_SZ   (2*64*QK_PITCH)     // 18432 per stage (hi+lo)
#define SCORES_SMEM (SC_BYTES + 2*QT_SZ + 2*KST_SZ)   // 178176

__global__ __launch_bounds__(256) void attn_scores(float* __restrict__ attn)
{
    extern __shared__ __align__(128) char smraw[];
    float* sc = (float*)smraw;
    uint32_t sb = s2u(smraw);
    uint32_t sQh = sb + SC_BYTES;
    uint32_t sQl = sQh + QT_SZ;
    uint32_t sK  = sQl + QT_SZ;

    int tid  = threadIdx.x;
    int wid  = tid >> 5, lane = tid & 31;
    int bh   = blockIdx.y;
    int row0 = blockIdx.x * 32;
    int wm   = (wid & 1) * 16;
    int wn   = (wid >> 1) * 16;

    const __nv_bfloat16* Qh = g_Qhi + ((size_t)bh * SS + row0) * DKK;
    const __nv_bfloat16* Ql = g_Qlo + ((size_t)bh * SS + row0) * DKK;
    const __nv_bfloat16* Kh = g_Khi + (size_t)bh * SS * DKK;
    const __nv_bfloat16* Kl = g_Klo + (size_t)bh * SS * DKK;

    {
        int r = tid >> 3, q = tid & 7;
        uint32_t d = (uint32_t)(r * QK_PITCH + q * 16);
        *(uint4*)(smraw + (sQh - sb) + d) = *(const uint4*)(Qh + (size_t)r * 64 + q * 8);
        *(uint4*)(smraw + (sQl - sb) + d) = *(const uint4*)(Ql + (size_t)r * 64 + q * 8);
    }

    int ntmax = (row0 + 31) >> 6;

    auto issue_K = [&](int nt, int st) {
        uint32_t kb = sK + (uint32_t)st * KST_SZ;
#pragma unroll
        for (int i = 0; i < 2; i++) {
            int c = i * 256 + tid;
            int r = c >> 3, q = c & 7;
            const __nv_bfloat16* srcH = Kh + (size_t)(nt * 64 + r) * 64 + q * 8;
            const __nv_bfloat16* srcL = Kl + (size_t)(nt * 64 + r) * 64 + q * 8;
            uint32_t d = (uint32_t)(r * QK_PITCH + q * 16);
            CP_ASYNC16(kb + d, srcH);
            CP_ASYNC16(kb + 9216 + d, srcL);
        }
    };

    issue_K(0, 0); CP_COMMIT();

    uint32_t offA = (uint32_t)((wm + (lane & 15)) * QK_PITCH + (lane >> 4) * 16);
    uint32_t offB = (uint32_t)((wn + ((lane >> 4) & 1) * 8 + (lane & 7)) * QK_PITCH
                               + ((lane >> 3) & 1) * 16);
    int lr = lane >> 2, lc = (lane & 3) * 2;

    for (int nt = 0; nt <= ntmax; nt++) {
        int st = nt & 1;
        CP_WAIT(0);
        __syncthreads();
        if (nt + 1 <= ntmax) issue_K(nt + 1, st ^ 1);
        CP_COMMIT();

        uint32_t kb = sK + (uint32_t)st * KST_SZ;
        float acc[2][4];
#pragma unroll
        for (int nf = 0; nf < 2; nf++)
#pragma unroll
            for (int t = 0; t < 4; t++) acc[nf][t] = 0.0f;

#pragma unroll
        for (int kk = 0; kk < 4; kk++) {
            uint32_t k2 = (uint32_t)(kk * 32);
            uint32_t ah[4], al[4], bhf[4], blf[4];
            ldsm4(ah, sQh + offA + k2);
            ldsm4(al, sQl + offA + k2);
            ldsm4(bhf, kb + offB + k2);
            ldsm4(blf, kb + 9216 + offB + k2);
#pragma unroll
            for (int nf = 0; nf < 2; nf++) {
                int hi = nf * 2;
                mma16816(acc[nf], ah, bhf[hi], bhf[hi + 1]);
                mma16816(acc[nf], ah, blf[hi], blf[hi + 1]);
                mma16816(acc[nf], al, bhf[hi], bhf[hi + 1]);
            }
        }

#pragma unroll
        for (int nf = 0; nf < 2; nf++)
#pragma unroll
            for (int half = 0; half < 2; half++) {
                int row = wm + lr + half * 8;
                int qr  = row0 + row;
                int c   = nt * 64 + wn + nf * 8 + lc;
                float v0 = fminf(fmaxf(acc[nf][half*2+0] * INV_SCALE, -30.0f), 30.0f);
                float v1 = fminf(fmaxf(acc[nf][half*2+1] * INV_SCALE, -30.0f), 30.0f);
                if (c     > qr) v0 = -1.0e9f;
                if (c + 1 > qr) v1 = -1.0e9f;
                sc[row * SCP + c]     = v0;
                sc[row * SCP + c + 1] = v1;
            }
        __syncthreads();
    }

    int r = tid >> 3, lane8 = tid & 7;
    int qr = row0 + r;
    float mx = -1.0e30f;
    for (int c = lane8; c <= qr; c += 8) mx = fmaxf(mx, sc[r*SCP + c]);
#pragma unroll
    for (int o = 4; o; o >>= 1) mx = fmaxf(mx, __shfl_xor_sync(0xffffffffu, mx, o));

    float s = 0.0f;
    for (int c = lane8; c <= qr; c += 8) {
        float e = __expf(sc[r*SCP + c] - mx);
        sc[r*SCP + c] = e;
        s += e;
    }
#pragma unroll
    for (int o = 4; o; o >>= 1) s += __shfl_xor_sync(0xffffffffu, s, o);
    float inv = 1.0f / s;

    float* arow = attn + ((size_t)bh * SS + qr) * SS;
    for (int t = lane8; t < 256; t += 8) {
        int c = t * 4;
        float4 v;
        v.x = (c+0 <= qr) ? sc[r*SCP + c+0] * inv : 0.0f;
        v.y = (c+1 <= qr) ? sc[r*SCP + c+1] * inv : 0.0f;
        v.z = (c+2 <= qr) ? sc[r*SCP + c+2] * inv : 0.0f;
        v.w = (c+3 <= qr) ? sc[r*SCP + c+3] * inv : 0.0f;
        ((float4*)arow)[t] = v;
    }
}

// ================= context = attn @ V on HMMA =================
// block = 128 q-rows x 64 dk of one (b,h); 8 warps, warp = 16 rows x 64 dk.
// attn fp32 tiles converted in-kernel to bf16 hi/lo; V pre-split bf16.
// A frags: row-major ldmatrix; B frags: ldmatrix.trans on V [key][dk].
#define AV_PITCH 144
#define AV_AHI 0
#define AV_ALO 18432
#define AV_VHI 36864
#define AV_VLO 46080
#define AV_SMEM 55296

__global__ __launch_bounds__(256) void attn_v(const float* __restrict__ attn)
{
    extern __shared__ __align__(128) char smB[];
    uint32_t sb = s2u(smB);

    int tid  = threadIdx.x;
    int wid  = tid >> 5, lane = tid & 31;
    int bh   = blockIdx.y;
    int rt   = blockIdx.x;            // 0..7
    int wm   = wid * 16;

    const float* Ab = attn + ((size_t)bh * SS + rt * 128) * SS;
    const __nv_bfloat16* Vh = g_Vhi + (size_t)bh * SS * DKK;
    const __nv_bfloat16* Vl = g_Vlo + (size_t)bh * SS * DKK;

    uint32_t offA  = (uint32_t)((wm + (lane & 15)) * AV_PITCH + (lane >> 4) * 16);
    uint32_t offBT = (uint32_t)(((lane & 7) + ((lane >> 3) & 1) * 8) * AV_PITCH
                                + ((lane >> 4) & 1) * 16);

    float acc[8][4];
#pragma unroll
    for (int nf = 0; nf < 8; nf++)
#pragma unroll
        for (int t = 0; t < 4; t++) acc[nf][t] = 0.0f;

    int ktmax = rt * 2 + 1;
    for (int kt = 0; kt <= ktmax; kt++) {
        __syncthreads();
        // load attn 128x64 fp32 -> bf16 hi/lo smem (2048 float4 chunks, 8/thread)
#pragma unroll
        for (int i = 0; i < 8; i++) {
            int c = i * 256 + tid;            // 0..2047
            int r = c >> 4;                   // row 0..127
            int q = c & 15;                   // float4 within row
            float4 a = *(const float4*)(Ab + (size_t)r * SS + kt * 64 + q * 4);
            uint32_t h01, l01, h23, l23;
            split2(a.x, a.y, h01, l01);
            split2(a.z, a.w, h23, l23);
            uint32_t d = (uint32_t)(r * AV_PITCH + q * 8);
            *(uint2*)(smB + AV_AHI + d) = make_uint2(h01, h23);
            *(uint2*)(smB + AV_ALO + d) = make_uint2(l01, l23);
        }
        // load V 64x64 bf16 hi/lo (512 uint4 chunks each, 2/thread)
#pragma unroll
        for (int i = 0; i < 2; i++) {
            int c = i * 256 + tid;            // 0..511
            int r = c >> 3, q = c & 7;
            uint32_t d = (uint32_t)(r * AV_PITCH + q * 16);
            *(uint4*)(smB + AV_VHI + d) = *(const uint4*)(Vh + (size_t)(kt*64 + r) * 64 + q * 8);
            *(uint4*)(smB + AV_VLO + d) = *(const uint4*)(Vl + (size_t)(kt*64 + r) * 64 + q * 8);
        }
        __syncthreads();

#pragma unroll
        for (int kk = 0; kk < 4; kk++) {      // k16 steps within the 64-key tile
            uint32_t ah[4], al[4], bhf[4][4], blf[4][4];
            ldsm4(ah, sb + AV_AHI + offA + kk * 32);
            ldsm4(al, sb + AV_ALO + offA + kk * 32);
#pragma unroll
            for (int g = 0; g < 4; g++) {     // n16 groups over dk=64
                uint32_t ba = offBT + (uint32_t)(kk * 16 * AV_PITCH + g * 32);
                ldsm4t(bhf[g], sb + AV_VHI + ba);
                ldsm4t(blf[g], sb + AV_VLO + ba);
            }
#pragma unroll
            for (int nf = 0; nf < 8; nf++) {
                int g = nf >> 1, s2i = (nf & 1) * 2;
                mma16816(acc[nf], ah, bhf[g][s2i], bhf[g][s2i + 1]);
                mma16816(acc[nf], ah, blf[g][s2i], blf[g][s2i + 1]);
                mma16816(acc[nf], al, bhf[g][s2i], bhf[g][s2i + 1]);
            }
        }
    }

    // epilogue: ctx -> bf16 hi/lo splits at [B,S,D]
    int lr = lane >> 2, lc = (lane & 3) * 2;
    int b = bh >> 4, h = bh & 15;
#pragma unroll
    for (int nf = 0; nf < 8; nf++)
#pragma unroll
        for (int half = 0; half < 2; half++) {
            int m = rt * 128 + wm + lr + half * 8;
            int c = nf * 8 + lc;
            size_t off = ((size_t)b * SS + m) * DD + h * DKK + c;
            uint32_t hh, ll;
            split2(acc[nf][half*2], acc[nf][half*2+1], hh, ll);
            *(uint32_t*)(g_Chi + off) = hh;
            *(uint32_t*)(g_Clo + off) = ll;
        }
}

// ============================================================
extern "C" void kernel_launch(void* const* d_in, const int* in_sizes, int n_in,
                              void* d_out, int out_size)
{
    (void)in_sizes; (void)n_in;
    const float* q  = (const float*)d_in[0];
    const float* k  = (const float*)d_in[1];
    const float* v  = (const float*)d_in[2];
    const float* Wq = (const float*)d_in[4];
    const float* Wk = (const float*)d_in[5];
    const float* Wv = (const float*)d_in[6];
    const float* Wo = (const float*)d_in[7];
    float* out = (float*)d_out;

    const size_t OUTE  = (size_t)BB * SS * DD;        // 8,388,608
    const size_t ATTNE = (size_t)BB * HH * SS * SS;   // 134,217,728

    float* attn_ptr;
    bool write_out = true;
    size_t osz = (size_t)out_size;
    if (osz >= OUTE + ATTNE) {
        attn_ptr = out + OUTE;
    } else if (osz == ATTNE) {
        attn_ptr = out;
        write_out = false;
    } else {
        void* p = nullptr;
        cudaGetSymbolAddress(&p, g_attn);
        attn_ptr = (float*)p;
    }

    // 1. bf16 splits (2 launches)
    split_x<<<dim3(2097152/256, 3), 256>>>(q, k, v);
    split_w<<<dim3(262144/256, 4), 256>>>(Wq, Wk, Wv, Wo);

    // 2. projections (HMMA, cp.async pipeline)
    cudaFuncSetAttribute(mma_gemm, cudaFuncAttributeMaxDynamicSharedMemorySize, GEMM_SMEM);
    dim3 gg(8, 64);
    mma_gemm<<<gg, 256, GEMM_SMEM>>>(nullptr, 0);
    mma_gemm<<<gg, 256, GEMM_SMEM>>>(nullptr, 1);
    mma_gemm<<<gg, 256, GEMM_SMEM>>>(nullptr, 2);

    // 3. scores on HMMA + softmax
    cudaFuncSetAttribute(attn_scores, cudaFuncAttributeMaxDynamicSharedMemorySize, SCORES_SMEM);
    attn_scores<<<dim3(32, 128), 256, SCORES_SMEM>>>(attn_ptr);

    // 4. context on HMMA (+ bf16 split epilogue)
    cudaFuncSetAttribute(attn_v, cudaFuncAttributeMaxDynamicSharedMemorySize, AV_SMEM);
    attn_v<<<dim3(8, 128), 256, AV_SMEM>>>(attn_ptr);

    // 5. output projection
    if (write_out)
        mma_gemm<<<gg, 256, GEMM_SMEM>>>(out, 3);
}

// round 8
// speedup vs baseline: 2.7219x; 1.1190x over previous
#include <cuda_runtime.h>
#include <cuda_bf16.h>
#include <cstdint>
#include <cstddef>

// Problem constants
#define BB   8
#define SS   1024
#define DD   1024
#define HH   16
#define DKK  64
#define INV_SCALE (1.0f/16.0f)   // SCALE = sqrt(64)*2 = 16

// ---------------- scratch (no cudaMalloc allowed) ----------------
__device__ __nv_bfloat16 g_Xhi[3u*8388608u];   // input splits q,k,v
__device__ __nv_bfloat16 g_Xlo[3u*8388608u];
__device__ __nv_bfloat16 g_Whi_[4u*1048576u];  // weight splits Wq,Wk,Wv,Wo
__device__ __nv_bfloat16 g_Wlo_[4u*1048576u];
__device__ __nv_bfloat16 g_Qhi[BB*HH*SS*DKK];  // [B,H,S,dk] bf16 splits
__device__ __nv_bfloat16 g_Qlo[BB*HH*SS*DKK];
__device__ __nv_bfloat16 g_Khi[BB*HH*SS*DKK];
__device__ __nv_bfloat16 g_Klo[BB*HH*SS*DKK];
__device__ __nv_bfloat16 g_Vhi[BB*HH*SS*DKK];
__device__ __nv_bfloat16 g_Vlo[BB*HH*SS*DKK];
__device__ __nv_bfloat16 g_Chi[BB*SS*DD];      // ctx splits [B,S,D]
__device__ __nv_bfloat16 g_Clo[BB*SS*DD];
__device__ float g_attn[(size_t)BB*HH*SS*SS];  // fallback

__device__ __forceinline__ uint32_t s2u(const void* p) {
    return (uint32_t)__cvta_generic_to_shared(p);
}
#define CP_ASYNC16(dst, src) \
    asm volatile("cp.async.cg.shared.global [%0], [%1], 16;" :: "r"(dst), "l"(src))
#define CP_COMMIT() asm volatile("cp.async.commit_group;" ::: "memory")
#define CP_WAIT(n)  asm volatile("cp.async.wait_group %0;" :: "n"(n) : "memory")

__device__ __forceinline__ void ldsm4(uint32_t* r, uint32_t addr) {
    asm volatile("ldmatrix.sync.aligned.m8n8.x4.shared.b16 {%0,%1,%2,%3}, [%4];"
                 : "=r"(r[0]), "=r"(r[1]), "=r"(r[2]), "=r"(r[3]) : "r"(addr));
}
__device__ __forceinline__ void ldsm4t(uint32_t* r, uint32_t addr) {
    asm volatile("ldmatrix.sync.aligned.m8n8.x4.trans.shared.b16 {%0,%1,%2,%3}, [%4];"
                 : "=r"(r[0]), "=r"(r[1]), "=r"(r[2]), "=r"(r[3]) : "r"(addr));
}
__device__ __forceinline__ void mma16816(float* d, const uint32_t* a,
                                         uint32_t b0, uint32_t b1) {
    asm volatile("mma.sync.aligned.m16n8k16.row.col.f32.bf16.bf16.f32 "
        "{%0,%1,%2,%3}, {%4,%5,%6,%7}, {%8,%9}, {%0,%1,%2,%3};"
        : "+f"(d[0]), "+f"(d[1]), "+f"(d[2]), "+f"(d[3])
        : "r"(a[0]), "r"(a[1]), "r"(a[2]), "r"(a[3]), "r"(b0), "r"(b1));
}
__device__ __forceinline__ void split2(float x, float y, uint32_t& h, uint32_t& l) {
    __nv_bfloat162 hh, ll;
    hh.x = __float2bfloat16(x); ll.x = __float2bfloat16(x - __bfloat162float(hh.x));
    hh.y = __float2bfloat16(y); ll.y = __float2bfloat16(y - __bfloat162float(hh.y));
    h = *(uint32_t*)&hh; l = *(uint32_t*)&ll;
}

// ================= split kernels (batched) =================
__global__ void split_x(const float* __restrict__ q, const float* __restrict__ k,
                        const float* __restrict__ v)
{
    int slot = blockIdx.y;
    const float* src = (slot == 0) ? q : (slot == 1) ? k : v;
    int i = blockIdx.x * blockDim.x + threadIdx.x;          // < 2097152
    __nv_bfloat16* hi = g_Xhi + (size_t)slot * 8388608u;
    __nv_bfloat16* lo = g_Xlo + (size_t)slot * 8388608u;
    float4 f = ((const float4*)src)[i];
    uint32_t h01, l01, h23, l23;
    split2(f.x, f.y, h01, l01);
    split2(f.z, f.w, h23, l23);
    ((uint32_t*)hi)[i*2] = h01; ((uint32_t*)hi)[i*2+1] = h23;
    ((uint32_t*)lo)[i*2] = l01; ((uint32_t*)lo)[i*2+1] = l23;
}
__global__ void split_w(const float* __restrict__ wq, const float* __restrict__ wk,
                        const float* __restrict__ wv, const float* __restrict__ wo)
{
    int slot = blockIdx.y;
    const float* src = (slot == 0) ? wq : (slot == 1) ? wk : (slot == 2) ? wv : wo;
    int i = blockIdx.x * blockDim.x + threadIdx.x;          // < 262144
    __nv_bfloat16* hi = g_Whi_ + (size_t)slot * 1048576u;
    __nv_bfloat16* lo = g_Wlo_ + (size_t)slot * 1048576u;
    float4 f = ((const float4*)src)[i];
    uint32_t h01, l01, h23, l23;
    split2(f.x, f.y, h01, l01);
    split2(f.z, f.w, h23, l23);
    ((uint32_t*)hi)[i*2] = h01; ((uint32_t*)hi)[i*2+1] = h23;
    ((uint32_t*)lo)[i*2] = l01; ((uint32_t*)lo)[i*2+1] = l23;
}

// ================= HMMA GEMM, cp.async 2-stage pipeline, 2 CTAs/SM =========
// C = Ahi·Whi^T + Ahi·Wlo^T + Alo·Whi^T (bf16, fp32 accum)
// mode 0/1/2: -> bf16 splits g_{Q,K,V}{hi,lo} [B,H,S,dk]
// mode 3:     ctx -> Cout fp32 row-major
// mode < 0:   mode = blockIdx.z (merged q/k/v launch)
#define PITCH    80
#define T_AHI    0
#define T_ALO    10240
#define T_WHI    20480
#define T_WLO    30720
#define STAGE_SZ 40960
#define N_STAGES 2
#define GEMM_SMEM (N_STAGES*STAGE_SZ)   // 81920 B -> 2 CTAs/SM

__global__ __launch_bounds__(256, 2) void mma_gemm(float* __restrict__ Cout, int mode_arg)
{
    extern __shared__ __align__(128) char sm[];
    uint32_t sb = s2u(sm);

    int mode = (mode_arg < 0) ? (int)blockIdx.z : mode_arg;

    int tid  = threadIdx.x;
    int wid  = tid >> 5, lane = tid & 31;
    int bm   = blockIdx.y * 128, bn = blockIdx.x * 128;
    int wm   = (wid & 1) * 64;
    int wn   = (wid >> 1) * 32;

    const __nv_bfloat16* Ah = (mode < 3) ? (g_Xhi + (size_t)mode * 8388608u) : g_Chi;
    const __nv_bfloat16* Al = (mode < 3) ? (g_Xlo + (size_t)mode * 8388608u) : g_Clo;
    const __nv_bfloat16* Wh = g_Whi_ + (size_t)mode * 1048576u;
    const __nv_bfloat16* Wl = g_Wlo_ + (size_t)mode * 1048576u;

    int c0 = tid, c1 = tid + 256;
    int r0 = c0 >> 2, q0 = c0 & 3;
    int r1 = c1 >> 2, q1 = c1 & 3;
    const __nv_bfloat16* gAh0 = Ah + (size_t)(bm + r0) * 1024 + q0 * 8;
    const __nv_bfloat16* gAh1 = Ah + (size_t)(bm + r1) * 1024 + q1 * 8;
    const __nv_bfloat16* gAl0 = Al + (size_t)(bm + r0) * 1024 + q0 * 8;
    const __nv_bfloat16* gAl1 = Al + (size_t)(bm + r1) * 1024 + q1 * 8;
    const __nv_bfloat16* gWh0 = Wh + (size_t)(bn + r0) * 1024 + q0 * 8;
    const __nv_bfloat16* gWh1 = Wh + (size_t)(bn + r1) * 1024 + q1 * 8;
    const __nv_bfloat16* gWl0 = Wl + (size_t)(bn + r0) * 1024 + q0 * 8;
    const __nv_bfloat16* gWl1 = Wl + (size_t)(bn + r1) * 1024 + q1 * 8;
    uint32_t sd0 = (uint32_t)(r0 * PITCH + q0 * 16);
    uint32_t sd1 = (uint32_t)(r1 * PITCH + q1 * 16);

    uint32_t offA = (uint32_t)((wm + (lane & 15)) * PITCH + (lane >> 4) * 16);
    uint32_t offB = (uint32_t)((wn + ((lane >> 4) & 1) * 8 + (lane & 7)) * PITCH
                               + ((lane >> 3) & 1) * 16);

    float acc[4][4][4];
#pragma unroll
    for (int i = 0; i < 4; i++)
#pragma unroll
        for (int j = 0; j < 4; j++)
#pragma unroll
            for (int t = 0; t < 4; t++) acc[i][j][t] = 0.0f;

    auto issue_stage = [&](int kt, int s) {
        uint32_t st = sb + (uint32_t)s * STAGE_SZ;
        size_t ko = (size_t)kt * 32;
        CP_ASYNC16(st + T_AHI + sd0, gAh0 + ko); CP_ASYNC16(st + T_AHI + sd1, gAh1 + ko);
        CP_ASYNC16(st + T_ALO + sd0, gAl0 + ko); CP_ASYNC16(st + T_ALO + sd1, gAl1 + ko);
        CP_ASYNC16(st + T_WHI + sd0, gWh0 + ko); CP_ASYNC16(st + T_WHI + sd1, gWh1 + ko);
        CP_ASYNC16(st + T_WLO + sd0, gWl0 + ko); CP_ASYNC16(st + T_WLO + sd1, gWl1 + ko);
    };

    // prologue: fill both stages. Groups: G0=stage0, G1=stage1; loop iter kt
    // commits exactly one group (may be empty) -> stage kt lives in group kt.
    issue_stage(0, 0); CP_COMMIT();
    issue_stage(1, 1); CP_COMMIT();

    for (int kt = 0; kt < 32; kt++) {
        int s = kt & 1;
        CP_WAIT(1);                      // group kt complete (1 newer pending)
        __syncthreads();

        uint32_t stg = sb + (uint32_t)s * STAGE_SZ;
#pragma unroll
        for (int kk = 0; kk < 2; kk++) {
            uint32_t k2 = (uint32_t)(kk * 32);
            uint32_t ah[4][4], al[4][4], bhf[2][4], blf[2][4];
#pragma unroll
            for (int mf = 0; mf < 4; mf++) {
                ldsm4(ah[mf], stg + T_AHI + offA + mf * (16 * PITCH) + k2);
                ldsm4(al[mf], stg + T_ALO + offA + mf * (16 * PITCH) + k2);
            }
#pragma unroll
            for (int nf2 = 0; nf2 < 2; nf2++) {
                ldsm4(bhf[nf2], stg + T_WHI + offB + nf2 * (16 * PITCH) + k2);
                ldsm4(blf[nf2], stg + T_WLO + offB + nf2 * (16 * PITCH) + k2);
            }
#pragma unroll
            for (int mf = 0; mf < 4; mf++)
#pragma unroll
                for (int nf = 0; nf < 4; nf++) {
                    int n2 = nf >> 1, hi = (nf & 1) * 2;
                    mma16816(acc[mf][nf], ah[mf], bhf[n2][hi], bhf[n2][hi + 1]);
                    mma16816(acc[mf][nf], ah[mf], blf[n2][hi], blf[n2][hi + 1]);
                    mma16816(acc[mf][nf], al[mf], bhf[n2][hi], bhf[n2][hi + 1]);
                }
        }

        __syncthreads();                 // stage s fully consumed by all warps
        if (kt + 2 < 32) issue_stage(kt + 2, s);
        CP_COMMIT();                     // one group per iteration, always
    }

    int lr = lane >> 2, lc = (lane & 3) * 2;
#pragma unroll
    for (int mf = 0; mf < 4; mf++)
#pragma unroll
        for (int nf = 0; nf < 4; nf++) {
            int r = bm + wm + mf * 16 + lr;
            int c = bn + wn + nf * 8 + lc;
            float2 v0 = make_float2(acc[mf][nf][0], acc[mf][nf][1]);
            float2 v1 = make_float2(acc[mf][nf][2], acc[mf][nf][3]);
            if (mode == 3) {
                *(float2*)(Cout + (size_t)r * 1024 + c)       = v0;
                *(float2*)(Cout + (size_t)(r + 8) * 1024 + c) = v1;
            } else {
                int h = c >> 6, dk = c & 63;
                int b0i = r >> 10, s0 = r & 1023;
                int b1i = (r + 8) >> 10, s1 = (r + 8) & 1023;
                size_t o0 = (((size_t)(b0i*HH + h) * SS + s0) << 6) + dk;
                size_t o1 = (((size_t)(b1i*HH + h) * SS + s1) << 6) + dk;
                __nv_bfloat16* ghi = (mode == 0) ? g_Qhi : (mode == 1) ? g_Khi : g_Vhi;
                __nv_bfloat16* glo = (mode == 0) ? g_Qlo : (mode == 1) ? g_Klo : g_Vlo;
                uint32_t h0, l0, h1, l1;
                split2(v0.x, v0.y, h0, l0);
                split2(v1.x, v1.y, h1, l1);
                *(uint32_t*)(ghi + o0) = h0; *(uint32_t*)(glo + o0) = l0;
                *(uint32_t*)(ghi + o1) = h1; *(uint32_t*)(glo + o1) = l1;
            }
        }
}

// ================= scores on HMMA + softmax -> attn =================
#define SCP 1032
#define QK_PITCH 144
#define SC_BYTES (32*SCP*4)          // 132096
#define QT_SZ    (32*QK_PITCH)       // 4608
#define KST_SZ   (2*64*QK_PITCH)     // 18432 per stage (hi+lo)
#define SCORES_SMEM (SC_BYTES + 2*QT_SZ + 2*KST_SZ)   // 178176

__global__ __launch_bounds__(256) void attn_scores(float* __restrict__ attn)
{
    extern __shared__ __align__(128) char smraw[];
    float* sc = (float*)smraw;
    uint32_t sb = s2u(smraw);
    uint32_t sQh = sb + SC_BYTES;
    uint32_t sQl = sQh + QT_SZ;
    uint32_t sK  = sQl + QT_SZ;

    int tid  = threadIdx.x;
    int wid  = tid >> 5, lane = tid & 31;
    int bh   = blockIdx.y;
    int row0 = blockIdx.x * 32;
    int wm   = (wid & 1) * 16;
    int wn   = (wid >> 1) * 16;

    const __nv_bfloat16* Qh = g_Qhi + ((size_t)bh * SS + row0) * DKK;
    const __nv_bfloat16* Ql = g_Qlo + ((size_t)bh * SS + row0) * DKK;
    const __nv_bfloat16* Kh = g_Khi + (size_t)bh * SS * DKK;
    const __nv_bfloat16* Kl = g_Klo + (size_t)bh * SS * DKK;

    {
        int r = tid >> 3, q = tid & 7;
        uint32_t d = (uint32_t)(r * QK_PITCH + q * 16);
        *(uint4*)(smraw + (sQh - sb) + d) = *(const uint4*)(Qh + (size_t)r * 64 + q * 8);
        *(uint4*)(smraw + (sQl - sb) + d) = *(const uint4*)(Ql + (size_t)r * 64 + q * 8);
    }

    int ntmax = (row0 + 31) >> 6;

    auto issue_K = [&](int nt, int st) {
        uint32_t kb = sK + (uint32_t)st * KST_SZ;
#pragma unroll
        for (int i = 0; i < 2; i++) {
            int c = i * 256 + tid;
            int r = c >> 3, q = c & 7;
            const __nv_bfloat16* srcH = Kh + (size_t)(nt * 64 + r) * 64 + q * 8;
            const __nv_bfloat16* srcL = Kl + (size_t)(nt * 64 + r) * 64 + q * 8;
            uint32_t d = (uint32_t)(r * QK_PITCH + q * 16);
            CP_ASYNC16(kb + d, srcH);
            CP_ASYNC16(kb + 9216 + d, srcL);
        }
    };

    issue_K(0, 0); CP_COMMIT();

    uint32_t offA = (uint32_t)((wm + (lane & 15)) * QK_PITCH + (lane >> 4) * 16);
    uint32_t offB = (uint32_t)((wn + ((lane >> 4) & 1) * 8 + (lane & 7)) * QK_PITCH
                               + ((lane >> 3) & 1) * 16);
    int lr = lane >> 2, lc = (lane & 3) * 2;

    for (int nt = 0; nt <= ntmax; nt++) {
        int st = nt & 1;
        CP_WAIT(0);
        __syncthreads();
        if (nt + 1 <= ntmax) issue_K(nt + 1, st ^ 1);
        CP_COMMIT();

        uint32_t kb = sK + (uint32_t)st * KST_SZ;
        float acc[2][4];
#pragma unroll
        for (int nf = 0; nf < 2; nf++)
#pragma unroll
            for (int t = 0; t < 4; t++) acc[nf][t] = 0.0f;

#pragma unroll
        for (int kk = 0; kk < 4; kk++) {
            uint32_t k2 = (uint32_t)(kk * 32);
            uint32_t ah[4], al[4], bhf[4], blf[4];
            ldsm4(ah, sQh + offA + k2);
            ldsm4(al, sQl + offA + k2);
            ldsm4(bhf, kb + offB + k2);
            ldsm4(blf, kb + 9216 + offB + k2);
#pragma unroll
            for (int nf = 0; nf < 2; nf++) {
                int hi = nf * 2;
                mma16816(acc[nf], ah, bhf[hi], bhf[hi + 1]);
                mma16816(acc[nf], ah, blf[hi], blf[hi + 1]);
                mma16816(acc[nf], al, bhf[hi], bhf[hi + 1]);
            }
        }

#pragma unroll
        for (int nf = 0; nf < 2; nf++)
#pragma unroll
            for (int half = 0; half < 2; half++) {
                int row = wm + lr + half * 8;
                int qr  = row0 + row;
                int c   = nt * 64 + wn + nf * 8 + lc;
                float v0 = fminf(fmaxf(acc[nf][half*2+0] * INV_SCALE, -30.0f), 30.0f);
                float v1 = fminf(fmaxf(acc[nf][half*2+1] * INV_SCALE, -30.0f), 30.0f);
                if (c     > qr) v0 = -1.0e9f;
                if (c + 1 > qr) v1 = -1.0e9f;
                sc[row * SCP + c]     = v0;
                sc[row * SCP + c + 1] = v1;
            }
        __syncthreads();
    }

    int r = tid >> 3, lane8 = tid & 7;
    int qr = row0 + r;
    float mx = -1.0e30f;
    for (int c = lane8; c <= qr; c += 8) mx = fmaxf(mx, sc[r*SCP + c]);
#pragma unroll
    for (int o = 4; o; o >>= 1) mx = fmaxf(mx, __shfl_xor_sync(0xffffffffu, mx, o));

    float s = 0.0f;
    for (int c = lane8; c <= qr; c += 8) {
        float e = __expf(sc[r*SCP + c] - mx);
        sc[r*SCP + c] = e;
        s += e;
    }
#pragma unroll
    for (int o = 4; o; o >>= 1) s += __shfl_xor_sync(0xffffffffu, s, o);
    float inv = 1.0f / s;

    float* arow = attn + ((size_t)bh * SS + qr) * SS;
    for (int t = lane8; t < 256; t += 8) {
        int c = t * 4;
        float4 v;
        v.x = (c+0 <= qr) ? sc[r*SCP + c+0] * inv : 0.0f;
        v.y = (c+1 <= qr) ? sc[r*SCP + c+1] * inv : 0.0f;
        v.z = (c+2 <= qr) ? sc[r*SCP + c+2] * inv : 0.0f;
        v.w = (c+3 <= qr) ? sc[r*SCP + c+3] * inv : 0.0f;
        ((float4*)arow)[t] = v;
    }
}

// ================= context = attn @ V on HMMA =================
#define AV_PITCH 144
#define AV_AHI 0
#define AV_ALO 18432
#define AV_VHI 36864
#define AV_VLO 46080
#define AV_SMEM 55296

__global__ __launch_bounds__(256) void attn_v(const float* __restrict__ attn)
{
    extern __shared__ __align__(128) char smB[];
    uint32_t sb = s2u(smB);

    int tid  = threadIdx.x;
    int wid  = tid >> 5, lane = tid & 31;
    int bh   = blockIdx.y;
    int rt   = blockIdx.x;            // 0..7
    int wm   = wid * 16;

    const float* Ab = attn + ((size_t)bh * SS + rt * 128) * SS;
    const __nv_bfloat16* Vh = g_Vhi + (size_t)bh * SS * DKK;
    const __nv_bfloat16* Vl = g_Vlo + (size_t)bh * SS * DKK;

    uint32_t offA  = (uint32_t)((wm + (lane & 15)) * AV_PITCH + (lane >> 4) * 16);
    uint32_t offBT = (uint32_t)(((lane & 7) + ((lane >> 3) & 1) * 8) * AV_PITCH
                                + ((lane >> 4) & 1) * 16);

    float acc[8][4];
#pragma unroll
    for (int nf = 0; nf < 8; nf++)
#pragma unroll
        for (int t = 0; t < 4; t++) acc[nf][t] = 0.0f;

    int ktmax = rt * 2 + 1;
    for (int kt = 0; kt <= ktmax; kt++) {
        __syncthreads();
#pragma unroll
        for (int i = 0; i < 8; i++) {
            int c = i * 256 + tid;            // 0..2047
            int r = c >> 4;
            int q = c & 15;
            float4 a = *(const float4*)(Ab + (size_t)r * SS + kt * 64 + q * 4);
            uint32_t h01, l01, h23, l23;
            split2(a.x, a.y, h01, l01);
            split2(a.z, a.w, h23, l23);
            uint32_t d = (uint32_t)(r * AV_PITCH + q * 8);
            *(uint2*)(smB + AV_AHI + d) = make_uint2(h01, h23);
            *(uint2*)(smB + AV_ALO + d) = make_uint2(l01, l23);
        }
#pragma unroll
        for (int i = 0; i < 2; i++) {
            int c = i * 256 + tid;
            int r = c >> 3, q = c & 7;
            uint32_t d = (uint32_t)(r * AV_PITCH + q * 16);
            *(uint4*)(smB + AV_VHI + d) = *(const uint4*)(Vh + (size_t)(kt*64 + r) * 64 + q * 8);
            *(uint4*)(smB + AV_VLO + d) = *(const uint4*)(Vl + (size_t)(kt*64 + r) * 64 + q * 8);
        }
        __syncthreads();

#pragma unroll
        for (int kk = 0; kk < 4; kk++) {
            uint32_t ah[4], al[4], bhf[4][4], blf[4][4];
            ldsm4(ah, sb + AV_AHI + offA + kk * 32);
            ldsm4(al, sb + AV_ALO + offA + kk * 32);
#pragma unroll
            for (int g = 0; g < 4; g++) {
                uint32_t ba = offBT + (uint32_t)(kk * 16 * AV_PITCH + g * 32);
                ldsm4t(bhf[g], sb + AV_VHI + ba);
                ldsm4t(blf[g], sb + AV_VLO + ba);
            }
#pragma unroll
            for (int nf = 0; nf < 8; nf++) {
                int g = nf >> 1, s2i = (nf & 1) * 2;
                mma16816(acc[nf], ah, bhf[g][s2i], bhf[g][s2i + 1]);
                mma16816(acc[nf], ah, blf[g][s2i], blf[g][s2i + 1]);
                mma16816(acc[nf], al, bhf[g][s2i], bhf[g][s2i + 1]);
            }
        }
    }

    int lr = lane >> 2, lc = (lane & 3) * 2;
    int b = bh >> 4, h = bh & 15;
#pragma unroll
    for (int nf = 0; nf < 8; nf++)
#pragma unroll
        for (int half = 0; half < 2; half++) {
            int m = rt * 128 + wm + lr + half * 8;
            int c = nf * 8 + lc;
            size_t off = ((size_t)b * SS + m) * DD + h * DKK + c;
            uint32_t hh, ll;
            split2(acc[nf][half*2], acc[nf][half*2+1], hh, ll);
            *(uint32_t*)(g_Chi + off) = hh;
            *(uint32_t*)(g_Clo + off) = ll;
        }
}

// ============================================================
extern "C" void kernel_launch(void* const* d_in, const int* in_sizes, int n_in,
                              void* d_out, int out_size)
{
    (void)in_sizes; (void)n_in;
    const float* q  = (const float*)d_in[0];
    const float* k  = (const float*)d_in[1];
    const float* v  = (const float*)d_in[2];
    const float* Wq = (const float*)d_in[4];
    const float* Wk = (const float*)d_in[5];
    const float* Wv = (const float*)d_in[6];
    const float* Wo = (const float*)d_in[7];
    float* out = (float*)d_out;

    const size_t OUTE  = (size_t)BB * SS * DD;        // 8,388,608
    const size_t ATTNE = (size_t)BB * HH * SS * SS;   // 134,217,728

    float* attn_ptr;
    bool write_out = true;
    size_t osz = (size_t)out_size;
    if (osz >= OUTE + ATTNE) {
        attn_ptr = out + OUTE;
    } else if (osz == ATTNE) {
        attn_ptr = out;
        write_out = false;
    } else {
        void* p = nullptr;
        cudaGetSymbolAddress(&p, g_attn);
        attn_ptr = (float*)p;
    }

    // 1. bf16 splits (2 launches)
    split_x<<<dim3(2097152/256, 3), 256>>>(q, k, v);
    split_w<<<dim3(262144/256, 4), 256>>>(Wq, Wk, Wv, Wo);

    // 2. q/k/v projections merged into one launch (mode = blockIdx.z)
    cudaFuncSetAttribute(mma_gemm, cudaFuncAttributeMaxDynamicSharedMemorySize, GEMM_SMEM);
    mma_gemm<<<dim3(8, 64, 3), 256, GEMM_SMEM>>>(nullptr, -1);

    // 3. scores on HMMA + softmax
    cudaFuncSetAttribute(attn_scores, cudaFuncAttributeMaxDynamicSharedMemorySize, SCORES_SMEM);
    attn_scores<<<dim3(32, 128), 256, SCORES_SMEM>>>(attn_ptr);

    // 4. context on HMMA (+ bf16 split epilogue)
    cudaFuncSetAttribute(attn_v, cudaFuncAttributeMaxDynamicSharedMemorySize, AV_SMEM);
    attn_v<<<dim3(8, 128), 256, AV_SMEM>>>(attn_ptr);

    // 5. output projection
    if (write_out)
        mma_gemm<<<dim3(8, 64, 1), 256, GEMM_SMEM>>>(out, 3);
}

// round 11
// speedup vs baseline: 2.8808x; 1.0584x over previous
#include <cuda_runtime.h>
#include <cuda_bf16.h>
#include <cstdint>
#include <cstddef>

// Problem constants
#define BB   8
#define SS   1024
#define DD   1024
#define HH   16
#define DKK  64
#define INV_SCALE (1.0f/16.0f)   // SCALE = sqrt(64)*2 = 16

// ---------------- scratch (no cudaMalloc allowed) ----------------
__device__ __nv_bfloat16 g_Xhi[3u*8388608u];   // input splits q,k,v
__device__ __nv_bfloat16 g_Xlo[3u*8388608u];
__device__ __nv_bfloat16 g_Whi_[4u*1048576u];  // weight splits Wq,Wk,Wv,Wo
__device__ __nv_bfloat16 g_Wlo_[4u*1048576u];
__device__ __nv_bfloat16 g_Qhi[BB*HH*SS*DKK];  // [B,H,S,dk] bf16 splits
__device__ __nv_bfloat16 g_Qlo[BB*HH*SS*DKK];
__device__ __nv_bfloat16 g_Khi[BB*HH*SS*DKK];
__device__ __nv_bfloat16 g_Klo[BB*HH*SS*DKK];
__device__ __nv_bfloat16 g_Vhi[BB*HH*SS*DKK];
__device__ __nv_bfloat16 g_Vlo[BB*HH*SS*DKK];
__device__ __nv_bfloat16 g_Chi[BB*SS*DD];      // ctx splits [B,S,D]
__device__ __nv_bfloat16 g_Clo[BB*SS*DD];
__device__ float g_attn[(size_t)BB*HH*SS*SS];  // fallback

__device__ __forceinline__ uint32_t s2u(const void* p) {
    return (uint32_t)__cvta_generic_to_shared(p);
}
#define CP_ASYNC16(dst, src) \
    asm volatile("cp.async.cg.shared.global [%0], [%1], 16;" :: "r"(dst), "l"(src))
#define CP_COMMIT() asm volatile("cp.async.commit_group;" ::: "memory")
#define CP_WAIT(n)  asm volatile("cp.async.wait_group %0;" :: "n"(n) : "memory")

__device__ __forceinline__ void ldsm4(uint32_t* r, uint32_t addr) {
    asm volatile("ldmatrix.sync.aligned.m8n8.x4.shared.b16 {%0,%1,%2,%3}, [%4];"
                 : "=r"(r[0]), "=r"(r[1]), "=r"(r[2]), "=r"(r[3]) : "r"(addr));
}
__device__ __forceinline__ void ldsm4t(uint32_t* r, uint32_t addr) {
    asm volatile("ldmatrix.sync.aligned.m8n8.x4.trans.shared.b16 {%0,%1,%2,%3}, [%4];"
                 : "=r"(r[0]), "=r"(r[1]), "=r"(r[2]), "=r"(r[3]) : "r"(addr));
}
__device__ __forceinline__ void mma16816(float* d, const uint32_t* a,
                                         uint32_t b0, uint32_t b1) {
    asm volatile("mma.sync.aligned.m16n8k16.row.col.f32.bf16.bf16.f32 "
        "{%0,%1,%2,%3}, {%4,%5,%6,%7}, {%8,%9}, {%0,%1,%2,%3};"
        : "+f"(d[0]), "+f"(d[1]), "+f"(d[2]), "+f"(d[3])
        : "r"(a[0]), "r"(a[1]), "r"(a[2]), "r"(a[3]), "r"(b0), "r"(b1));
}
__device__ __forceinline__ void split2(float x, float y, uint32_t& h, uint32_t& l) {
    __nv_bfloat162 hh, ll;
    hh.x = __float2bfloat16(x); ll.x = __float2bfloat16(x - __bfloat162float(hh.x));
    hh.y = __float2bfloat16(y); ll.y = __float2bfloat16(y - __bfloat162float(hh.y));
    h = *(uint32_t*)&hh; l = *(uint32_t*)&ll;
}

// ================= split kernels (batched) =================
__global__ void split_x(const float* __restrict__ q, const float* __restrict__ k,
                        const float* __restrict__ v)
{
    int slot = blockIdx.y;
    const float* src = (slot == 0) ? q : (slot == 1) ? k : v;
    int i = blockIdx.x * blockDim.x + threadIdx.x;          // < 2097152
    __nv_bfloat16* hi = g_Xhi + (size_t)slot * 8388608u;
    __nv_bfloat16* lo = g_Xlo + (size_t)slot * 8388608u;
    float4 f = ((const float4*)src)[i];
    uint32_t h01, l01, h23, l23;
    split2(f.x, f.y, h01, l01);
    split2(f.z, f.w, h23, l23);
    ((uint32_t*)hi)[i*2] = h01; ((uint32_t*)hi)[i*2+1] = h23;
    ((uint32_t*)lo)[i*2] = l01; ((uint32_t*)lo)[i*2+1] = l23;
}
__global__ void split_w(const float* __restrict__ wq, const float* __restrict__ wk,
                        const float* __restrict__ wv, const float* __restrict__ wo)
{
    int slot = blockIdx.y;
    const float* src = (slot == 0) ? wq : (slot == 1) ? wk : (slot == 2) ? wv : wo;
    int i = blockIdx.x * blockDim.x + threadIdx.x;          // < 262144
    __nv_bfloat16* hi = g_Whi_ + (size_t)slot * 1048576u;
    __nv_bfloat16* lo = g_Wlo_ + (size_t)slot * 1048576u;
    float4 f = ((const float4*)src)[i];
    uint32_t h01, l01, h23, l23;
    split2(f.x, f.y, h01, l01);
    split2(f.z, f.w, h23, l23);
    ((uint32_t*)hi)[i*2] = h01; ((uint32_t*)hi)[i*2+1] = h23;
    ((uint32_t*)lo)[i*2] = l01; ((uint32_t*)lo)[i*2+1] = l23;
}

// ================= HMMA GEMM, cp.async 2-stage pipeline, 2 CTAs/SM =========
#define PITCH    80
#define T_AHI    0
#define T_ALO    10240
#define T_WHI    20480
#define T_WLO    30720
#define STAGE_SZ 40960
#define N_STAGES 2
#define GEMM_SMEM (N_STAGES*STAGE_SZ)   // 81920 B -> 2 CTAs/SM

__global__ __launch_bounds__(256, 2) void mma_gemm(float* __restrict__ Cout, int mode_arg)
{
    extern __shared__ __align__(128) char sm[];
    uint32_t sb = s2u(sm);

    int mode = (mode_arg < 0) ? (int)blockIdx.z : mode_arg;

    int tid  = threadIdx.x;
    int wid  = tid >> 5, lane = tid & 31;
    int bm   = blockIdx.y * 128, bn = blockIdx.x * 128;
    int wm   = (wid & 1) * 64;
    int wn   = (wid >> 1) * 32;

    const __nv_bfloat16* Ah = (mode < 3) ? (g_Xhi + (size_t)mode * 8388608u) : g_Chi;
    const __nv_bfloat16* Al = (mode < 3) ? (g_Xlo + (size_t)mode * 8388608u) : g_Clo;
    const __nv_bfloat16* Wh = g_Whi_ + (size_t)mode * 1048576u;
    const __nv_bfloat16* Wl = g_Wlo_ + (size_t)mode * 1048576u;

    int c0 = tid, c1 = tid + 256;
    int r0 = c0 >> 2, q0 = c0 & 3;
    int r1 = c1 >> 2, q1 = c1 & 3;
    const __nv_bfloat16* gAh0 = Ah + (size_t)(bm + r0) * 1024 + q0 * 8;
    const __nv_bfloat16* gAh1 = Ah + (size_t)(bm + r1) * 1024 + q1 * 8;
    const __nv_bfloat16* gAl0 = Al + (size_t)(bm + r0) * 1024 + q0 * 8;
    const __nv_bfloat16* gAl1 = Al + (size_t)(bm + r1) * 1024 + q1 * 8;
    const __nv_bfloat16* gWh0 = Wh + (size_t)(bn + r0) * 1024 + q0 * 8;
    const __nv_bfloat16* gWh1 = Wh + (size_t)(bn + r1) * 1024 + q1 * 8;
    const __nv_bfloat16* gWl0 = Wl + (size_t)(bn + r0) * 1024 + q0 * 8;
    const __nv_bfloat16* gWl1 = Wl + (size_t)(bn + r1) * 1024 + q1 * 8;
    uint32_t sd0 = (uint32_t)(r0 * PITCH + q0 * 16);
    uint32_t sd1 = (uint32_t)(r1 * PITCH + q1 * 16);

    uint32_t offA = (uint32_t)((wm + (lane & 15)) * PITCH + (lane >> 4) * 16);
    uint32_t offB = (uint32_t)((wn + ((lane >> 4) & 1) * 8 + (lane & 7)) * PITCH
                               + ((lane >> 3) & 1) * 16);

    float acc[4][4][4];
#pragma unroll
    for (int i = 0; i < 4; i++)
#pragma unroll
        for (int j = 0; j < 4; j++)
#pragma unroll
            for (int t = 0; t < 4; t++) acc[i][j][t] = 0.0f;

    auto issue_stage = [&](int kt, int s) {
        uint32_t st = sb + (uint32_t)s * STAGE_SZ;
        size_t ko = (size_t)kt * 32;
        CP_ASYNC16(st + T_AHI + sd0, gAh0 + ko); CP_ASYNC16(st + T_AHI + sd1, gAh1 + ko);
        CP_ASYNC16(st + T_ALO + sd0, gAl0 + ko); CP_ASYNC16(st + T_ALO + sd1, gAl1 + ko);
        CP_ASYNC16(st + T_WHI + sd0, gWh0 + ko); CP_ASYNC16(st + T_WHI + sd1, gWh1 + ko);
        CP_ASYNC16(st + T_WLO + sd0, gWl0 + ko); CP_ASYNC16(st + T_WLO + sd1, gWl1 + ko);
    };

    issue_stage(0, 0); CP_COMMIT();
    issue_stage(1, 1); CP_COMMIT();

    for (int kt = 0; kt < 32; kt++) {
        int s = kt & 1;
        CP_WAIT(1);
        __syncthreads();

        uint32_t stg = sb + (uint32_t)s * STAGE_SZ;
#pragma unroll
        for (int kk = 0; kk < 2; kk++) {
            uint32_t k2 = (uint32_t)(kk * 32);
            uint32_t ah[4][4], al[4][4], bhf[2][4], blf[2][4];
#pragma unroll
            for (int mf = 0; mf < 4; mf++) {
                ldsm4(ah[mf], stg + T_AHI + offA + mf * (16 * PITCH) + k2);
                ldsm4(al[mf], stg + T_ALO + offA + mf * (16 * PITCH) + k2);
            }
#pragma unroll
            for (int nf2 = 0; nf2 < 2; nf2++) {
                ldsm4(bhf[nf2], stg + T_WHI + offB + nf2 * (16 * PITCH) + k2);
                ldsm4(blf[nf2], stg + T_WLO + offB + nf2 * (16 * PITCH) + k2);
            }
#pragma unroll
            for (int mf = 0; mf < 4; mf++)
#pragma unroll
                for (int nf = 0; nf < 4; nf++) {
                    int n2 = nf >> 1, hi = (nf & 1) * 2;
                    mma16816(acc[mf][nf], ah[mf], bhf[n2][hi], bhf[n2][hi + 1]);
                    mma16816(acc[mf][nf], ah[mf], blf[n2][hi], blf[n2][hi + 1]);
                    mma16816(acc[mf][nf], al[mf], bhf[n2][hi], bhf[n2][hi + 1]);
                }
        }

        __syncthreads();
        if (kt + 2 < 32) issue_stage(kt + 2, s);
        CP_COMMIT();
    }

    int lr = lane >> 2, lc = (lane & 3) * 2;
#pragma unroll
    for (int mf = 0; mf < 4; mf++)
#pragma unroll
        for (int nf = 0; nf < 4; nf++) {
            int r = bm + wm + mf * 16 + lr;
            int c = bn + wn + nf * 8 + lc;
            float2 v0 = make_float2(acc[mf][nf][0], acc[mf][nf][1]);
            float2 v1 = make_float2(acc[mf][nf][2], acc[mf][nf][3]);
            if (mode == 3) {
                *(float2*)(Cout + (size_t)r * 1024 + c)       = v0;
                *(float2*)(Cout + (size_t)(r + 8) * 1024 + c) = v1;
            } else {
                int h = c >> 6, dk = c & 63;
                int b0i = r >> 10, s0 = r & 1023;
                int b1i = (r + 8) >> 10, s1 = (r + 8) & 1023;
                size_t o0 = (((size_t)(b0i*HH + h) * SS + s0) << 6) + dk;
                size_t o1 = (((size_t)(b1i*HH + h) * SS + s1) << 6) + dk;
                __nv_bfloat16* ghi = (mode == 0) ? g_Qhi : (mode == 1) ? g_Khi : g_Vhi;
                __nv_bfloat16* glo = (mode == 0) ? g_Qlo : (mode == 1) ? g_Klo : g_Vlo;
                uint32_t h0, l0, h1, l1;
                split2(v0.x, v0.y, h0, l0);
                split2(v1.x, v1.y, h1, l1);
                *(uint32_t*)(ghi + o0) = h0; *(uint32_t*)(glo + o0) = l0;
                *(uint32_t*)(ghi + o1) = h1; *(uint32_t*)(glo + o1) = l1;
            }
        }
}

// ========= scores: two-pass streaming softmax (no score buffer) =========
// CTA = 64 q-rows of one (b,h); 8 warps: 4(m)x2(n); warp tile 16 rows x 32 cols
// (two 16-col sub-tiles). Softmax uses fixed offset 30 (scores clipped to
// [-30,30] => exp(s-30) in [e^-60,1], shift-invariant, no max pass needed).
// Pass1: accumulate per-row sum of exp(s-30). Pass2: recompute, write
// exp(s-30)*inv_l via smem staging tile (coalesced float4 stores).
#define KP    144           // bf16 tile pitch bytes (64 bf16 + 16 pad)
#define S_QH  0
#define S_QL  9216
#define S_K   18432         // stage st at +st*18432; lo at +9216
#define S_P   55296         // fp32 staging, pitch 68 floats (272 B, 16-aligned)
#define S_LB  72704         // float lbuf[2][64]
#define S_IR  73216         // float irow[64]
#define SC2_SMEM 73472      // -> 3 CTAs/SM

__global__ __launch_bounds__(256, 3) void attn_scores(float* __restrict__ attn)
{
    extern __shared__ __align__(128) char smraw[];
    uint32_t sb = s2u(smraw);
    float* sP   = (float*)(smraw + S_P);
    float* lbuf = (float*)(smraw + S_LB);
    float* irow = (float*)(smraw + S_IR);

    int tid  = threadIdx.x;
    int wid  = tid >> 5, lane = tid & 31;
    int bh   = blockIdx.y;
    int rt   = blockIdx.x;               // 0..15, row0 = rt*64, tiles 0..rt
    int row0 = rt * 64;
    int wm   = (wid & 3) * 16;           // warp row band
    int wnw  = (wid >> 2) * 16;          // warp col base (sub adds +32)

    const __nv_bfloat16* Qh = g_Qhi + ((size_t)bh * SS + row0) * DKK;
    const __nv_bfloat16* Ql = g_Qlo + ((size_t)bh * SS + row0) * DKK;
    const __nv_bfloat16* Kh = g_Khi + (size_t)bh * SS * DKK;
    const __nv_bfloat16* Kl = g_Klo + (size_t)bh * SS * DKK;

    // load Q 64x64 hi/lo (512 uint4 chunks each, 2 per thread)
#pragma unroll
    for (int i = 0; i < 2; i++) {
        int c = i * 256 + tid;
        int r = c >> 3, q = c & 7;
        uint32_t d = (uint32_t)(r * KP + q * 16);
        *(uint4*)(smraw + S_QH + d) = *(const uint4*)(Qh + (size_t)r * 64 + q * 8);
        *(uint4*)(smraw + S_QL + d) = *(const uint4*)(Ql + (size_t)r * 64 + q * 8);
    }

    // zero upper-triangle tiles (pure streaming writes, fully masked region)
    float4* atile = (float4*)attn + ((size_t)bh * SS + row0) * 256;
    float4 z4 = make_float4(0.f, 0.f, 0.f, 0.f);
    for (int nt = rt + 1; nt < 16; nt++)
#pragma unroll
        for (int i = 0; i < 4; i++) {
            int idx = i * 256 + tid;
            atile[(size_t)(idx >> 4) * 256 + nt * 16 + (idx & 15)] = z4;
        }

    auto issue_K = [&](int nt, int st) {
        uint32_t kb = sb + S_K + (uint32_t)st * 18432;
#pragma unroll
        for (int i = 0; i < 2; i++) {
            int c = i * 256 + tid;
            int r = c >> 3, q = c & 7;
            uint32_t d = (uint32_t)(r * KP + q * 16);
            CP_ASYNC16(kb + d,        Kh + (size_t)(nt * 64 + r) * 64 + q * 8);
            CP_ASYNC16(kb + 9216 + d, Kl + (size_t)(nt * 64 + r) * 64 + q * 8);
        }
    };

    uint32_t offA = (uint32_t)((wm + (lane & 15)) * KP + (lane >> 4) * 16);
    uint32_t offB = (uint32_t)((wnw + ((lane >> 4) & 1) * 8 + (lane & 7)) * KP
                               + ((lane >> 3) & 1) * 16);
    int lr = lane >> 2, lc = (lane & 3) * 2;

    // ---------------- pass 1: row sums of exp(s-30) ----------------
    float lsum[2] = {0.0f, 0.0f};
    issue_K(0, 0); CP_COMMIT();
    for (int nt = 0; nt <= rt; nt++) {
        int st = nt & 1;
        CP_WAIT(0);
        __syncthreads();
        if (nt < rt) issue_K(nt + 1, st ^ 1);
        CP_COMMIT();

        uint32_t kb = sb + S_K + (uint32_t)st * 18432;
        float acc[2][2][4];
#pragma unroll
        for (int su = 0; su < 2; su++)
#pragma unroll
            for (int nf = 0; nf < 2; nf++)
#pragma unroll
                for (int t = 0; t < 4; t++) acc[su][nf][t] = 0.0f;

#pragma unroll
        for (int kk = 0; kk < 4; kk++) {
            uint32_t k2 = (uint32_t)(kk * 32);
            uint32_t ah[4], al[4];
            ldsm4(ah, sb + S_QH + offA + k2);
            ldsm4(al, sb + S_QL + offA + k2);
#pragma unroll
            for (int su = 0; su < 2; su++) {
                uint32_t bo = offB + (uint32_t)(su * 32 * KP) + k2;
                uint32_t bhf[4], blf[4];
                ldsm4(bhf, kb + bo);
                ldsm4(blf, kb + 9216 + bo);
#pragma unroll
                for (int nf = 0; nf < 2; nf++) {
                    int hi = nf * 2;
                    mma16816(acc[su][nf], ah, bhf[hi], bhf[hi + 1]);
                    mma16816(acc[su][nf], ah, blf[hi], blf[hi + 1]);
                    mma16816(acc[su][nf], al, bhf[hi], bhf[hi + 1]);
                }
            }
        }
#pragma unroll
        for (int su = 0; su < 2; su++)
#pragma unroll
            for (int nf = 0; nf < 2; nf++)
#pragma unroll
                for (int half = 0; half < 2; half++) {
                    int qr = row0 + wm + lr + half * 8;
                    int c  = nt * 64 + wnw + su * 32 + nf * 8 + lc;
                    float v0 = fminf(fmaxf(acc[su][nf][half*2]   * INV_SCALE, -30.f), 30.f);
                    float v1 = fminf(fmaxf(acc[su][nf][half*2+1] * INV_SCALE, -30.f), 30.f);
                    float e0 = (c     <= qr) ? __expf(v0 - 30.f) : 0.0f;
                    float e1 = (c + 1 <= qr) ? __expf(v1 - 30.f) : 0.0f;
                    lsum[half] += e0 + e1;
                }
    }

    // reduce sums: quad (lanes sharing a row), then across the 2 n-warps
#pragma unroll
    for (int half = 0; half < 2; half++) {
        lsum[half] += __shfl_xor_sync(0xffffffffu, lsum[half], 1);
        lsum[half] += __shfl_xor_sync(0xffffffffu, lsum[half], 2);
    }
    if ((lane & 3) == 0) {
        lbuf[(wid >> 2) * 64 + wm + lr]     = lsum[0];
        lbuf[(wid >> 2) * 64 + wm + lr + 8] = lsum[1];
    }
    __syncthreads();
    if (tid < 64) irow[tid] = 1.0f / (lbuf[tid] + lbuf[64 + tid]);
    __syncthreads();

    // ---------------- pass 2: recompute, normalize, write ----------------
    issue_K(0, 0); CP_COMMIT();
    for (int nt = 0; nt <= rt; nt++) {
        int st = nt & 1;
        CP_WAIT(0);
        __syncthreads();                  // also guards sP reuse
        if (nt < rt) issue_K(nt + 1, st ^ 1);
        CP_COMMIT();

        uint32_t kb = sb + S_K + (uint32_t)st * 18432;
        float acc[2][2][4];
#pragma unroll
        for (int su = 0; su < 2; su++)
#pragma unroll
            for (int nf = 0; nf < 2; nf++)
#pragma unroll
                for (int t = 0; t < 4; t++) acc[su][nf][t] = 0.0f;

#pragma unroll
        for (int kk = 0; kk < 4; kk++) {
            uint32_t k2 = (uint32_t)(kk * 32);
            uint32_t ah[4], al[4];
            ldsm4(ah, sb + S_QH + offA + k2);
            ldsm4(al, sb + S_QL + offA + k2);
#pragma unroll
            for (int su = 0; su < 2; su++) {
                uint32_t bo = offB + (uint32_t)(su * 32 * KP) + k2;
                uint32_t bhf[4], blf[4];
                ldsm4(bhf, kb + bo);
                ldsm4(blf, kb + 9216 + bo);
#pragma unroll
                for (int nf = 0; nf < 2; nf++) {
                    int hi = nf * 2;
                    mma16816(acc[su][nf], ah, bhf[hi], bhf[hi + 1]);
                    mma16816(acc[su][nf], ah, blf[hi], blf[hi + 1]);
                    mma16816(acc[su][nf], al, bhf[hi], bhf[hi + 1]);
                }
            }
        }
#pragma unroll
        for (int su = 0; su < 2; su++)
#pragma unroll
            for (int nf = 0; nf < 2; nf++)
#pragma unroll
                for (int half = 0; half < 2; half++) {
                    int row = wm + lr + half * 8;
                    int qr  = row0 + row;
                    int cl  = wnw + su * 32 + nf * 8 + lc;     // col within tile
                    int c   = nt * 64 + cl;
                    float inv = irow[row];
                    float v0 = fminf(fmaxf(acc[su][nf][half*2]   * INV_SCALE, -30.f), 30.f);
                    float v1 = fminf(fmaxf(acc[su][nf][half*2+1] * INV_SCALE, -30.f), 30.f);
                    sP[row * 68 + cl]     = (c     <= qr) ? __expf(v0 - 30.f) * inv : 0.0f;
                    sP[row * 68 + cl + 1] = (c + 1 <= qr) ? __expf(v1 - 30.f) * inv : 0.0f;
                }
        __syncthreads();
        // coalesced write: 64 rows x 16 float4, 4 per thread
#pragma unroll
        for (int i = 0; i < 4; i++) {
            int idx = i * 256 + tid;
            int r = idx >> 4, f4 = idx & 15;
            atile[(size_t)r * 256 + nt * 16 + f4] = *(float4*)&sP[r * 68 + f4 * 4];
        }
    }
}

// ================= context = attn @ V on HMMA =================
#define AV_PITCH 144
#define AV_AHI 0
#define AV_ALO 18432
#define AV_VHI 36864
#define AV_VLO 46080
#define AV_SMEM 55296

__global__ __launch_bounds__(256) void attn_v(const float* __restrict__ attn)
{
    extern __shared__ __align__(128) char smB[];
    uint32_t sb = s2u(smB);

    int tid  = threadIdx.x;
    int wid  = tid >> 5, lane = tid & 31;
    int bh   = blockIdx.y;
    int rt   = blockIdx.x;            // 0..7
    int wm   = wid * 16;

    const float* Ab = attn + ((size_t)bh * SS + rt * 128) * SS;
    const __nv_bfloat16* Vh = g_Vhi + (size_t)bh * SS * DKK;
    const __nv_bfloat16* Vl = g_Vlo + (size_t)bh * SS * DKK;

    uint32_t offA  = (uint32_t)((wm + (lane & 15)) * AV_PITCH + (lane >> 4) * 16);
    uint32_t offBT = (uint32_t)(((lane & 7) + ((lane >> 3) & 1) * 8) * AV_PITCH
                                + ((lane >> 4) & 1) * 16);

    float acc[8][4];
#pragma unroll
    for (int nf = 0; nf < 8; nf++)
#pragma unroll
        for (int t = 0; t < 4; t++) acc[nf][t] = 0.0f;

    int ktmax = rt * 2 + 1;
    for (int kt = 0; kt <= ktmax; kt++) {
        __syncthreads();
#pragma unroll
        for (int i = 0; i < 8; i++) {
            int c = i * 256 + tid;            // 0..2047
            int r = c >> 4;
            int q = c & 15;
            float4 a = *(const float4*)(Ab + (size_t)r * SS + kt * 64 + q * 4);
            uint32_t h01, l01, h23, l23;
            split2(a.x, a.y, h01, l01);
            split2(a.z, a.w, h23, l23);
            uint32_t d = (uint32_t)(r * AV_PITCH + q * 8);
            *(uint2*)(smB + AV_AHI + d) = make_uint2(h01, h23);
            *(uint2*)(smB + AV_ALO + d) = make_uint2(l01, l23);
        }
#pragma unroll
        for (int i = 0; i < 2; i++) {
            int c = i * 256 + tid;
            int r = c >> 3, q = c & 7;
            uint32_t d = (uint32_t)(r * AV_PITCH + q * 16);
            *(uint4*)(smB + AV_VHI + d) = *(const uint4*)(Vh + (size_t)(kt*64 + r) * 64 + q * 8);
            *(uint4*)(smB + AV_VLO + d) = *(const uint4*)(Vl + (size_t)(kt*64 + r) * 64 + q * 8);
        }
        __syncthreads();

#pragma unroll
        for (int kk = 0; kk < 4; kk++) {
            uint32_t ah[4], al[4], bhf[4][4], blf[4][4];
            ldsm4(ah, sb + AV_AHI + offA + kk * 32);
            ldsm4(al, sb + AV_ALO + offA + kk * 32);
#pragma unroll
            for (int g = 0; g < 4; g++) {
                uint32_t ba = offBT + (uint32_t)(kk * 16 * AV_PITCH + g * 32);
                ldsm4t(bhf[g], sb + AV_VHI + ba);
                ldsm4t(blf[g], sb + AV_VLO + ba);
            }
#pragma unroll
            for (int nf = 0; nf < 8; nf++) {
                int g = nf >> 1, s2i = (nf & 1) * 2;
                mma16816(acc[nf], ah, bhf[g][s2i], bhf[g][s2i + 1]);
                mma16816(acc[nf], ah, blf[g][s2i], blf[g][s2i + 1]);
                mma16816(acc[nf], al, bhf[g][s2i], bhf[g][s2i + 1]);
            }
        }
    }

    int lr = lane >> 2, lc = (lane & 3) * 2;
    int b = bh >> 4, h = bh & 15;
#pragma unroll
    for (int nf = 0; nf < 8; nf++)
#pragma unroll
        for (int half = 0; half < 2; half++) {
            int m = rt * 128 + wm + lr + half * 8;
            int c = nf * 8 + lc;
            size_t off = ((size_t)b * SS + m) * DD + h * DKK + c;
            uint32_t hh, ll;
            split2(acc[nf][half*2], acc[nf][half*2+1], hh, ll);
            *(uint32_t*)(g_Chi + off) = hh;
            *(uint32_t*)(g_Clo + off) = ll;
        }
}

// ============================================================
extern "C" void kernel_launch(void* const* d_in, const int* in_sizes, int n_in,
                              void* d_out, int out_size)
{
    (void)in_sizes; (void)n_in;
    const float* q  = (const float*)d_in[0];
    const float* k  = (const float*)d_in[1];
    const float* v  = (const float*)d_in[2];
    const float* Wq = (const float*)d_in[4];
    const float* Wk = (const float*)d_in[5];
    const float* Wv = (const float*)d_in[6];
    const float* Wo = (const float*)d_in[7];
    float* out = (float*)d_out;

    const size_t OUTE  = (size_t)BB * SS * DD;        // 8,388,608
    const size_t ATTNE = (size_t)BB * HH * SS * SS;   // 134,217,728

    float* attn_ptr;
    bool write_out = true;
    size_t osz = (size_t)out_size;
    if (osz >= OUTE + ATTNE) {
        attn_ptr = out + OUTE;
    } else if (osz == ATTNE) {
        attn_ptr = out;
        write_out = false;
    } else {
        void* p = nullptr;
        cudaGetSymbolAddress(&p, g_attn);
        attn_ptr = (float*)p;
    }

    // 1. bf16 splits (2 launches)
    split_x<<<dim3(2097152/256, 3), 256>>>(q, k, v);
    split_w<<<dim3(262144/256, 4), 256>>>(Wq, Wk, Wv, Wo);

    // 2. q/k/v projections merged into one launch (mode = blockIdx.z)
    cudaFuncSetAttribute(mma_gemm, cudaFuncAttributeMaxDynamicSharedMemorySize, GEMM_SMEM);
    mma_gemm<<<dim3(8, 64, 3), 256, GEMM_SMEM>>>(nullptr, -1);

    // 3. scores: two-pass streaming softmax on HMMA
    cudaFuncSetAttribute(attn_scores, cudaFuncAttributeMaxDynamicSharedMemorySize, SC2_SMEM);
    attn_scores<<<dim3(16, 128), 256, SC2_SMEM>>>(attn_ptr);

    // 4. context on HMMA (+ bf16 split epilogue)
    cudaFuncSetAttribute(attn_v, cudaFuncAttributeMaxDynamicSharedMemorySize, AV_SMEM);
    attn_v<<<dim3(8, 128), 256, AV_SMEM>>>(attn_ptr);

    // 5. output projection
    if (write_out)
        mma_gemm<<<dim3(8, 64, 1), 256, GEMM_SMEM>>>(out, 3);
}

// round 12
// speedup vs baseline: 3.0575x; 1.0613x over previous
#include <cuda_runtime.h>
#include <cuda_bf16.h>
#include <cstdint>
#include <cstddef>

// Problem constants
#define BB   8
#define SS   1024
#define DD   1024
#define HH   16
#define DKK  64
#define INV_SCALE (1.0f/16.0f)   // SCALE = sqrt(64)*2 = 16

// ---------------- scratch (no cudaMalloc allowed) ----------------
__device__ __nv_bfloat16 g_Xhi[3u*8388608u];   // input splits q,k,v
__device__ __nv_bfloat16 g_Xlo[3u*8388608u];
__device__ __nv_bfloat16 g_Whi_[4u*1048576u];  // weight splits Wq,Wk,Wv,Wo
__device__ __nv_bfloat16 g_Wlo_[4u*1048576u];
__device__ __nv_bfloat16 g_Qhi[BB*HH*SS*DKK];  // [B,H,S,dk] bf16 splits
__device__ __nv_bfloat16 g_Qlo[BB*HH*SS*DKK];
__device__ __nv_bfloat16 g_Khi[BB*HH*SS*DKK];
__device__ __nv_bfloat16 g_Klo[BB*HH*SS*DKK];
__device__ __nv_bfloat16 g_Vhi[BB*HH*SS*DKK];
__device__ __nv_bfloat16 g_Vlo[BB*HH*SS*DKK];
__device__ __nv_bfloat16 g_Chi[BB*SS*DD];      // ctx splits [B,S,D]
__device__ __nv_bfloat16 g_Clo[BB*SS*DD];
__device__ float g_attn[(size_t)BB*HH*SS*SS];  // fallback

__device__ __forceinline__ uint32_t s2u(const void* p) {
    return (uint32_t)__cvta_generic_to_shared(p);
}
#define CP_ASYNC16(dst, src) \
    asm volatile("cp.async.cg.shared.global [%0], [%1], 16;" :: "r"(dst), "l"(src))
#define CP_COMMIT() asm volatile("cp.async.commit_group;" ::: "memory")
#define CP_WAIT(n)  asm volatile("cp.async.wait_group %0;" :: "n"(n) : "memory")

__device__ __forceinline__ void ldsm4(uint32_t* r, uint32_t addr) {
    asm volatile("ldmatrix.sync.aligned.m8n8.x4.shared.b16 {%0,%1,%2,%3}, [%4];"
                 : "=r"(r[0]), "=r"(r[1]), "=r"(r[2]), "=r"(r[3]) : "r"(addr));
}
__device__ __forceinline__ void ldsm4t(uint32_t* r, uint32_t addr) {
    asm volatile("ldmatrix.sync.aligned.m8n8.x4.trans.shared.b16 {%0,%1,%2,%3}, [%4];"
                 : "=r"(r[0]), "=r"(r[1]), "=r"(r[2]), "=r"(r[3]) : "r"(addr));
}
__device__ __forceinline__ void mma16816(float* d, const uint32_t* a,
                                         uint32_t b0, uint32_t b1) {
    asm volatile("mma.sync.aligned.m16n8k16.row.col.f32.bf16.bf16.f32 "
        "{%0,%1,%2,%3}, {%4,%5,%6,%7}, {%8,%9}, {%0,%1,%2,%3};"
        : "+f"(d[0]), "+f"(d[1]), "+f"(d[2]), "+f"(d[3])
        : "r"(a[0]), "r"(a[1]), "r"(a[2]), "r"(a[3]), "r"(b0), "r"(b1));
}
__device__ __forceinline__ void split2(float x, float y, uint32_t& h, uint32_t& l) {
    __nv_bfloat162 hh, ll;
    hh.x = __float2bfloat16(x); ll.x = __float2bfloat16(x - __bfloat162float(hh.x));
    hh.y = __float2bfloat16(y); ll.y = __float2bfloat16(y - __bfloat162float(hh.y));
    h = *(uint32_t*)&hh; l = *(uint32_t*)&ll;
}

// ================= split kernels (batched) =================
__global__ void split_x(const float* __restrict__ q, const float* __restrict__ k,
                        const float* __restrict__ v)
{
    int slot = blockIdx.y;
    const float* src = (slot == 0) ? q : (slot == 1) ? k : v;
    int i = blockIdx.x * blockDim.x + threadIdx.x;          // < 2097152
    __nv_bfloat16* hi = g_Xhi + (size_t)slot * 8388608u;
    __nv_bfloat16* lo = g_Xlo + (size_t)slot * 8388608u;
    float4 f = ((const float4*)src)[i];
    uint32_t h01, l01, h23, l23;
    split2(f.x, f.y, h01, l01);
    split2(f.z, f.w, h23, l23);
    ((uint32_t*)hi)[i*2] = h01; ((uint32_t*)hi)[i*2+1] = h23;
    ((uint32_t*)lo)[i*2] = l01; ((uint32_t*)lo)[i*2+1] = l23;
}
__global__ void split_w(const float* __restrict__ wq, const float* __restrict__ wk,
                        const float* __restrict__ wv, const float* __restrict__ wo)
{
    int slot = blockIdx.y;
    const float* src = (slot == 0) ? wq : (slot == 1) ? wk : (slot == 2) ? wv : wo;
    int i = blockIdx.x * blockDim.x + threadIdx.x;          // < 262144
    __nv_bfloat16* hi = g_Whi_ + (size_t)slot * 1048576u;
    __nv_bfloat16* lo = g_Wlo_ + (size_t)slot * 1048576u;
    float4 f = ((const float4*)src)[i];
    uint32_t h01, l01, h23, l23;
    split2(f.x, f.y, h01, l01);
    split2(f.z, f.w, h23, l23);
    ((uint32_t*)hi)[i*2] = h01; ((uint32_t*)hi)[i*2+1] = h23;
    ((uint32_t*)lo)[i*2] = l01; ((uint32_t*)lo)[i*2+1] = l23;
}

// ================= HMMA GEMM, cp.async 2-stage pipeline, 2 CTAs/SM =========
#define PITCH    80
#define T_AHI    0
#define T_ALO    10240
#define T_WHI    20480
#define T_WLO    30720
#define STAGE_SZ 40960
#define N_STAGES 2
#define GEMM_SMEM (N_STAGES*STAGE_SZ)   // 81920 B -> 2 CTAs/SM

__global__ __launch_bounds__(256, 2) void mma_gemm(float* __restrict__ Cout, int mode_arg)
{
    extern __shared__ __align__(128) char sm[];
    uint32_t sb = s2u(sm);

    int mode = (mode_arg < 0) ? (int)blockIdx.z : mode_arg;

    int tid  = threadIdx.x;
    int wid  = tid >> 5, lane = tid & 31;
    int bm   = blockIdx.y * 128, bn = blockIdx.x * 128;
    int wm   = (wid & 1) * 64;
    int wn   = (wid >> 1) * 32;

    const __nv_bfloat16* Ah = (mode < 3) ? (g_Xhi + (size_t)mode * 8388608u) : g_Chi;
    const __nv_bfloat16* Al = (mode < 3) ? (g_Xlo + (size_t)mode * 8388608u) : g_Clo;
    const __nv_bfloat16* Wh = g_Whi_ + (size_t)mode * 1048576u;
    const __nv_bfloat16* Wl = g_Wlo_ + (size_t)mode * 1048576u;

    int c0 = tid, c1 = tid + 256;
    int r0 = c0 >> 2, q0 = c0 & 3;
    int r1 = c1 >> 2, q1 = c1 & 3;
    const __nv_bfloat16* gAh0 = Ah + (size_t)(bm + r0) * 1024 + q0 * 8;
    const __nv_bfloat16* gAh1 = Ah + (size_t)(bm + r1) * 1024 + q1 * 8;
    const __nv_bfloat16* gAl0 = Al + (size_t)(bm + r0) * 1024 + q0 * 8;
    const __nv_bfloat16* gAl1 = Al + (size_t)(bm + r1) * 1024 + q1 * 8;
    const __nv_bfloat16* gWh0 = Wh + (size_t)(bn + r0) * 1024 + q0 * 8;
    const __nv_bfloat16* gWh1 = Wh + (size_t)(bn + r1) * 1024 + q1 * 8;
    const __nv_bfloat16* gWl0 = Wl + (size_t)(bn + r0) * 1024 + q0 * 8;
    const __nv_bfloat16* gWl1 = Wl + (size_t)(bn + r1) * 1024 + q1 * 8;
    uint32_t sd0 = (uint32_t)(r0 * PITCH + q0 * 16);
    uint32_t sd1 = (uint32_t)(r1 * PITCH + q1 * 16);

    uint32_t offA = (uint32_t)((wm + (lane & 15)) * PITCH + (lane >> 4) * 16);
    uint32_t offB = (uint32_t)((wn + ((lane >> 4) & 1) * 8 + (lane & 7)) * PITCH
                               + ((lane >> 3) & 1) * 16);

    float acc[4][4][4];
#pragma unroll
    for (int i = 0; i < 4; i++)
#pragma unroll
        for (int j = 0; j < 4; j++)
#pragma unroll
            for (int t = 0; t < 4; t++) acc[i][j][t] = 0.0f;

    auto issue_stage = [&](int kt, int s) {
        uint32_t st = sb + (uint32_t)s * STAGE_SZ;
        size_t ko = (size_t)kt * 32;
        CP_ASYNC16(st + T_AHI + sd0, gAh0 + ko); CP_ASYNC16(st + T_AHI + sd1, gAh1 + ko);
        CP_ASYNC16(st + T_ALO + sd0, gAl0 + ko); CP_ASYNC16(st + T_ALO + sd1, gAl1 + ko);
        CP_ASYNC16(st + T_WHI + sd0, gWh0 + ko); CP_ASYNC16(st + T_WHI + sd1, gWh1 + ko);
        CP_ASYNC16(st + T_WLO + sd0, gWl0 + ko); CP_ASYNC16(st + T_WLO + sd1, gWl1 + ko);
    };

    issue_stage(0, 0); CP_COMMIT();
    issue_stage(1, 1); CP_COMMIT();

    for (int kt = 0; kt < 32; kt++) {
        int s = kt & 1;
        CP_WAIT(1);
        __syncthreads();

        uint32_t stg = sb + (uint32_t)s * STAGE_SZ;
#pragma unroll
        for (int kk = 0; kk < 2; kk++) {
            uint32_t k2 = (uint32_t)(kk * 32);
            uint32_t ah[4][4], al[4][4], bhf[2][4], blf[2][4];
#pragma unroll
            for (int mf = 0; mf < 4; mf++) {
                ldsm4(ah[mf], stg + T_AHI + offA + mf * (16 * PITCH) + k2);
                ldsm4(al[mf], stg + T_ALO + offA + mf * (16 * PITCH) + k2);
            }
#pragma unroll
            for (int nf2 = 0; nf2 < 2; nf2++) {
                ldsm4(bhf[nf2], stg + T_WHI + offB + nf2 * (16 * PITCH) + k2);
                ldsm4(blf[nf2], stg + T_WLO + offB + nf2 * (16 * PITCH) + k2);
            }
#pragma unroll
            for (int mf = 0; mf < 4; mf++)
#pragma unroll
                for (int nf = 0; nf < 4; nf++) {
                    int n2 = nf >> 1, hi = (nf & 1) * 2;
                    mma16816(acc[mf][nf], ah[mf], bhf[n2][hi], bhf[n2][hi + 1]);
                    mma16816(acc[mf][nf], ah[mf], blf[n2][hi], blf[n2][hi + 1]);
                    mma16816(acc[mf][nf], al[mf], bhf[n2][hi], bhf[n2][hi + 1]);
                }
        }

        __syncthreads();
        if (kt + 2 < 32) issue_stage(kt + 2, s);
        CP_COMMIT();
    }

    int lr = lane >> 2, lc = (lane & 3) * 2;
#pragma unroll
    for (int mf = 0; mf < 4; mf++)
#pragma unroll
        for (int nf = 0; nf < 4; nf++) {
            int r = bm + wm + mf * 16 + lr;
            int c = bn + wn + nf * 8 + lc;
            float2 v0 = make_float2(acc[mf][nf][0], acc[mf][nf][1]);
            float2 v1 = make_float2(acc[mf][nf][2], acc[mf][nf][3]);
            if (mode == 3) {
                *(float2*)(Cout + (size_t)r * 1024 + c)       = v0;
                *(float2*)(Cout + (size_t)(r + 8) * 1024 + c) = v1;
            } else {
                int h = c >> 6, dk = c & 63;
                int b0i = r >> 10, s0 = r & 1023;
                int b1i = (r + 8) >> 10, s1 = (r + 8) & 1023;
                size_t o0 = (((size_t)(b0i*HH + h) * SS + s0) << 6) + dk;
                size_t o1 = (((size_t)(b1i*HH + h) * SS + s1) << 6) + dk;
                __nv_bfloat16* ghi = (mode == 0) ? g_Qhi : (mode == 1) ? g_Khi : g_Vhi;
                __nv_bfloat16* glo = (mode == 0) ? g_Qlo : (mode == 1) ? g_Klo : g_Vlo;
                uint32_t h0, l0, h1, l1;
                split2(v0.x, v0.y, h0, l0);
                split2(v1.x, v1.y, h1, l1);
                *(uint32_t*)(ghi + o0) = h0; *(uint32_t*)(glo + o0) = l0;
                *(uint32_t*)(ghi + o1) = h1; *(uint32_t*)(glo + o1) = l1;
            }
        }
}

// ===== fused scores + softmax + attn write + P@V context (FA-style) =====
// CTA = 64 q-rows of one (b,h); 8 warps: 4(m) x 2(n). Fixed-offset softmax
// (scores clipped to [-30,30] -> exp(s-30), shift-invariant, no max pass).
// Pass1: row sums of exp(s-30) (K only). Pass2: recompute S, normalize,
// write attn directly (sector-aligned float2 stores), reuse S C-fragments
// as P A-fragments (C layout == A layout for paired n8 tiles), multiply by
// V tiles streamed in the same cp.async pipeline; per-warp partial ctx over
// its k-columns; cross-warp smem reduction; bf16 hi/lo ctx epilogue.
#define KP    144           // bf16 tile pitch bytes (64 bf16 + 16 pad)
#define S_QH  0
#define S_QL  9216
#define S_K   18432         // stage st at +st*STG: Khi 0, Klo 9216, Vhi 18432, Vlo 27648
#define STG   36864
#define S_LB  92160         // float lbuf[2][64]
#define S_IR  92672         // float irow[64]
#define FUSED_SMEM 92928    // -> 2 CTAs/SM
#define S_RED S_K           // ctx reduce buffers reuse stage area (2 x 64x68 fp32)

__global__ __launch_bounds__(256, 2) void attn_fused(float* __restrict__ attn)
{
    extern __shared__ __align__(128) char smraw[];
    uint32_t sb = s2u(smraw);
    float* lbuf = (float*)(smraw + S_LB);
    float* irow = (float*)(smraw + S_IR);

    int tid  = threadIdx.x;
    int wid  = tid >> 5, lane = tid & 31;
    int bh   = blockIdx.y;
    int rt   = blockIdx.x;               // 0..15, row0 = rt*64, tiles 0..rt
    int row0 = rt * 64;
    int wm   = (wid & 3) * 16;           // warp row band
    int wnw  = (wid >> 2) * 16;          // warp col base (su adds +32)

    const __nv_bfloat16* Qh = g_Qhi + ((size_t)bh * SS + row0) * DKK;
    const __nv_bfloat16* Ql = g_Qlo + ((size_t)bh * SS + row0) * DKK;
    const __nv_bfloat16* Kh = g_Khi + (size_t)bh * SS * DKK;
    const __nv_bfloat16* Kl = g_Klo + (size_t)bh * SS * DKK;
    const __nv_bfloat16* Vh = g_Vhi + (size_t)bh * SS * DKK;
    const __nv_bfloat16* Vl = g_Vlo + (size_t)bh * SS * DKK;

    // load Q 64x64 hi/lo (512 uint4 chunks each, 2 per thread)
#pragma unroll
    for (int i = 0; i < 2; i++) {
        int c = i * 256 + tid;
        int r = c >> 3, q = c & 7;
        uint32_t d = (uint32_t)(r * KP + q * 16);
        *(uint4*)(smraw + S_QH + d) = *(const uint4*)(Qh + (size_t)r * 64 + q * 8);
        *(uint4*)(smraw + S_QL + d) = *(const uint4*)(Ql + (size_t)r * 64 + q * 8);
    }

    // zero upper-triangle tiles (fully masked region)
    float4* atile = (float4*)attn + ((size_t)bh * SS + row0) * 256;
    float4 z4 = make_float4(0.f, 0.f, 0.f, 0.f);
    for (int nt = rt + 1; nt < 16; nt++)
#pragma unroll
        for (int i = 0; i < 4; i++) {
            int idx = i * 256 + tid;
            atile[(size_t)(idx >> 4) * 256 + nt * 16 + (idx & 15)] = z4;
        }

    auto issue_K = [&](int nt, int st, bool withV) {
        uint32_t kb = sb + S_K + (uint32_t)st * STG;
#pragma unroll
        for (int i = 0; i < 2; i++) {
            int c = i * 256 + tid;
            int r = c >> 3, q = c & 7;
            uint32_t d = (uint32_t)(r * KP + q * 16);
            size_t go = (size_t)(nt * 64 + r) * 64 + q * 8;
            CP_ASYNC16(kb + d,        Kh + go);
            CP_ASYNC16(kb + 9216 + d, Kl + go);
            if (withV) {
                CP_ASYNC16(kb + 18432 + d, Vh + go);
                CP_ASYNC16(kb + 27648 + d, Vl + go);
            }
        }
    };

    uint32_t offA = (uint32_t)((wm + (lane & 15)) * KP + (lane >> 4) * 16);
    uint32_t offB = (uint32_t)((wnw + ((lane >> 4) & 1) * 8 + (lane & 7)) * KP
                               + ((lane >> 3) & 1) * 16);
    uint32_t offBT = (uint32_t)(((lane & 7) + ((lane >> 3) & 1) * 8) * KP
                                + ((lane >> 4) & 1) * 16);
    int lr = lane >> 2, lc = (lane & 3) * 2;
    int qr0 = row0 + wm + lr, qr1 = qr0 + 8;

    // ---------------- pass 1: row sums of exp(s-30) ----------------
    float lsum[2] = {0.0f, 0.0f};
    issue_K(0, 0, false); CP_COMMIT();
    for (int nt = 0; nt <= rt; nt++) {
        int st = nt & 1;
        CP_WAIT(0);
        __syncthreads();
        if (nt < rt) issue_K(nt + 1, st ^ 1, false);
        CP_COMMIT();

        uint32_t kb = sb + S_K + (uint32_t)st * STG;
        float acc[2][2][4];
#pragma unroll
        for (int su = 0; su < 2; su++)
#pragma unroll
            for (int nf = 0; nf < 2; nf++)
#pragma unroll
                for (int t = 0; t < 4; t++) acc[su][nf][t] = 0.0f;

#pragma unroll
        for (int kk = 0; kk < 4; kk++) {
            uint32_t k2 = (uint32_t)(kk * 32);
            uint32_t ah[4], al[4];
            ldsm4(ah, sb + S_QH + offA + k2);
            ldsm4(al, sb + S_QL + offA + k2);
#pragma unroll
            for (int su = 0; su < 2; su++) {
                uint32_t bo = offB + (uint32_t)(su * 32 * KP) + k2;
                uint32_t bhf[4], blf[4];
                ldsm4(bhf, kb + bo);
                ldsm4(blf, kb + 9216 + bo);
#pragma unroll
                for (int nf = 0; nf < 2; nf++) {
                    int hi = nf * 2;
                    mma16816(acc[su][nf], ah, bhf[hi], bhf[hi + 1]);
                    mma16816(acc[su][nf], ah, blf[hi], blf[hi + 1]);
                    mma16816(acc[su][nf], al, bhf[hi], bhf[hi + 1]);
                }
            }
        }
#pragma unroll
        for (int su = 0; su < 2; su++)
#pragma unroll
            for (int nf = 0; nf < 2; nf++) {
                int c = nt * 64 + wnw + su * 32 + nf * 8 + lc;
                float v0 = fminf(fmaxf(acc[su][nf][0] * INV_SCALE, -30.f), 30.f);
                float v1 = fminf(fmaxf(acc[su][nf][1] * INV_SCALE, -30.f), 30.f);
                float v2 = fminf(fmaxf(acc[su][nf][2] * INV_SCALE, -30.f), 30.f);
                float v3 = fminf(fmaxf(acc[su][nf][3] * INV_SCALE, -30.f), 30.f);
                lsum[0] += ((c     <= qr0) ? __expf(v0 - 30.f) : 0.0f)
                         + ((c + 1 <= qr0) ? __expf(v1 - 30.f) : 0.0f);
                lsum[1] += ((c     <= qr1) ? __expf(v2 - 30.f) : 0.0f)
                         + ((c + 1 <= qr1) ? __expf(v3 - 30.f) : 0.0f);
            }
    }

    // reduce sums: quad (lanes sharing a row), then across the 2 n-warps
#pragma unroll
    for (int half = 0; half < 2; half++) {
        lsum[half] += __shfl_xor_sync(0xffffffffu, lsum[half], 1);
        lsum[half] += __shfl_xor_sync(0xffffffffu, lsum[half], 2);
    }
    if ((lane & 3) == 0) {
        lbuf[(wid >> 2) * 64 + wm + lr]     = lsum[0];
        lbuf[(wid >> 2) * 64 + wm + lr + 8] = lsum[1];
    }
    __syncthreads();
    if (tid < 64) irow[tid] = 1.0f / (lbuf[tid] + lbuf[64 + tid]);
    __syncthreads();

    float inv0 = irow[wm + lr], inv1 = irow[wm + lr + 8];
    float* arow_t = attn + ((size_t)bh * SS + qr0) * SS;
    float* arow_b = attn + ((size_t)bh * SS + qr1) * SS;

    // ---------- pass 2: recompute S, write attn, P@V accumulate ----------
    float ctx[8][4];
#pragma unroll
    for (int nf2 = 0; nf2 < 8; nf2++)
#pragma unroll
        for (int t = 0; t < 4; t++) ctx[nf2][t] = 0.0f;

    issue_K(0, 0, true); CP_COMMIT();
    for (int nt = 0; nt <= rt; nt++) {
        int st = nt & 1;
        CP_WAIT(0);
        __syncthreads();
        if (nt < rt) issue_K(nt + 1, st ^ 1, true);
        CP_COMMIT();

        uint32_t kb = sb + S_K + (uint32_t)st * STG;
        float acc[2][2][4];
#pragma unroll
        for (int su = 0; su < 2; su++)
#pragma unroll
            for (int nf = 0; nf < 2; nf++)
#pragma unroll
                for (int t = 0; t < 4; t++) acc[su][nf][t] = 0.0f;

#pragma unroll
        for (int kk = 0; kk < 4; kk++) {
            uint32_t k2 = (uint32_t)(kk * 32);
            uint32_t ah[4], al[4];
            ldsm4(ah, sb + S_QH + offA + k2);
            ldsm4(al, sb + S_QL + offA + k2);
#pragma unroll
            for (int su = 0; su < 2; su++) {
                uint32_t bo = offB + (uint32_t)(su * 32 * KP) + k2;
                uint32_t bhf[4], blf[4];
                ldsm4(bhf, kb + bo);
                ldsm4(blf, kb + 9216 + bo);
#pragma unroll
                for (int nf = 0; nf < 2; nf++) {
                    int hi = nf * 2;
                    mma16816(acc[su][nf], ah, bhf[hi], bhf[hi + 1]);
                    mma16816(acc[su][nf], ah, blf[hi], blf[hi + 1]);
                    mma16816(acc[su][nf], al, bhf[hi], bhf[hi + 1]);
                }
            }
        }

#pragma unroll
        for (int su = 0; su < 2; su++) {
            float pn[2][4];
#pragma unroll
            for (int nf = 0; nf < 2; nf++) {
                int c = nt * 64 + wnw + su * 32 + nf * 8 + lc;
                float v0 = fminf(fmaxf(acc[su][nf][0] * INV_SCALE, -30.f), 30.f);
                float v1 = fminf(fmaxf(acc[su][nf][1] * INV_SCALE, -30.f), 30.f);
                float v2 = fminf(fmaxf(acc[su][nf][2] * INV_SCALE, -30.f), 30.f);
                float v3 = fminf(fmaxf(acc[su][nf][3] * INV_SCALE, -30.f), 30.f);
                pn[nf][0] = (c     <= qr0) ? __expf(v0 - 30.f) * inv0 : 0.0f;
                pn[nf][1] = (c + 1 <= qr0) ? __expf(v1 - 30.f) * inv0 : 0.0f;
                pn[nf][2] = (c     <= qr1) ? __expf(v2 - 30.f) * inv1 : 0.0f;
                pn[nf][3] = (c + 1 <= qr1) ? __expf(v3 - 30.f) * inv1 : 0.0f;
                // direct attn store: each 4-lane quad covers a 32B sector
                *(float2*)(arow_t + c) = make_float2(pn[nf][0], pn[nf][1]);
                *(float2*)(arow_b + c) = make_float2(pn[nf][2], pn[nf][3]);
            }
            // P C-frags -> A-frags (m16k16), bf16 hi/lo split
            uint32_t pah[4], pal[4];
            split2(pn[0][0], pn[0][1], pah[0], pal[0]);
            split2(pn[0][2], pn[0][3], pah[1], pal[1]);
            split2(pn[1][0], pn[1][1], pah[2], pal[2]);
            split2(pn[1][2], pn[1][3], pah[3], pal[3]);
            int kc = su * 2 + (wnw >> 4);     // k16 chunk within 64-key tile
#pragma unroll
            for (int g = 0; g < 4; g++) {     // dk 16-col groups
                uint32_t ba = offBT + (uint32_t)(kc * 16 * KP + g * 32);
                uint32_t vh[4], vl[4];
                ldsm4t(vh, kb + 18432 + ba);
                ldsm4t(vl, kb + 27648 + ba);
#pragma unroll
                for (int s2 = 0; s2 < 2; s2++) {
                    int nf2 = g * 2 + s2;
                    mma16816(ctx[nf2], pah, vh[s2*2], vh[s2*2 + 1]);
                    mma16816(ctx[nf2], pah, vl[s2*2], vl[s2*2 + 1]);
                    mma16816(ctx[nf2], pal, vh[s2*2], vh[s2*2 + 1]);
                }
            }
        }
    }

    // ---------------- ctx cross-warp reduction + epilogue ----------------
    __syncthreads();                           // stage buffers free now
    float* sred = (float*)(smraw + S_RED) + (wid >> 2) * (64 * 68);
#pragma unroll
    for (int nf2 = 0; nf2 < 8; nf2++) {
        *(float2*)&sred[(wm + lr) * 68 + nf2 * 8 + lc]     = make_float2(ctx[nf2][0], ctx[nf2][1]);
        *(float2*)&sred[(wm + lr + 8) * 68 + nf2 * 8 + lc] = make_float2(ctx[nf2][2], ctx[nf2][3]);
    }
    __syncthreads();

    {
        float* s0 = (float*)(smraw + S_RED);
        float* s1 = s0 + 64 * 68;
        int row = tid >> 2;
        int cq  = (tid & 3) * 16;
        int b = bh >> 4, h = bh & 15;
        size_t obase = ((size_t)b * SS + row0 + row) * DD + h * DKK;
#pragma unroll
        for (int j = 0; j < 4; j++) {
            int col = cq + j * 4;
            int si = row * 68 + col;
            float f0 = s0[si]     + s1[si];
            float f1 = s0[si + 1] + s1[si + 1];
            float f2 = s0[si + 2] + s1[si + 2];
            float f3 = s0[si + 3] + s1[si + 3];
            uint32_t h01, l01, h23, l23;
            split2(f0, f1, h01, l01);
            split2(f2, f3, h23, l23);
            *(uint2*)(g_Chi + obase + col) = make_uint2(h01, h23);
            *(uint2*)(g_Clo + obase + col) = make_uint2(l01, l23);
        }
    }
}

// ============================================================
extern "C" void kernel_launch(void* const* d_in, const int* in_sizes, int n_in,
                              void* d_out, int out_size)
{
    (void)in_sizes; (void)n_in;
    const float* q  = (const float*)d_in[0];
    const float* k  = (const float*)d_in[1];
    const float* v  = (const float*)d_in[2];
    const float* Wq = (const float*)d_in[4];
    const float* Wk = (const float*)d_in[5];
    const float* Wv = (const float*)d_in[6];
    const float* Wo = (const float*)d_in[7];
    float* out = (float*)d_out;

    const size_t OUTE  = (size_t)BB * SS * DD;        // 8,388,608
    const size_t ATTNE = (size_t)BB * HH * SS * SS;   // 134,217,728

    float* attn_ptr;
    bool write_out = true;
    size_t osz = (size_t)out_size;
    if (osz >= OUTE + ATTNE) {
        attn_ptr = out + OUTE;
    } else if (osz == ATTNE) {
        attn_ptr = out;
        write_out = false;
    } else {
        void* p = nullptr;
        cudaGetSymbolAddress(&p, g_attn);
        attn_ptr = (float*)p;
    }

    // 1. bf16 splits (2 launches)
    split_x<<<dim3(2097152/256, 3), 256>>>(q, k, v);
    split_w<<<dim3(262144/256, 4), 256>>>(Wq, Wk, Wv, Wo);

    // 2. q/k/v projections merged into one launch (mode = blockIdx.z)
    cudaFuncSetAttribute(mma_gemm, cudaFuncAttributeMaxDynamicSharedMemorySize, GEMM_SMEM);
    mma_gemm<<<dim3(8, 64, 3), 256, GEMM_SMEM>>>(nullptr, -1);

    // 3. fused scores + softmax + attn write + P@V context
    cudaFuncSetAttribute(attn_fused, cudaFuncAttributeMaxDynamicSharedMemorySize, FUSED_SMEM);
    attn_fused<<<dim3(16, 128), 256, FUSED_SMEM>>>(attn_ptr);

    // 4. output projection
    if (write_out)
        mma_gemm<<<dim3(8, 64, 1), 256, GEMM_SMEM>>>(out, 3);
}

// round 14
// speedup vs baseline: 3.4049x; 1.1136x over previous
#include <cuda_runtime.h>
#include <cuda_bf16.h>
#include <cstdint>
#include <cstddef>

// Problem constants
#define BB   8
#define SS   1024
#define DD   1024
#define HH   16
#define DKK  64
#define INV_SCALE (1.0f/16.0f)   // SCALE = sqrt(64)*2 = 16

// ---------------- scratch (no cudaMalloc allowed) ----------------
__device__ __nv_bfloat16 g_Xhi[3u*8388608u];   // input splits q,k,v
__device__ __nv_bfloat16 g_Xlo[3u*8388608u];
__device__ __nv_bfloat16 g_Whi_[4u*1048576u];  // weight splits Wq,Wk,Wv,Wo
__device__ __nv_bfloat16 g_Wlo_[4u*1048576u];
__device__ __nv_bfloat16 g_Qhi[BB*HH*SS*DKK];  // [B,H,S,dk] bf16 splits
__device__ __nv_bfloat16 g_Qlo[BB*HH*SS*DKK];
__device__ __nv_bfloat16 g_Khi[BB*HH*SS*DKK];
__device__ __nv_bfloat16 g_Klo[BB*HH*SS*DKK];
__device__ __nv_bfloat16 g_Vhi[BB*HH*SS*DKK];
__device__ __nv_bfloat16 g_Vlo[BB*HH*SS*DKK];
__device__ __nv_bfloat16 g_Chi[BB*SS*DD];      // ctx splits [B,S,D]
__device__ __nv_bfloat16 g_Clo[BB*SS*DD];
__device__ float g_attn[(size_t)BB*HH*SS*SS];  // fallback

__device__ __forceinline__ uint32_t s2u(const void* p) {
    return (uint32_t)__cvta_generic_to_shared(p);
}
#define CP_ASYNC16(dst, src) \
    asm volatile("cp.async.cg.shared.global [%0], [%1], 16;" :: "r"(dst), "l"(src))
#define CP_COMMIT() asm volatile("cp.async.commit_group;" ::: "memory")
#define CP_WAIT(n)  asm volatile("cp.async.wait_group %0;" :: "n"(n) : "memory")

__device__ __forceinline__ void ldsm4(uint32_t* r, uint32_t addr) {
    asm volatile("ldmatrix.sync.aligned.m8n8.x4.shared.b16 {%0,%1,%2,%3}, [%4];"
                 : "=r"(r[0]), "=r"(r[1]), "=r"(r[2]), "=r"(r[3]) : "r"(addr));
}
__device__ __forceinline__ void ldsm4t(uint32_t* r, uint32_t addr) {
    asm volatile("ldmatrix.sync.aligned.m8n8.x4.trans.shared.b16 {%0,%1,%2,%3}, [%4];"
                 : "=r"(r[0]), "=r"(r[1]), "=r"(r[2]), "=r"(r[3]) : "r"(addr));
}
__device__ __forceinline__ void mma16816(float* d, const uint32_t* a,
                                         uint32_t b0, uint32_t b1) {
    asm volatile("mma.sync.aligned.m16n8k16.row.col.f32.bf16.bf16.f32 "
        "{%0,%1,%2,%3}, {%4,%5,%6,%7}, {%8,%9}, {%0,%1,%2,%3};"
        : "+f"(d[0]), "+f"(d[1]), "+f"(d[2]), "+f"(d[3])
        : "r"(a[0]), "r"(a[1]), "r"(a[2]), "r"(a[3]), "r"(b0), "r"(b1));
}
__device__ __forceinline__ void split2(float x, float y, uint32_t& h, uint32_t& l) {
    __nv_bfloat162 hh, ll;
    hh.x = __float2bfloat16(x); ll.x = __float2bfloat16(x - __bfloat162float(hh.x));
    hh.y = __float2bfloat16(y); ll.y = __float2bfloat16(y - __bfloat162float(hh.y));
    h = *(uint32_t*)&hh; l = *(uint32_t*)&ll;
}

// ================= split kernels (batched) =================
__global__ void split_x(const float* __restrict__ q, const float* __restrict__ k,
                        const float* __restrict__ v)
{
    int slot = blockIdx.y;
    const float* src = (slot == 0) ? q : (slot == 1) ? k : v;
    int i = blockIdx.x * blockDim.x + threadIdx.x;          // < 2097152
    __nv_bfloat16* hi = g_Xhi + (size_t)slot * 8388608u;
    __nv_bfloat16* lo = g_Xlo + (size_t)slot * 8388608u;
    float4 f = ((const float4*)src)[i];
    uint32_t h01, l01, h23, l23;
    split2(f.x, f.y, h01, l01);
    split2(f.z, f.w, h23, l23);
    ((uint32_t*)hi)[i*2] = h01; ((uint32_t*)hi)[i*2+1] = h23;
    ((uint32_t*)lo)[i*2] = l01; ((uint32_t*)lo)[i*2+1] = l23;
}
__global__ void split_w(const float* __restrict__ wq, const float* __restrict__ wk,
                        const float* __restrict__ wv, const float* __restrict__ wo)
{
    int slot = blockIdx.y;
    const float* src = (slot == 0) ? wq : (slot == 1) ? wk : (slot == 2) ? wv : wo;
    int i = blockIdx.x * blockDim.x + threadIdx.x;          // < 262144
    __nv_bfloat16* hi = g_Whi_ + (size_t)slot * 1048576u;
    __nv_bfloat16* lo = g_Wlo_ + (size_t)slot * 1048576u;
    float4 f = ((const float4*)src)[i];
    uint32_t h01, l01, h23, l23;
    split2(f.x, f.y, h01, l01);
    split2(f.z, f.w, h23, l23);
    ((uint32_t*)hi)[i*2] = h01; ((uint32_t*)hi)[i*2+1] = h23;
    ((uint32_t*)lo)[i*2] = l01; ((uint32_t*)lo)[i*2+1] = l23;
}

// ===== HMMA GEMM: XOR-swizzled smem, 3-stage cp.async, 1 sync/kt =========
// Tile layout: 128 rows x 64B (32 bf16), 16B chunk c at row r stored at
// chunk c ^ ((r>>1)&3). Conflict-free ldmatrix (8-row groups: r&1 picks
// word-offset 0/16, (r>>1)&3 injective per parity -> 8 disjoint bank spans).
#define TSZ      8192
#define T_AHI    0
#define T_ALO    8192
#define T_WHI    16384
#define T_WLO    24576
#define STAGE_SZ 32768
#define GEMM_SMEM (3*STAGE_SZ)   // 98304 B -> 2 CTAs/SM

__global__ __launch_bounds__(256, 2) void mma_gemm(float* __restrict__ Cout, int mode_arg)
{
    extern __shared__ __align__(128) char sm[];
    uint32_t sb = s2u(sm);

    int mode = (mode_arg < 0) ? (int)blockIdx.z : mode_arg;

    int tid  = threadIdx.x;
    int wid  = tid >> 5, lane = tid & 31;
    int bm   = blockIdx.y * 128, bn = blockIdx.x * 128;
    int wm   = (wid & 1) * 64;
    int wn   = (wid >> 1) * 32;

    const __nv_bfloat16* Ah = (mode < 3) ? (g_Xhi + (size_t)mode * 8388608u) : g_Chi;
    const __nv_bfloat16* Al = (mode < 3) ? (g_Xlo + (size_t)mode * 8388608u) : g_Clo;
    const __nv_bfloat16* Wh = g_Whi_ + (size_t)mode * 1048576u;
    const __nv_bfloat16* Wl = g_Wlo_ + (size_t)mode * 1048576u;

    // copy mapping: thread does chunks tid and tid+256 (128 rows x 4 chunks)
    int r0 = tid >> 2, q0 = tid & 3;
    const __nv_bfloat16* gAh0 = Ah + (size_t)(bm + r0) * 1024 + q0 * 8;
    const __nv_bfloat16* gAh1 = gAh0 + (size_t)64 * 1024;
    const __nv_bfloat16* gAl0 = Al + (size_t)(bm + r0) * 1024 + q0 * 8;
    const __nv_bfloat16* gAl1 = gAl0 + (size_t)64 * 1024;
    const __nv_bfloat16* gWh0 = Wh + (size_t)(bn + r0) * 1024 + q0 * 8;
    const __nv_bfloat16* gWh1 = gWh0 + (size_t)64 * 1024;
    const __nv_bfloat16* gWl0 = Wl + (size_t)(bn + r0) * 1024 + q0 * 8;
    const __nv_bfloat16* gWl1 = gWl0 + (size_t)64 * 1024;
    uint32_t sd0 = (uint32_t)(r0 * 64 + ((q0 ^ ((r0 >> 1) & 3)) << 4));
    uint32_t sd1 = sd0 + 4096;       // row+64: (r>>1)&3 unchanged mod 4

    // ldsm swizzled per-thread offsets (per kk)
    int fA = ((lane & 15) >> 1) & 3;
    uint32_t aRow = (uint32_t)((wm + (lane & 15)) * 64);
    uint32_t offA_k[2] = { aRow + (uint32_t)((((lane >> 4) + 0) ^ fA) << 4),
                           aRow + (uint32_t)((((lane >> 4) + 2) ^ fA) << 4) };
    int rB = wn + ((lane >> 4) & 1) * 8 + (lane & 7);
    int fB = ((lane & 7) >> 1) & 3;
    uint32_t offB_k[2] = { (uint32_t)(rB * 64 + (((((lane >> 3) & 1) + 0) ^ fB) << 4)),
                           (uint32_t)(rB * 64 + (((((lane >> 3) & 1) + 2) ^ fB) << 4)) };

    float acc[4][4][4];
#pragma unroll
    for (int i = 0; i < 4; i++)
#pragma unroll
        for (int j = 0; j < 4; j++)
#pragma unroll
            for (int t = 0; t < 4; t++) acc[i][j][t] = 0.0f;

    auto issue_stage = [&](int kt, int s) {
        uint32_t st = sb + (uint32_t)s * STAGE_SZ;
        size_t ko = (size_t)kt * 32;
        CP_ASYNC16(st + T_AHI + sd0, gAh0 + ko); CP_ASYNC16(st + T_AHI + sd1, gAh1 + ko);
        CP_ASYNC16(st + T_ALO + sd0, gAl0 + ko); CP_ASYNC16(st + T_ALO + sd1, gAl1 + ko);
        CP_ASYNC16(st + T_WHI + sd0, gWh0 + ko); CP_ASYNC16(st + T_WHI + sd1, gWh1 + ko);
        CP_ASYNC16(st + T_WLO + sd0, gWl0 + ko); CP_ASYNC16(st + T_WLO + sd1, gWl1 + ko);
    };

    // prologue: stages 0,1 in flight (groups G0,G1)
    issue_stage(0, 0); CP_COMMIT();
    issue_stage(1, 1); CP_COMMIT();

    int s_cons = 0, s_next = 2;
    for (int kt = 0; kt < 32; kt++) {
        CP_WAIT(1);                      // group kt complete (1 newer pending)
        __syncthreads();                 // all warps past kt-1 consume
        if (kt + 2 < 32) issue_stage(kt + 2, s_next);   // stage freed at kt-1
        CP_COMMIT();                     // exactly one group per iteration

        uint32_t stg = sb + (uint32_t)s_cons * STAGE_SZ;
#pragma unroll
        for (int kk = 0; kk < 2; kk++) {
            uint32_t oA = offA_k[kk], oB = offB_k[kk];
            uint32_t ah[4][4], al[4][4], bhf[2][4], blf[2][4];
#pragma unroll
            for (int mf = 0; mf < 4; mf++) {
                ldsm4(ah[mf], stg + T_AHI + oA + mf * 1024);
                ldsm4(al[mf], stg + T_ALO + oA + mf * 1024);
            }
#pragma unroll
            for (int nf2 = 0; nf2 < 2; nf2++) {
                ldsm4(bhf[nf2], stg + T_WHI + oB + nf2 * 1024);
                ldsm4(blf[nf2], stg + T_WLO + oB + nf2 * 1024);
            }
#pragma unroll
            for (int mf = 0; mf < 4; mf++)
#pragma unroll
                for (int nf = 0; nf < 4; nf++) {
                    int n2 = nf >> 1, hi = (nf & 1) * 2;
                    mma16816(acc[mf][nf], ah[mf], bhf[n2][hi], bhf[n2][hi + 1]);
                    mma16816(acc[mf][nf], ah[mf], blf[n2][hi], blf[n2][hi + 1]);
                    mma16816(acc[mf][nf], al[mf], bhf[n2][hi], bhf[n2][hi + 1]);
                }
        }
        s_cons = (s_cons == 2) ? 0 : s_cons + 1;
        s_next = (s_next == 2) ? 0 : s_next + 1;
    }

    int lr = lane >> 2, lc = (lane & 3) * 2;
#pragma unroll
    for (int mf = 0; mf < 4; mf++)
#pragma unroll
        for (int nf = 0; nf < 4; nf++) {
            int r = bm + wm + mf * 16 + lr;
            int c = bn + wn + nf * 8 + lc;
            float2 v0 = make_float2(acc[mf][nf][0], acc[mf][nf][1]);
            float2 v1 = make_float2(acc[mf][nf][2], acc[mf][nf][3]);
            if (mode == 3) {
                *(float2*)(Cout + (size_t)r * 1024 + c)       = v0;
                *(float2*)(Cout + (size_t)(r + 8) * 1024 + c) = v1;
            } else {
                int h = c >> 6, dk = c & 63;
                int b0i = r >> 10, s0 = r & 1023;
                int b1i = (r + 8) >> 10, s1 = (r + 8) & 1023;
                size_t o0 = (((size_t)(b0i*HH + h) * SS + s0) << 6) + dk;
                size_t o1 = (((size_t)(b1i*HH + h) * SS + s1) << 6) + dk;
                __nv_bfloat16* ghi = (mode == 0) ? g_Qhi : (mode == 1) ? g_Khi : g_Vhi;
                __nv_bfloat16* glo = (mode == 0) ? g_Qlo : (mode == 1) ? g_Klo : g_Vlo;
                uint32_t h0, l0, h1, l1;
                split2(v0.x, v0.y, h0, l0);
                split2(v1.x, v1.y, h1, l1);
                *(uint32_t*)(ghi + o0) = h0; *(uint32_t*)(glo + o0) = l0;
                *(uint32_t*)(ghi + o1) = h1; *(uint32_t*)(glo + o1) = l1;
            }
        }
}

// ===== fused scores + softmax + attn write + P@V context (FA-style) =====
#define KP    144           // bf16 tile pitch bytes (64 bf16 + 16 pad)
#define S_QH  0
#define S_QL  9216
#define S_K   18432         // stage st at +st*STG: Khi 0, Klo 9216, Vhi 18432, Vlo 27648
#define STG   36864
#define S_LB  92160         // float lbuf[2][64]
#define S_IR  92672         // float irow[64]
#define FUSED_SMEM 92928    // -> 2 CTAs/SM
#define S_RED S_K           // ctx reduce buffers reuse stage area (2 x 64x68 fp32)

__global__ __launch_bounds__(256, 2) void attn_fused(float* __restrict__ attn)
{
    extern __shared__ __align__(128) char smraw[];
    uint32_t sb = s2u(smraw);
    float* lbuf = (float*)(smraw + S_LB);
    float* irow = (float*)(smraw + S_IR);

    int tid  = threadIdx.x;
    int wid  = tid >> 5, lane = tid & 31;
    int bh   = blockIdx.y;
    int rt   = blockIdx.x;               // 0..15, row0 = rt*64, tiles 0..rt
    int row0 = rt * 64;
    int wm   = (wid & 3) * 16;           // warp row band
    int wnw  = (wid >> 2) * 16;          // warp col base (su adds +32)

    const __nv_bfloat16* Qh = g_Qhi + ((size_t)bh * SS + row0) * DKK;
    const __nv_bfloat16* Ql = g_Qlo + ((size_t)bh * SS + row0) * DKK;
    const __nv_bfloat16* Kh = g_Khi + (size_t)bh * SS * DKK;
    const __nv_bfloat16* Kl = g_Klo + (size_t)bh * SS * DKK;
    const __nv_bfloat16* Vh = g_Vhi + (size_t)bh * SS * DKK;
    const __nv_bfloat16* Vl = g_Vlo + (size_t)bh * SS * DKK;

    // load Q 64x64 hi/lo
#pragma unroll
    for (int i = 0; i < 2; i++) {
        int c = i * 256 + tid;
        int r = c >> 3, q = c & 7;
        uint32_t d = (uint32_t)(r * KP + q * 16);
        *(uint4*)(smraw + S_QH + d) = *(const uint4*)(Qh + (size_t)r * 64 + q * 8);
        *(uint4*)(smraw + S_QL + d) = *(const uint4*)(Ql + (size_t)r * 64 + q * 8);
    }

    // zero upper-triangle tiles
    float4* atile = (float4*)attn + ((size_t)bh * SS + row0) * 256;
    float4 z4 = make_float4(0.f, 0.f, 0.f, 0.f);
    for (int nt = rt + 1; nt < 16; nt++)
#pragma unroll
        for (int i = 0; i < 4; i++) {
            int idx = i * 256 + tid;
            atile[(size_t)(idx >> 4) * 256 + nt * 16 + (idx & 15)] = z4;
        }

    auto issue_K = [&](int nt, int st, bool withV) {
        uint32_t kb = sb + S_K + (uint32_t)st * STG;
#pragma unroll
        for (int i = 0; i < 2; i++) {
            int c = i * 256 + tid;
            int r = c >> 3, q = c & 7;
            uint32_t d = (uint32_t)(r * KP + q * 16);
            size_t go = (size_t)(nt * 64 + r) * 64 + q * 8;
            CP_ASYNC16(kb + d,        Kh + go);
            CP_ASYNC16(kb + 9216 + d, Kl + go);
            if (withV) {
                CP_ASYNC16(kb + 18432 + d, Vh + go);
                CP_ASYNC16(kb + 27648 + d, Vl + go);
            }
        }
    };

    uint32_t offA = (uint32_t)((wm + (lane & 15)) * KP + (lane >> 4) * 16);
    uint32_t offB = (uint32_t)((wnw + ((lane >> 4) & 1) * 8 + (lane & 7)) * KP
                               + ((lane >> 3) & 1) * 16);
    uint32_t offBT = (uint32_t)(((lane & 7) + ((lane >> 3) & 1) * 8) * KP
                                + ((lane >> 4) & 1) * 16);
    int lr = lane >> 2, lc = (lane & 3) * 2;
    int qr0 = row0 + wm + lr, qr1 = qr0 + 8;

    // ---------------- pass 1: row sums of exp(s-30) ----------------
    float lsum[2] = {0.0f, 0.0f};
    issue_K(0, 0, false); CP_COMMIT();
    for (int nt = 0; nt <= rt; nt++) {
        int st = nt & 1;
        CP_WAIT(0);
        __syncthreads();
        if (nt < rt) issue_K(nt + 1, st ^ 1, false);
        CP_COMMIT();

        uint32_t kb = sb + S_K + (uint32_t)st * STG;
        float acc[2][2][4];
#pragma unroll
        for (int su = 0; su < 2; su++)
#pragma unroll
            for (int nf = 0; nf < 2; nf++)
#pragma unroll
                for (int t = 0; t < 4; t++) acc[su][nf][t] = 0.0f;

#pragma unroll
        for (int kk = 0; kk < 4; kk++) {
            uint32_t k2 = (uint32_t)(kk * 32);
            uint32_t ah[4], al[4];
            ldsm4(ah, sb + S_QH + offA + k2);
            ldsm4(al, sb + S_QL + offA + k2);
#pragma unroll
            for (int su = 0; su < 2; su++) {
                uint32_t bo = offB + (uint32_t)(su * 32 * KP) + k2;
                uint32_t bhf[4], blf[4];
                ldsm4(bhf, kb + bo);
                ldsm4(blf, kb + 9216 + bo);
#pragma unroll
                for (int nf = 0; nf < 2; nf++) {
                    int hi = nf * 2;
                    mma16816(acc[su][nf], ah, bhf[hi], bhf[hi + 1]);
                    mma16816(acc[su][nf], ah, blf[hi], blf[hi + 1]);
                    mma16816(acc[su][nf], al, bhf[hi], bhf[hi + 1]);
                }
            }
        }
#pragma unroll
        for (int su = 0; su < 2; su++)
#pragma unroll
            for (int nf = 0; nf < 2; nf++) {
                int c = nt * 64 + wnw + su * 32 + nf * 8 + lc;
                float v0 = fminf(fmaxf(acc[su][nf][0] * INV_SCALE, -30.f), 30.f);
                float v1 = fminf(fmaxf(acc[su][nf][1] * INV_SCALE, -30.f), 30.f);
                float v2 = fminf(fmaxf(acc[su][nf][2] * INV_SCALE, -30.f), 30.f);
                float v3 = fminf(fmaxf(acc[su][nf][3] * INV_SCALE, -30.f), 30.f);
                lsum[0] += ((c     <= qr0) ? __expf(v0 - 30.f) : 0.0f)
                         + ((c + 1 <= qr0) ? __expf(v1 - 30.f) : 0.0f);
                lsum[1] += ((c     <= qr1) ? __expf(v2 - 30.f) : 0.0f)
                         + ((c + 1 <= qr1) ? __expf(v3 - 30.f) : 0.0f);
            }
    }

#pragma unroll
    for (int half = 0; half < 2; half++) {
        lsum[half] += __shfl_xor_sync(0xffffffffu, lsum[half], 1);
        lsum[half] += __shfl_xor_sync(0xffffffffu, lsum[half], 2);
    }
    if ((lane & 3) == 0) {
        lbuf[(wid >> 2) * 64 + wm + lr]     = lsum[0];
        lbuf[(wid >> 2) * 64 + wm + lr + 8] = lsum[1];
    }
    __syncthreads();
    if (tid < 64) irow[tid] = 1.0f / (lbuf[tid] + lbuf[64 + tid]);
    __syncthreads();

    float inv0 = irow[wm + lr], inv1 = irow[wm + lr + 8];
    float* arow_t = attn + ((size_t)bh * SS + qr0) * SS;
    float* arow_b = attn + ((size_t)bh * SS + qr1) * SS;

    // ---------- pass 2: recompute S, write attn, P@V accumulate ----------
    float ctx[8][4];
#pragma unroll
    for (int nf2 = 0; nf2 < 8; nf2++)
#pragma unroll
        for (int t = 0; t < 4; t++) ctx[nf2][t] = 0.0f;

    issue_K(0, 0, true); CP_COMMIT();
    for (int nt = 0; nt <= rt; nt++) {
        int st = nt & 1;
        CP_WAIT(0);
        __syncthreads();
        if (nt < rt) issue_K(nt + 1, st ^ 1, true);
        CP_COMMIT();

        uint32_t kb = sb + S_K + (uint32_t)st * STG;
        float acc[2][2][4];
#pragma unroll
        for (int su = 0; su < 2; su++)
#pragma unroll
            for (int nf = 0; nf < 2; nf++)
#pragma unroll
                for (int t = 0; t < 4; t++) acc[su][nf][t] = 0.0f;

#pragma unroll
        for (int kk = 0; kk < 4; kk++) {
            uint32_t k2 = (uint32_t)(kk * 32);
            uint32_t ah[4], al[4];
            ldsm4(ah, sb + S_QH + offA + k2);
            ldsm4(al, sb + S_QL + offA + k2);
#pragma unroll
            for (int su = 0; su < 2; su++) {
                uint32_t bo = offB + (uint32_t)(su * 32 * KP) + k2;
                uint32_t bhf[4], blf[4];
                ldsm4(bhf, kb + bo);
                ldsm4(blf, kb + 9216 + bo);
#pragma unroll
                for (int nf = 0; nf < 2; nf++) {
                    int hi = nf * 2;
                    mma16816(acc[su][nf], ah, bhf[hi], bhf[hi + 1]);
                    mma16816(acc[su][nf], ah, blf[hi], blf[hi + 1]);
                    mma16816(acc[su][nf], al, bhf[hi], bhf[hi + 1]);
                }
            }
        }

#pragma unroll
        for (int su = 0; su < 2; su++) {
            float pn[2][4];
#pragma unroll
            for (int nf = 0; nf < 2; nf++) {
                int c = nt * 64 + wnw + su * 32 + nf * 8 + lc;
                float v0 = fminf(fmaxf(acc[su][nf][0] * INV_SCALE, -30.f), 30.f);
                float v1 = fminf(fmaxf(acc[su][nf][1] * INV_SCALE, -30.f), 30.f);
                float v2 = fminf(fmaxf(acc[su][nf][2] * INV_SCALE, -30.f), 30.f);
                float v3 = fminf(fmaxf(acc[su][nf][3] * INV_SCALE, -30.f), 30.f);
                pn[nf][0] = (c     <= qr0) ? __expf(v0 - 30.f) * inv0 : 0.0f;
                pn[nf][1] = (c + 1 <= qr0) ? __expf(v1 - 30.f) * inv0 : 0.0f;
                pn[nf][2] = (c     <= qr1) ? __expf(v2 - 30.f) * inv1 : 0.0f;
                pn[nf][3] = (c + 1 <= qr1) ? __expf(v3 - 30.f) * inv1 : 0.0f;
                *(float2*)(arow_t + c) = make_float2(pn[nf][0], pn[nf][1]);
                *(float2*)(arow_b + c) = make_float2(pn[nf][2], pn[nf][3]);
            }
            uint32_t pah[4], pal[4];
            split2(pn[0][0], pn[0][1], pah[0], pal[0]);
            split2(pn[0][2], pn[0][3], pah[1], pal[1]);
            split2(pn[1][0], pn[1][1], pah[2], pal[2]);
            split2(pn[1][2], pn[1][3], pah[3], pal[3]);
            int kc = su * 2 + (wnw >> 4);     // k16 chunk within 64-key tile
#pragma unroll
            for (int g = 0; g < 4; g++) {     // dk 16-col groups
                uint32_t ba = offBT + (uint32_t)(kc * 16 * KP + g * 32);
                uint32_t vh[4], vl[4];
                ldsm4t(vh, kb + 18432 + ba);
                ldsm4t(vl, kb + 27648 + ba);
#pragma unroll
                for (int s2 = 0; s2 < 2; s2++) {
                    int nf2 = g * 2 + s2;
                    mma16816(ctx[nf2], pah, vh[s2*2], vh[s2*2 + 1]);
                    mma16816(ctx[nf2], pah, vl[s2*2], vl[s2*2 + 1]);
                    mma16816(ctx[nf2], pal, vh[s2*2], vh[s2*2 + 1]);
                }
            }
        }
    }

    // ---------------- ctx cross-warp reduction + epilogue ----------------
    __syncthreads();
    float* sred = (float*)(smraw + S_RED) + (wid >> 2) * (64 * 68);
#pragma unroll
    for (int nf2 = 0; nf2 < 8; nf2++) {
        *(float2*)&sred[(wm + lr) * 68 + nf2 * 8 + lc]     = make_float2(ctx[nf2][0], ctx[nf2][1]);
        *(float2*)&sred[(wm + lr + 8) * 68 + nf2 * 8 + lc] = make_float2(ctx[nf2][2], ctx[nf2][3]);
    }
    __syncthreads();

    {
        float* s0 = (float*)(smraw + S_RED);
        float* s1 = s0 + 64 * 68;
        int row = tid >> 2;
        int cq  = (tid & 3) * 16;
        int b = bh >> 4, h = bh & 15;
        size_t obase = ((size_t)b * SS + row0 + row) * DD + h * DKK;
#pragma unroll
        for (int j = 0; j < 4; j++) {
            int col = cq + j * 4;
            int si = row * 68 + col;
            float f0 = s0[si]     + s1[si];
            float f1 = s0[si + 1] + s1[si + 1];
            float f2 = s0[si + 2] + s1[si + 2];
            float f3 = s0[si + 3] + s1[si + 3];
            uint32_t h01, l01, h23, l23;
            split2(f0, f1, h01, l01);
            split2(f2, f3, h23, l23);
            *(uint2*)(g_Chi + obase + col) = make_uint2(h01, h23);
            *(uint2*)(g_Clo + obase + col) = make_uint2(l01, l23);
        }
    }
}

// ============================================================
extern "C" void kernel_launch(void* const* d_in, const int* in_sizes, int n_in,
                              void* d_out, int out_size)
{
    (void)in_sizes; (void)n_in;
    const float* q  = (const float*)d_in[0];
    const float* k  = (const float*)d_in[1];
    const float* v  = (const float*)d_in[2];
    const float* Wq = (const float*)d_in[4];
    const float* Wk = (const float*)d_in[5];
    const float* Wv = (const float*)d_in[6];
    const float* Wo = (const float*)d_in[7];
    float* out = (float*)d_out;

    const size_t OUTE  = (size_t)BB * SS * DD;        // 8,388,608
    const size_t ATTNE = (size_t)BB * HH * SS * SS;   // 134,217,728

    float* attn_ptr;
    bool write_out = true;
    size_t osz = (size_t)out_size;
    if (osz >= OUTE + ATTNE) {
        attn_ptr = out + OUTE;
    } else if (osz == ATTNE) {
        attn_ptr = out;
        write_out = false;
    } else {
        void* p = nullptr;
        cudaGetSymbolAddress(&p, g_attn);
        attn_ptr = (float*)p;
    }

    // 1. bf16 splits (2 launches)
    split_x<<<dim3(2097152/256, 3), 256>>>(q, k, v);
    split_w<<<dim3(262144/256, 4), 256>>>(Wq, Wk, Wv, Wo);

    // 2. q/k/v projections merged into one launch (mode = blockIdx.z)
    cudaFuncSetAttribute(mma_gemm, cudaFuncAttributeMaxDynamicSharedMemorySize, GEMM_SMEM);
    mma_gemm<<<dim3(8, 64, 3), 256, GEMM_SMEM>>>(nullptr, -1);

    // 3. fused scores + softmax + attn write + P@V context
    cudaFuncSetAttribute(attn_fused, cudaFuncAttributeMaxDynamicSharedMemorySize, FUSED_SMEM);
    attn_fused<<<dim3(16, 128), 256, FUSED_SMEM>>>(attn_ptr);

    // 4. output projection
    if (write_out)
        mma_gemm<<<dim3(8, 64, 1), 256, GEMM_SMEM>>>(out, 3);
}

// round 16
// speedup vs baseline: 3.4859x; 1.0238x over previous
#include <cuda_runtime.h>
#include <cuda_bf16.h>
#include <cstdint>
#include <cstddef>

// Problem constants
#define BB   8
#define SS   1024
#define DD   1024
#define HH   16
#define DKK  64
#define INV_SCALE (1.0f/16.0f)   // SCALE = sqrt(64)*2 = 16

// ---------------- scratch (no cudaMalloc allowed) ----------------
__device__ __nv_bfloat16 g_Xhi[3u*8388608u];   // input splits q,k,v
__device__ __nv_bfloat16 g_Xlo[3u*8388608u];
__device__ __nv_bfloat16 g_Whi_[4u*1048576u];  // weight splits Wq,Wk,Wv,Wo
__device__ __nv_bfloat16 g_Wlo_[4u*1048576u];
__device__ __nv_bfloat16 g_Qhi[BB*HH*SS*DKK];  // [B,H,S,dk] bf16 splits
__device__ __nv_bfloat16 g_Qlo[BB*HH*SS*DKK];
__device__ __nv_bfloat16 g_Khi[BB*HH*SS*DKK];
__device__ __nv_bfloat16 g_Klo[BB*HH*SS*DKK];
__device__ __nv_bfloat16 g_Vhi[BB*HH*SS*DKK];
__device__ __nv_bfloat16 g_Vlo[BB*HH*SS*DKK];
__device__ __nv_bfloat16 g_Chi[BB*SS*DD];      // ctx splits [B,S,D]
__device__ __nv_bfloat16 g_Clo[BB*SS*DD];
__device__ float g_attn[(size_t)BB*HH*SS*SS];  // fallback

__device__ __forceinline__ uint32_t s2u(const void* p) {
    return (uint32_t)__cvta_generic_to_shared(p);
}
#define CP_ASYNC16(dst, src) \
    asm volatile("cp.async.cg.shared.global [%0], [%1], 16;" :: "r"(dst), "l"(src))
#define CP_COMMIT() asm volatile("cp.async.commit_group;" ::: "memory")
#define CP_WAIT(n)  asm volatile("cp.async.wait_group %0;" :: "n"(n) : "memory")

__device__ __forceinline__ void ldsm4(uint32_t* r, uint32_t addr) {
    asm volatile("ldmatrix.sync.aligned.m8n8.x4.shared.b16 {%0,%1,%2,%3}, [%4];"
                 : "=r"(r[0]), "=r"(r[1]), "=r"(r[2]), "=r"(r[3]) : "r"(addr));
}
__device__ __forceinline__ void ldsm4t(uint32_t* r, uint32_t addr) {
    asm volatile("ldmatrix.sync.aligned.m8n8.x4.trans.shared.b16 {%0,%1,%2,%3}, [%4];"
                 : "=r"(r[0]), "=r"(r[1]), "=r"(r[2]), "=r"(r[3]) : "r"(addr));
}
__device__ __forceinline__ void mma16816(float* d, const uint32_t* a,
                                         uint32_t b0, uint32_t b1) {
    asm volatile("mma.sync.aligned.m16n8k16.row.col.f32.bf16.bf16.f32 "
        "{%0,%1,%2,%3}, {%4,%5,%6,%7}, {%8,%9}, {%0,%1,%2,%3};"
        : "+f"(d[0]), "+f"(d[1]), "+f"(d[2]), "+f"(d[3])
        : "r"(a[0]), "r"(a[1]), "r"(a[2]), "r"(a[3]), "r"(b0), "r"(b1));
}
__device__ __forceinline__ void split2(float x, float y, uint32_t& h, uint32_t& l) {
    __nv_bfloat162 hh, ll;
    hh.x = __float2bfloat16(x); ll.x = __float2bfloat16(x - __bfloat162float(hh.x));
    hh.y = __float2bfloat16(y); ll.y = __float2bfloat16(y - __bfloat162float(hh.y));
    h = *(uint32_t*)&hh; l = *(uint32_t*)&ll;
}

// ================= split kernels (batched) =================
__global__ void split_x(const float* __restrict__ q, const float* __restrict__ k,
                        const float* __restrict__ v)
{
    int slot = blockIdx.y;
    const float* src = (slot == 0) ? q : (slot == 1) ? k : v;
    int i = blockIdx.x * blockDim.x + threadIdx.x;          // < 2097152
    __nv_bfloat16* hi = g_Xhi + (size_t)slot * 8388608u;
    __nv_bfloat16* lo = g_Xlo + (size_t)slot * 8388608u;
    float4 f = ((const float4*)src)[i];
    uint32_t h01, l01, h23, l23;
    split2(f.x, f.y, h01, l01);
    split2(f.z, f.w, h23, l23);
    ((uint32_t*)hi)[i*2] = h01; ((uint32_t*)hi)[i*2+1] = h23;
    ((uint32_t*)lo)[i*2] = l01; ((uint32_t*)lo)[i*2+1] = l23;
}
__global__ void split_w(const float* __restrict__ wq, const float* __restrict__ wk,
                        const float* __restrict__ wv, const float* __restrict__ wo)
{
    int slot = blockIdx.y;
    const float* src = (slot == 0) ? wq : (slot == 1) ? wk : (slot == 2) ? wv : wo;
    int i = blockIdx.x * blockDim.x + threadIdx.x;          // < 262144
    __nv_bfloat16* hi = g_Whi_ + (size_t)slot * 1048576u;
    __nv_bfloat16* lo = g_Wlo_ + (size_t)slot * 1048576u;
    float4 f = ((const float4*)src)[i];
    uint32_t h01, l01, h23, l23;
    split2(f.x, f.y, h01, l01);
    split2(f.z, f.w, h23, l23);
    ((uint32_t*)hi)[i*2] = h01; ((uint32_t*)hi)[i*2+1] = h23;
    ((uint32_t*)lo)[i*2] = l01; ((uint32_t*)lo)[i*2+1] = l23;
}

// ===== HMMA GEMM: XOR-swizzled smem, 3-stage cp.async, 1 sync/kt =========
#define TSZ      8192
#define T_AHI    0
#define T_ALO    8192
#define T_WHI    16384
#define T_WLO    24576
#define STAGE_SZ 32768
#define GEMM_SMEM (3*STAGE_SZ)   // 98304 B -> 2 CTAs/SM

__global__ __launch_bounds__(256, 2) void mma_gemm(float* __restrict__ Cout, int mode_arg)
{
    extern __shared__ __align__(128) char sm[];
    uint32_t sb = s2u(sm);

    int mode = (mode_arg < 0) ? (int)blockIdx.z : mode_arg;

    int tid  = threadIdx.x;
    int wid  = tid >> 5, lane = tid & 31;
    int bm   = blockIdx.y * 128, bn = blockIdx.x * 128;
    int wm   = (wid & 1) * 64;
    int wn   = (wid >> 1) * 32;

    const __nv_bfloat16* Ah = (mode < 3) ? (g_Xhi + (size_t)mode * 8388608u) : g_Chi;
    const __nv_bfloat16* Al = (mode < 3) ? (g_Xlo + (size_t)mode * 8388608u) : g_Clo;
    const __nv_bfloat16* Wh = g_Whi_ + (size_t)mode * 1048576u;
    const __nv_bfloat16* Wl = g_Wlo_ + (size_t)mode * 1048576u;

    int r0 = tid >> 2, q0 = tid & 3;
    const __nv_bfloat16* gAh0 = Ah + (size_t)(bm + r0) * 1024 + q0 * 8;
    const __nv_bfloat16* gAh1 = gAh0 + (size_t)64 * 1024;
    const __nv_bfloat16* gAl0 = Al + (size_t)(bm + r0) * 1024 + q0 * 8;
    const __nv_bfloat16* gAl1 = gAl0 + (size_t)64 * 1024;
    const __nv_bfloat16* gWh0 = Wh + (size_t)(bn + r0) * 1024 + q0 * 8;
    const __nv_bfloat16* gWh1 = gWh0 + (size_t)64 * 1024;
    const __nv_bfloat16* gWl0 = Wl + (size_t)(bn + r0) * 1024 + q0 * 8;
    const __nv_bfloat16* gWl1 = gWl0 + (size_t)64 * 1024;
    uint32_t sd0 = (uint32_t)(r0 * 64 + ((q0 ^ ((r0 >> 1) & 3)) << 4));
    uint32_t sd1 = sd0 + 4096;

    int fA = ((lane & 15) >> 1) & 3;
    uint32_t aRow = (uint32_t)((wm + (lane & 15)) * 64);
    uint32_t offA_k[2] = { aRow + (uint32_t)((((lane >> 4) + 0) ^ fA) << 4),
                           aRow + (uint32_t)((((lane >> 4) + 2) ^ fA) << 4) };
    int rB = wn + ((lane >> 4) & 1) * 8 + (lane & 7);
    int fB = ((lane & 7) >> 1) & 3;
    uint32_t offB_k[2] = { (uint32_t)(rB * 64 + (((((lane >> 3) & 1) + 0) ^ fB) << 4)),
                           (uint32_t)(rB * 64 + (((((lane >> 3) & 1) + 2) ^ fB) << 4)) };

    float acc[4][4][4];
#pragma unroll
    for (int i = 0; i < 4; i++)
#pragma unroll
        for (int j = 0; j < 4; j++)
#pragma unroll
            for (int t = 0; t < 4; t++) acc[i][j][t] = 0.0f;

    auto issue_stage = [&](int kt, int s) {
        uint32_t st = sb + (uint32_t)s * STAGE_SZ;
        size_t ko = (size_t)kt * 32;
        CP_ASYNC16(st + T_AHI + sd0, gAh0 + ko); CP_ASYNC16(st + T_AHI + sd1, gAh1 + ko);
        CP_ASYNC16(st + T_ALO + sd0, gAl0 + ko); CP_ASYNC16(st + T_ALO + sd1, gAl1 + ko);
        CP_ASYNC16(st + T_WHI + sd0, gWh0 + ko); CP_ASYNC16(st + T_WHI + sd1, gWh1 + ko);
        CP_ASYNC16(st + T_WLO + sd0, gWl0 + ko); CP_ASYNC16(st + T_WLO + sd1, gWl1 + ko);
    };

    issue_stage(0, 0); CP_COMMIT();
    issue_stage(1, 1); CP_COMMIT();

    int s_cons = 0, s_next = 2;
    for (int kt = 0; kt < 32; kt++) {
        CP_WAIT(1);
        __syncthreads();
        if (kt + 2 < 32) issue_stage(kt + 2, s_next);
        CP_COMMIT();

        uint32_t stg = sb + (uint32_t)s_cons * STAGE_SZ;
#pragma unroll
        for (int kk = 0; kk < 2; kk++) {
            uint32_t oA = offA_k[kk], oB = offB_k[kk];
            uint32_t ah[4][4], al[4][4], bhf[2][4], blf[2][4];
#pragma unroll
            for (int mf = 0; mf < 4; mf++) {
                ldsm4(ah[mf], stg + T_AHI + oA + mf * 1024);
                ldsm4(al[mf], stg + T_ALO + oA + mf * 1024);
            }
#pragma unroll
            for (int nf2 = 0; nf2 < 2; nf2++) {
                ldsm4(bhf[nf2], stg + T_WHI + oB + nf2 * 1024);
                ldsm4(blf[nf2], stg + T_WLO + oB + nf2 * 1024);
            }
#pragma unroll
            for (int mf = 0; mf < 4; mf++)
#pragma unroll
                for (int nf = 0; nf < 4; nf++) {
                    int n2 = nf >> 1, hi = (nf & 1) * 2;
                    mma16816(acc[mf][nf], ah[mf], bhf[n2][hi], bhf[n2][hi + 1]);
                    mma16816(acc[mf][nf], ah[mf], blf[n2][hi], blf[n2][hi + 1]);
                    mma16816(acc[mf][nf], al[mf], bhf[n2][hi], bhf[n2][hi + 1]);
                }
        }
        s_cons = (s_cons == 2) ? 0 : s_cons + 1;
        s_next = (s_next == 2) ? 0 : s_next + 1;
    }

    int lr = lane >> 2, lc = (lane & 3) * 2;
#pragma unroll
    for (int mf = 0; mf < 4; mf++)
#pragma unroll
        for (int nf = 0; nf < 4; nf++) {
            int r = bm + wm + mf * 16 + lr;
            int c = bn + wn + nf * 8 + lc;
            float2 v0 = make_float2(acc[mf][nf][0], acc[mf][nf][1]);
            float2 v1 = make_float2(acc[mf][nf][2], acc[mf][nf][3]);
            if (mode == 3) {
                *(float2*)(Cout + (size_t)r * 1024 + c)       = v0;
                *(float2*)(Cout + (size_t)(r + 8) * 1024 + c) = v1;
            } else {
                int h = c >> 6, dk = c & 63;
                int b0i = r >> 10, s0 = r & 1023;
                int b1i = (r + 8) >> 10, s1 = (r + 8) & 1023;
                size_t o0 = (((size_t)(b0i*HH + h) * SS + s0) << 6) + dk;
                size_t o1 = (((size_t)(b1i*HH + h) * SS + s1) << 6) + dk;
                __nv_bfloat16* ghi = (mode == 0) ? g_Qhi : (mode == 1) ? g_Khi : g_Vhi;
                __nv_bfloat16* glo = (mode == 0) ? g_Qlo : (mode == 1) ? g_Klo : g_Vlo;
                uint32_t h0, l0, h1, l1;
                split2(v0.x, v0.y, h0, l0);
                split2(v1.x, v1.y, h1, l1);
                *(uint32_t*)(ghi + o0) = h0; *(uint32_t*)(glo + o0) = l0;
                *(uint32_t*)(ghi + o1) = h1; *(uint32_t*)(glo + o1) = l1;
            }
        }
}

// ===== fused scores + softmax + attn write + P@V (FA-style) ==============
// Now: 128B XOR-swizzled rows (chunk^(row&7)), 3-stage cp.async, WAIT(1),
// heavy-first CTA order (rt = 15 - blockIdx.x).
#define S_QH  0
#define S_QL  8192
#define S_K   16384         // stage st at +st*STG2: Khi 0, Klo 8192, Vhi 16384, Vlo 24576
#define STG2  32768
#define S_LB  114688        // float lbuf[2][64]
#define S_IR  115200        // float irow[64]
#define FUSED_SMEM 115456   // -> 2 CTAs/SM
#define S_RED S_K           // ctx reduce buffers reuse stage area (2 x 64x68 fp32)

__global__ __launch_bounds__(256, 2) void attn_fused(float* __restrict__ attn)
{
    extern __shared__ __align__(128) char smraw[];
    uint32_t sb = s2u(smraw);
    float* lbuf = (float*)(smraw + S_LB);
    float* irow = (float*)(smraw + S_IR);

    int tid  = threadIdx.x;
    int wid  = tid >> 5, lane = tid & 31;
    int bh   = blockIdx.y;
    int rt   = 15 - (int)blockIdx.x;     // heavy CTAs first
    int row0 = rt * 64;
    int wm   = (wid & 3) * 16;           // warp row band
    int wnw  = (wid >> 2) * 16;          // warp col base (su adds +32)

    const __nv_bfloat16* Qh = g_Qhi + ((size_t)bh * SS + row0) * DKK;
    const __nv_bfloat16* Ql = g_Qlo + ((size_t)bh * SS + row0) * DKK;
    const __nv_bfloat16* Kh = g_Khi + (size_t)bh * SS * DKK;
    const __nv_bfloat16* Kl = g_Klo + (size_t)bh * SS * DKK;
    const __nv_bfloat16* Vh = g_Vhi + (size_t)bh * SS * DKK;
    const __nv_bfloat16* Vl = g_Vlo + (size_t)bh * SS * DKK;

    // load Q 64x64 hi/lo, swizzled 128B rows
#pragma unroll
    for (int i = 0; i < 2; i++) {
        int c = i * 256 + tid;
        int r = c >> 3, q = c & 7;
        uint32_t d = (uint32_t)(r * 128 + ((q ^ (r & 7)) << 4));
        *(uint4*)(smraw + S_QH + d) = *(const uint4*)(Qh + (size_t)r * 64 + q * 8);
        *(uint4*)(smraw + S_QL + d) = *(const uint4*)(Ql + (size_t)r * 64 + q * 8);
    }

    // zero upper-triangle tiles
    float4* atile = (float4*)attn + ((size_t)bh * SS + row0) * 256;
    float4 z4 = make_float4(0.f, 0.f, 0.f, 0.f);
    for (int nt = rt + 1; nt < 16; nt++)
#pragma unroll
        for (int i = 0; i < 4; i++) {
            int idx = i * 256 + tid;
            atile[(size_t)(idx >> 4) * 256 + nt * 16 + (idx & 15)] = z4;
        }

    auto issue_K = [&](int nt, int st, bool withV) {
        uint32_t kb = sb + S_K + (uint32_t)st * STG2;
#pragma unroll
        for (int i = 0; i < 2; i++) {
            int c = i * 256 + tid;
            int r = c >> 3, q = c & 7;
            uint32_t d = (uint32_t)(r * 128 + ((q ^ (r & 7)) << 4));
            size_t go = (size_t)(nt * 64 + r) * 64 + q * 8;
            CP_ASYNC16(kb + d,         Kh + go);
            CP_ASYNC16(kb + 8192 + d,  Kl + go);
            if (withV) {
                CP_ASYNC16(kb + 16384 + d, Vh + go);
                CP_ASYNC16(kb + 24576 + d, Vl + go);
            }
        }
    };

    // swizzled ldsm per-lane offsets (all rows have row&7 == lane&7)
    int f  = lane & 7;
    int b3 = (lane >> 3) & 1;
    int b4 = (lane >> 4) & 1;
    uint32_t rowA = (uint32_t)((wm + (lane & 15)) * 128);
    uint32_t chA[4], chB[4], chBT[4];
#pragma unroll
    for (int kk = 0; kk < 4; kk++) {
        chA[kk] = (uint32_t)(((kk * 2 + (lane >> 4)) ^ f) << 4);
        chB[kk] = (uint32_t)(((kk * 2 + b3) ^ f) << 4);
        chBT[kk] = (uint32_t)(((kk * 2 + b4) ^ f) << 4);   // kk plays 'g' role
    }
    uint32_t rowB  = (uint32_t)((wnw + b4 * 8 + (lane & 7)) * 128);
    uint32_t rowBT = (uint32_t)(((lane & 7) + b3 * 8) * 128);
    int lr = lane >> 2, lc = (lane & 3) * 2;
    int qr0 = row0 + wm + lr, qr1 = qr0 + 8;

    // ---------------- pass 1: row sums of exp(s-30) ----------------
    float lsum[2] = {0.0f, 0.0f};
    issue_K(0, 0, false); CP_COMMIT();
    if (rt >= 1) issue_K(1, 1, false);
    CP_COMMIT();
    int sc = 0, sn = 2;
    for (int nt = 0; nt <= rt; nt++) {
        CP_WAIT(1);
        __syncthreads();
        if (nt + 2 <= rt) issue_K(nt + 2, sn, false);
        CP_COMMIT();

        uint32_t kb = sb + S_K + (uint32_t)sc * STG2;
        float acc[2][2][4];
#pragma unroll
        for (int su = 0; su < 2; su++)
#pragma unroll
            for (int nf = 0; nf < 2; nf++)
#pragma unroll
                for (int t = 0; t < 4; t++) acc[su][nf][t] = 0.0f;

#pragma unroll
        for (int kk = 0; kk < 4; kk++) {
            uint32_t ah[4], al[4];
            ldsm4(ah, sb + S_QH + rowA + chA[kk]);
            ldsm4(al, sb + S_QL + rowA + chA[kk]);
#pragma unroll
            for (int su = 0; su < 2; su++) {
                uint32_t bo = rowB + (uint32_t)(su * 4096) + chB[kk];
                uint32_t bhf[4], blf[4];
                ldsm4(bhf, kb + bo);
                ldsm4(blf, kb + 8192 + bo);
#pragma unroll
                for (int nf = 0; nf < 2; nf++) {
                    int hi = nf * 2;
                    mma16816(acc[su][nf], ah, bhf[hi], bhf[hi + 1]);
                    mma16816(acc[su][nf], ah, blf[hi], blf[hi + 1]);
                    mma16816(acc[su][nf], al, bhf[hi], bhf[hi + 1]);
                }
            }
        }
#pragma unroll
        for (int su = 0; su < 2; su++)
#pragma unroll
            for (int nf = 0; nf < 2; nf++) {
                int c = nt * 64 + wnw + su * 32 + nf * 8 + lc;
                float v0 = fminf(fmaxf(acc[su][nf][0] * INV_SCALE, -30.f), 30.f);
                float v1 = fminf(fmaxf(acc[su][nf][1] * INV_SCALE, -30.f), 30.f);
                float v2 = fminf(fmaxf(acc[su][nf][2] * INV_SCALE, -30.f), 30.f);
                float v3 = fminf(fmaxf(acc[su][nf][3] * INV_SCALE, -30.f), 30.f);
                lsum[0] += ((c     <= qr0) ? __expf(v0 - 30.f) : 0.0f)
                         + ((c + 1 <= qr0) ? __expf(v1 - 30.f) : 0.0f);
                lsum[1] += ((c     <= qr1) ? __expf(v2 - 30.f) : 0.0f)
                         + ((c + 1 <= qr1) ? __expf(v3 - 30.f) : 0.0f);
            }
        sc = (sc == 2) ? 0 : sc + 1;
        sn = (sn == 2) ? 0 : sn + 1;
    }

#pragma unroll
    for (int half = 0; half < 2; half++) {
        lsum[half] += __shfl_xor_sync(0xffffffffu, lsum[half], 1);
        lsum[half] += __shfl_xor_sync(0xffffffffu, lsum[half], 2);
    }
    if ((lane & 3) == 0) {
        lbuf[(wid >> 2) * 64 + wm + lr]     = lsum[0];
        lbuf[(wid >> 2) * 64 + wm + lr + 8] = lsum[1];
    }
    __syncthreads();
    if (tid < 64) irow[tid] = 1.0f / (lbuf[tid] + lbuf[64 + tid]);
    __syncthreads();

    float inv0 = irow[wm + lr], inv1 = irow[wm + lr + 8];
    float* arow_t = attn + ((size_t)bh * SS + qr0) * SS;
    float* arow_b = attn + ((size_t)bh * SS + qr1) * SS;

    // ---------- pass 2: recompute S, write attn, P@V accumulate ----------
    float ctx[8][4];
#pragma unroll
    for (int nf2 = 0; nf2 < 8; nf2++)
#pragma unroll
        for (int t = 0; t < 4; t++) ctx[nf2][t] = 0.0f;

    issue_K(0, 0, true); CP_COMMIT();
    if (rt >= 1) issue_K(1, 1, true);
    CP_COMMIT();
    sc = 0; sn = 2;
    for (int nt = 0; nt <= rt; nt++) {
        CP_WAIT(1);
        __syncthreads();
        if (nt + 2 <= rt) issue_K(nt + 2, sn, true);
        CP_COMMIT();

        uint32_t kb = sb + S_K + (uint32_t)sc * STG2;
        float acc[2][2][4];
#pragma unroll
        for (int su = 0; su < 2; su++)
#pragma unroll
            for (int nf = 0; nf < 2; nf++)
#pragma unroll
                for (int t = 0; t < 4; t++) acc[su][nf][t] = 0.0f;

#pragma unroll
        for (int kk = 0; kk < 4; kk++) {
            uint32_t ah[4], al[4];
            ldsm4(ah, sb + S_QH + rowA + chA[kk]);
            ldsm4(al, sb + S_QL + rowA + chA[kk]);
#pragma unroll
            for (int su = 0; su < 2; su++) {
                uint32_t bo = rowB + (uint32_t)(su * 4096) + chB[kk];
                uint32_t bhf[4], blf[4];
                ldsm4(bhf, kb + bo);
                ldsm4(blf, kb + 8192 + bo);
#pragma unroll
                for (int nf = 0; nf < 2; nf++) {
                    int hi = nf * 2;
                    mma16816(acc[su][nf], ah, bhf[hi], bhf[hi + 1]);
                    mma16816(acc[su][nf], ah, blf[hi], blf[hi + 1]);
                    mma16816(acc[su][nf], al, bhf[hi], bhf[hi + 1]);
                }
            }
        }

#pragma unroll
        for (int su = 0; su < 2; su++) {
            float pn[2][4];
#pragma unroll
            for (int nf = 0; nf < 2; nf++) {
                int c = nt * 64 + wnw + su * 32 + nf * 8 + lc;
                float v0 = fminf(fmaxf(acc[su][nf][0] * INV_SCALE, -30.f), 30.f);
                float v1 = fminf(fmaxf(acc[su][nf][1] * INV_SCALE, -30.f), 30.f);
                float v2 = fminf(fmaxf(acc[su][nf][2] * INV_SCALE, -30.f), 30.f);
                float v3 = fminf(fmaxf(acc[su][nf][3] * INV_SCALE, -30.f), 30.f);
                pn[nf][0] = (c     <= qr0) ? __expf(v0 - 30.f) * inv0 : 0.0f;
                pn[nf][1] = (c + 1 <= qr0) ? __expf(v1 - 30.f) * inv0 : 0.0f;
                pn[nf][2] = (c     <= qr1) ? __expf(v2 - 30.f) * inv1 : 0.0f;
                pn[nf][3] = (c + 1 <= qr1) ? __expf(v3 - 30.f) * inv1 : 0.0f;
                *(float2*)(arow_t + c) = make_float2(pn[nf][0], pn[nf][1]);
                *(float2*)(arow_b + c) = make_float2(pn[nf][2], pn[nf][3]);
            }
            uint32_t pah[4], pal[4];
            split2(pn[0][0], pn[0][1], pah[0], pal[0]);
            split2(pn[0][2], pn[0][3], pah[1], pal[1]);
            split2(pn[1][0], pn[1][1], pah[2], pal[2]);
            split2(pn[1][2], pn[1][3], pah[3], pal[3]);
            int kc = su * 2 + (wnw >> 4);     // k16 chunk within 64-key tile
#pragma unroll
            for (int g = 0; g < 4; g++) {     // dk 16-col groups
                uint32_t ba = rowBT + (uint32_t)(kc * 2048) + chBT[g];
                uint32_t vh[4], vl[4];
                ldsm4t(vh, kb + 16384 + ba);
                ldsm4t(vl, kb + 24576 + ba);
#pragma unroll
                for (int s2 = 0; s2 < 2; s2++) {
                    int nf2 = g * 2 + s2;
                    mma16816(ctx[nf2], pah, vh[s2*2], vh[s2*2 + 1]);
                    mma16816(ctx[nf2], pah, vl[s2*2], vl[s2*2 + 1]);
                    mma16816(ctx[nf2], pal, vh[s2*2], vh[s2*2 + 1]);
                }
            }
        }
        sc = (sc == 2) ? 0 : sc + 1;
        sn = (sn == 2) ? 0 : sn + 1;
    }

    // ---------------- ctx cross-warp reduction + epilogue ----------------
    __syncthreads();
    float* sred = (float*)(smraw + S_RED) + (wid >> 2) * (64 * 68);
#pragma unroll
    for (int nf2 = 0; nf2 < 8; nf2++) {
        *(float2*)&sred[(wm + lr) * 68 + nf2 * 8 + lc]     = make_float2(ctx[nf2][0], ctx[nf2][1]);
        *(float2*)&sred[(wm + lr + 8) * 68 + nf2 * 8 + lc] = make_float2(ctx[nf2][2], ctx[nf2][3]);
    }
    __syncthreads();

    {
        float* s0 = (float*)(smraw + S_RED);
        float* s1 = s0 + 64 * 68;
        int row = tid >> 2;
        int cq  = (tid & 3) * 16;
        int b = bh >> 4, h = bh & 15;
        size_t obase = ((size_t)b * SS + row0 + row) * DD + h * DKK;
#pragma unroll
        for (int j = 0; j < 4; j++) {
            int col = cq + j * 4;
            int si = row * 68 + col;
            float f0 = s0[si]     + s1[si];
            float f1 = s0[si + 1] + s1[si + 1];
            float f2 = s0[si + 2] + s1[si + 2];
            float f3 = s0[si + 3] + s1[si + 3];
            uint32_t h01, l01, h23, l23;
            split2(f0, f1, h01, l01);
            split2(f2, f3, h23, l23);
            *(uint2*)(g_Chi + obase + col) = make_uint2(h01, h23);
            *(uint2*)(g_Clo + obase + col) = make_uint2(l01, l23);
        }
    }
}

// ============================================================
extern "C" void kernel_launch(void* const* d_in, const int* in_sizes, int n_in,
                              void* d_out, int out_size)
{
    (void)in_sizes; (void)n_in;
    const float* q  = (const float*)d_in[0];
    const float* k  = (const float*)d_in[1];
    const float* v  = (const float*)d_in[2];
    const float* Wq = (const float*)d_in[4];
    const float* Wk = (const float*)d_in[5];
    const float* Wv = (const float*)d_in[6];
    const float* Wo = (const float*)d_in[7];
    float* out = (float*)d_out;

    const size_t OUTE  = (size_t)BB * SS * DD;        // 8,388,608
    const size_t ATTNE = (size_t)BB * HH * SS * SS;   // 134,217,728

    float* attn_ptr;
    bool write_out = true;
    size_t osz = (size_t)out_size;
    if (osz >= OUTE + ATTNE) {
        attn_ptr = out + OUTE;
    } else if (osz == ATTNE) {
        attn_ptr = out;
        write_out = false;
    } else {
        void* p = nullptr;
        cudaGetSymbolAddress(&p, g_attn);
        attn_ptr = (float*)p;
    }

    // 1. bf16 splits (2 launches)
    split_x<<<dim3(2097152/256, 3), 256>>>(q, k, v);
    split_w<<<dim3(262144/256, 4), 256>>>(Wq, Wk, Wv, Wo);

    // 2. q/k/v projections merged into one launch (mode = blockIdx.z)
    cudaFuncSetAttribute(mma_gemm, cudaFuncAttributeMaxDynamicSharedMemorySize, GEMM_SMEM);
    mma_gemm<<<dim3(8, 64, 3), 256, GEMM_SMEM>>>(nullptr, -1);

    // 3. fused scores + softmax + attn write + P@V context
    cudaFuncSetAttribute(attn_fused, cudaFuncAttributeMaxDynamicSharedMemorySize, FUSED_SMEM);
    attn_fused<<<dim3(16, 128), 256, FUSED_SMEM>>>(attn_ptr);

    // 4. output projection
    if (write_out)
        mma_gemm<<<dim3(8, 64, 1), 256, GEMM_SMEM>>>(out, 3);
}

// round 17
// speedup vs baseline: 3.4910x; 1.0014x over previous
#include <cuda_runtime.h>
#include <cuda_bf16.h>
#include <cstdint>
#include <cstddef>

// Problem constants
#define BB   8
#define SS   1024
#define DD   1024
#define HH   16
#define DKK  64
#define INV_SCALE (1.0f/16.0f)   // SCALE = sqrt(64)*2 = 16

// ---------------- scratch (no cudaMalloc allowed) ----------------
__device__ __nv_bfloat16 g_Xhi[3u*8388608u];   // input splits q,k,v
__device__ __nv_bfloat16 g_Xlo[3u*8388608u];
__device__ __nv_bfloat16 g_Whi_[4u*1048576u];  // weight splits Wq,Wk,Wv,Wo
__device__ __nv_bfloat16 g_Wlo_[4u*1048576u];
__device__ __nv_bfloat16 g_Qhi[BB*HH*SS*DKK];  // [B,H,S,dk] bf16 splits
__device__ __nv_bfloat16 g_Qlo[BB*HH*SS*DKK];
__device__ __nv_bfloat16 g_Khi[BB*HH*SS*DKK];
__device__ __nv_bfloat16 g_Klo[BB*HH*SS*DKK];
__device__ __nv_bfloat16 g_Vhi[BB*HH*SS*DKK];
__device__ __nv_bfloat16 g_Vlo[BB*HH*SS*DKK];
__device__ __nv_bfloat16 g_Chi[BB*SS*DD];      // ctx splits [B,S,D]
__device__ __nv_bfloat16 g_Clo[BB*SS*DD];
__device__ float g_inv[BB*HH*SS];              // per-row 1/l softmax denominators
__device__ float g_attn[(size_t)BB*HH*SS*SS];  // fallback

__device__ __forceinline__ uint32_t s2u(const void* p) {
    return (uint32_t)__cvta_generic_to_shared(p);
}
#define CP_ASYNC16(dst, src) \
    asm volatile("cp.async.cg.shared.global [%0], [%1], 16;" :: "r"(dst), "l"(src))
#define CP_COMMIT() asm volatile("cp.async.commit_group;" ::: "memory")
#define CP_WAIT(n)  asm volatile("cp.async.wait_group %0;" :: "n"(n) : "memory")

__device__ __forceinline__ void ldsm4(uint32_t* r, uint32_t addr) {
    asm volatile("ldmatrix.sync.aligned.m8n8.x4.shared.b16 {%0,%1,%2,%3}, [%4];"
                 : "=r"(r[0]), "=r"(r[1]), "=r"(r[2]), "=r"(r[3]) : "r"(addr));
}
__device__ __forceinline__ void ldsm4t(uint32_t* r, uint32_t addr) {
    asm volatile("ldmatrix.sync.aligned.m8n8.x4.trans.shared.b16 {%0,%1,%2,%3}, [%4];"
                 : "=r"(r[0]), "=r"(r[1]), "=r"(r[2]), "=r"(r[3]) : "r"(addr));
}
__device__ __forceinline__ void mma16816(float* d, const uint32_t* a,
                                         uint32_t b0, uint32_t b1) {
    asm volatile("mma.sync.aligned.m16n8k16.row.col.f32.bf16.bf16.f32 "
        "{%0,%1,%2,%3}, {%4,%5,%6,%7}, {%8,%9}, {%0,%1,%2,%3};"
        : "+f"(d[0]), "+f"(d[1]), "+f"(d[2]), "+f"(d[3])
        : "r"(a[0]), "r"(a[1]), "r"(a[2]), "r"(a[3]), "r"(b0), "r"(b1));
}
__device__ __forceinline__ void split2(float x, float y, uint32_t& h, uint32_t& l) {
    __nv_bfloat162 hh, ll;
    hh.x = __float2bfloat16(x); ll.x = __float2bfloat16(x - __bfloat162float(hh.x));
    hh.y = __float2bfloat16(y); ll.y = __float2bfloat16(y - __bfloat162float(hh.y));
    h = *(uint32_t*)&hh; l = *(uint32_t*)&ll;
}

// ================= split kernels (batched) =================
__global__ void split_x(const float* __restrict__ q, const float* __restrict__ k,
                        const float* __restrict__ v)
{
    int slot = blockIdx.y;
    const float* src = (slot == 0) ? q : (slot == 1) ? k : v;
    int i = blockIdx.x * blockDim.x + threadIdx.x;
    __nv_bfloat16* hi = g_Xhi + (size_t)slot * 8388608u;
    __nv_bfloat16* lo = g_Xlo + (size_t)slot * 8388608u;
    float4 f = ((const float4*)src)[i];
    uint32_t h01, l01, h23, l23;
    split2(f.x, f.y, h01, l01);
    split2(f.z, f.w, h23, l23);
    ((uint32_t*)hi)[i*2] = h01; ((uint32_t*)hi)[i*2+1] = h23;
    ((uint32_t*)lo)[i*2] = l01; ((uint32_t*)lo)[i*2+1] = l23;
}
__global__ void split_w(const float* __restrict__ wq, const float* __restrict__ wk,
                        const float* __restrict__ wv, const float* __restrict__ wo)
{
    int slot = blockIdx.y;
    const float* src = (slot == 0) ? wq : (slot == 1) ? wk : (slot == 2) ? wv : wo;
    int i = blockIdx.x * blockDim.x + threadIdx.x;
    __nv_bfloat16* hi = g_Whi_ + (size_t)slot * 1048576u;
    __nv_bfloat16* lo = g_Wlo_ + (size_t)slot * 1048576u;
    float4 f = ((const float4*)src)[i];
    uint32_t h01, l01, h23, l23;
    split2(f.x, f.y, h01, l01);
    split2(f.z, f.w, h23, l23);
    ((uint32_t*)hi)[i*2] = h01; ((uint32_t*)hi)[i*2+1] = h23;
    ((uint32_t*)lo)[i*2] = l01; ((uint32_t*)lo)[i*2+1] = l23;
}

// ===== HMMA GEMM: XOR-swizzled smem, 3-stage cp.async, 1 sync/kt =========
#define T_AHI    0
#define T_ALO    8192
#define T_WHI    16384
#define T_WLO    24576
#define STAGE_SZ 32768
#define GEMM_SMEM (3*STAGE_SZ)   // 98304 B -> 2 CTAs/SM

__global__ __launch_bounds__(256, 2) void mma_gemm(float* __restrict__ Cout, int mode_arg)
{
    extern __shared__ __align__(128) char sm[];
    uint32_t sb = s2u(sm);

    int mode = (mode_arg < 0) ? (int)blockIdx.z : mode_arg;

    int tid  = threadIdx.x;
    int wid  = tid >> 5, lane = tid & 31;
    int bm   = blockIdx.y * 128, bn = blockIdx.x * 128;
    int wm   = (wid & 1) * 64;
    int wn   = (wid >> 1) * 32;

    const __nv_bfloat16* Ah = (mode < 3) ? (g_Xhi + (size_t)mode * 8388608u) : g_Chi;
    const __nv_bfloat16* Al = (mode < 3) ? (g_Xlo + (size_t)mode * 8388608u) : g_Clo;
    const __nv_bfloat16* Wh = g_Whi_ + (size_t)mode * 1048576u;
    const __nv_bfloat16* Wl = g_Wlo_ + (size_t)mode * 1048576u;

    int r0 = tid >> 2, q0 = tid & 3;
    const __nv_bfloat16* gAh0 = Ah + (size_t)(bm + r0) * 1024 + q0 * 8;
    const __nv_bfloat16* gAh1 = gAh0 + (size_t)64 * 1024;
    const __nv_bfloat16* gAl0 = Al + (size_t)(bm + r0) * 1024 + q0 * 8;
    const __nv_bfloat16* gAl1 = gAl0 + (size_t)64 * 1024;
    const __nv_bfloat16* gWh0 = Wh + (size_t)(bn + r0) * 1024 + q0 * 8;
    const __nv_bfloat16* gWh1 = gWh0 + (size_t)64 * 1024;
    const __nv_bfloat16* gWl0 = Wl + (size_t)(bn + r0) * 1024 + q0 * 8;
    const __nv_bfloat16* gWl1 = gWl0 + (size_t)64 * 1024;
    uint32_t sd0 = (uint32_t)(r0 * 64 + ((q0 ^ ((r0 >> 1) & 3)) << 4));
    uint32_t sd1 = sd0 + 4096;

    int fA = ((lane & 15) >> 1) & 3;
    uint32_t aRow = (uint32_t)((wm + (lane & 15)) * 64);
    uint32_t offA_k[2] = { aRow + (uint32_t)((((lane >> 4) + 0) ^ fA) << 4),
                           aRow + (uint32_t)((((lane >> 4) + 2) ^ fA) << 4) };
    int rB = wn + ((lane >> 4) & 1) * 8 + (lane & 7);
    int fB = ((lane & 7) >> 1) & 3;
    uint32_t offB_k[2] = { (uint32_t)(rB * 64 + (((((lane >> 3) & 1) + 0) ^ fB) << 4)),
                           (uint32_t)(rB * 64 + (((((lane >> 3) & 1) + 2) ^ fB) << 4)) };

    float acc[4][4][4];
#pragma unroll
    for (int i = 0; i < 4; i++)
#pragma unroll
        for (int j = 0; j < 4; j++)
#pragma unroll
            for (int t = 0; t < 4; t++) acc[i][j][t] = 0.0f;

    auto issue_stage = [&](int kt, int s) {
        uint32_t st = sb + (uint32_t)s * STAGE_SZ;
        size_t ko = (size_t)kt * 32;
        CP_ASYNC16(st + T_AHI + sd0, gAh0 + ko); CP_ASYNC16(st + T_AHI + sd1, gAh1 + ko);
        CP_ASYNC16(st + T_ALO + sd0, gAl0 + ko); CP_ASYNC16(st + T_ALO + sd1, gAl1 + ko);
        CP_ASYNC16(st + T_WHI + sd0, gWh0 + ko); CP_ASYNC16(st + T_WHI + sd1, gWh1 + ko);
        CP_ASYNC16(st + T_WLO + sd0, gWl0 + ko); CP_ASYNC16(st + T_WLO + sd1, gWl1 + ko);
    };

    issue_stage(0, 0); CP_COMMIT();
    issue_stage(1, 1); CP_COMMIT();

    int s_cons = 0, s_next = 2;
    for (int kt = 0; kt < 32; kt++) {
        CP_WAIT(1);
        __syncthreads();
        if (kt + 2 < 32) issue_stage(kt + 2, s_next);
        CP_COMMIT();

        uint32_t stg = sb + (uint32_t)s_cons * STAGE_SZ;
#pragma unroll
        for (int kk = 0; kk < 2; kk++) {
            uint32_t oA = offA_k[kk], oB = offB_k[kk];
            uint32_t ah[4][4], al[4][4], bhf[2][4], blf[2][4];
#pragma unroll
            for (int mf = 0; mf < 4; mf++) {
                ldsm4(ah[mf], stg + T_AHI + oA + mf * 1024);
                ldsm4(al[mf], stg + T_ALO + oA + mf * 1024);
            }
#pragma unroll
            for (int nf2 = 0; nf2 < 2; nf2++) {
                ldsm4(bhf[nf2], stg + T_WHI + oB + nf2 * 1024);
                ldsm4(blf[nf2], stg + T_WLO + oB + nf2 * 1024);
            }
#pragma unroll
            for (int mf = 0; mf < 4; mf++)
#pragma unroll
                for (int nf = 0; nf < 4; nf++) {
                    int n2 = nf >> 1, hi = (nf & 1) * 2;
                    mma16816(acc[mf][nf], ah[mf], bhf[n2][hi], bhf[n2][hi + 1]);
                    mma16816(acc[mf][nf], ah[mf], blf[n2][hi], blf[n2][hi + 1]);
                    mma16816(acc[mf][nf], al[mf], bhf[n2][hi], bhf[n2][hi + 1]);
                }
        }
        s_cons = (s_cons == 2) ? 0 : s_cons + 1;
        s_next = (s_next == 2) ? 0 : s_next + 1;
    }

    int lr = lane >> 2, lc = (lane & 3) * 2;
#pragma unroll
    for (int mf = 0; mf < 4; mf++)
#pragma unroll
        for (int nf = 0; nf < 4; nf++) {
            int r = bm + wm + mf * 16 + lr;
            int c = bn + wn + nf * 8 + lc;
            float2 v0 = make_float2(acc[mf][nf][0], acc[mf][nf][1]);
            float2 v1 = make_float2(acc[mf][nf][2], acc[mf][nf][3]);
            if (mode == 3) {
                *(float2*)(Cout + (size_t)r * 1024 + c)       = v0;
                *(float2*)(Cout + (size_t)(r + 8) * 1024 + c) = v1;
            } else {
                int h = c >> 6, dk = c & 63;
                int b0i = r >> 10, s0 = r & 1023;
                int b1i = (r + 8) >> 10, s1 = (r + 8) & 1023;
                size_t o0 = (((size_t)(b0i*HH + h) * SS + s0) << 6) + dk;
                size_t o1 = (((size_t)(b1i*HH + h) * SS + s1) << 6) + dk;
                __nv_bfloat16* ghi = (mode == 0) ? g_Qhi : (mode == 1) ? g_Khi : g_Vhi;
                __nv_bfloat16* glo = (mode == 0) ? g_Qlo : (mode == 1) ? g_Klo : g_Vlo;
                uint32_t h0, l0, h1, l1;
                split2(v0.x, v0.y, h0, l0);
                split2(v1.x, v1.y, h1, l1);
                *(uint32_t*)(ghi + o0) = h0; *(uint32_t*)(glo + o0) = l0;
                *(uint32_t*)(ghi + o1) = h1; *(uint32_t*)(glo + o1) = l1;
            }
        }
}

// ===== kernel A: row sums of exp(s-30) -> g_inv; zero upper-tri attn =====
// K-only 3-stage pipeline (stage 16KB), Q fragments hoisted, 3 CTAs/SM.
#define LA_QH   0
#define LA_QL   8192
#define LA_K    16384
#define LA_STG  16384
#define LA_LB   65536          // float lbuf[2][64]
#define LA_SMEM 66048

__global__ __launch_bounds__(256, 3) void attn_lsum(float* __restrict__ attn)
{
    extern __shared__ __align__(128) char smraw[];
    uint32_t sb = s2u(smraw);
    float* lbuf = (float*)(smraw + LA_LB);

    int tid  = threadIdx.x;
    int wid  = tid >> 5, lane = tid & 31;
    int bh   = blockIdx.y;
    int rt   = 15 - (int)blockIdx.x;     // heavy CTAs first
    int row0 = rt * 64;
    int wm   = (wid & 3) * 16;
    int wnw  = (wid >> 2) * 16;

    const __nv_bfloat16* Qh = g_Qhi + ((size_t)bh * SS + row0) * DKK;
    const __nv_bfloat16* Ql = g_Qlo + ((size_t)bh * SS + row0) * DKK;
    const __nv_bfloat16* Kh = g_Khi + (size_t)bh * SS * DKK;
    const __nv_bfloat16* Kl = g_Klo + (size_t)bh * SS * DKK;

    auto issue_K = [&](int nt, int st) {
        uint32_t kb = sb + LA_K + (uint32_t)st * LA_STG;
#pragma unroll
        for (int i = 0; i < 2; i++) {
            int c = i * 256 + tid;
            int r = c >> 3, q = c & 7;
            uint32_t d = (uint32_t)(r * 128 + ((q ^ (r & 7)) << 4));
            size_t go = (size_t)(nt * 64 + r) * 64 + q * 8;
            CP_ASYNC16(kb + d,        Kh + go);
            CP_ASYNC16(kb + 8192 + d, Kl + go);
        }
    };

    issue_K(0, 0); CP_COMMIT();
    if (rt >= 1) issue_K(1, 1);
    CP_COMMIT();

    // stage Q (swizzled 128B rows)
#pragma unroll
    for (int i = 0; i < 2; i++) {
        int c = i * 256 + tid;
        int r = c >> 3, q = c & 7;
        uint32_t d = (uint32_t)(r * 128 + ((q ^ (r & 7)) << 4));
        *(uint4*)(smraw + LA_QH + d) = *(const uint4*)(Qh + (size_t)r * 64 + q * 8);
        *(uint4*)(smraw + LA_QL + d) = *(const uint4*)(Ql + (size_t)r * 64 + q * 8);
    }

    // zero upper-triangle attn tiles (this CTA's fully-masked region)
    float4* atile = (float4*)attn + ((size_t)bh * SS + row0) * 256;
    float4 z4 = make_float4(0.f, 0.f, 0.f, 0.f);
    for (int nt = rt + 1; nt < 16; nt++)
#pragma unroll
        for (int i = 0; i < 4; i++) {
            int idx = i * 256 + tid;
            atile[(size_t)(idx >> 4) * 256 + nt * 16 + (idx & 15)] = z4;
        }

    // ldsm offsets
    int f  = lane & 7;
    int b3 = (lane >> 3) & 1;
    uint32_t rowA = (uint32_t)((wm + (lane & 15)) * 128);
    uint32_t rowB = (uint32_t)((wnw + ((lane >> 4) & 1) * 8 + (lane & 7)) * 128);
    uint32_t chA[4], chB[4];
#pragma unroll
    for (int kk = 0; kk < 4; kk++) {
        chA[kk] = (uint32_t)(((kk * 2 + (lane >> 4)) ^ f) << 4);
        chB[kk] = (uint32_t)(((kk * 2 + b3) ^ f) << 4);
    }
    int lr = lane >> 2, lc = (lane & 3) * 2;
    int qr0 = row0 + wm + lr, qr1 = qr0 + 8;

    __syncthreads();
    // hoist Q fragments
    uint32_t ah[4][4], al[4][4];
#pragma unroll
    for (int kk = 0; kk < 4; kk++) {
        ldsm4(ah[kk], sb + LA_QH + rowA + chA[kk]);
        ldsm4(al[kk], sb + LA_QL + rowA + chA[kk]);
    }

    float lsum[2] = {0.0f, 0.0f};
    int sc = 0, sn = 2;
    for (int nt = 0; nt <= rt; nt++) {
        CP_WAIT(1);
        __syncthreads();
        if (nt + 2 <= rt) issue_K(nt + 2, sn);
        CP_COMMIT();

        uint32_t kb = sb + LA_K + (uint32_t)sc * LA_STG;
        float acc[2][2][4];
#pragma unroll
        for (int su = 0; su < 2; su++)
#pragma unroll
            for (int nf = 0; nf < 2; nf++)
#pragma unroll
                for (int t = 0; t < 4; t++) acc[su][nf][t] = 0.0f;

#pragma unroll
        for (int kk = 0; kk < 4; kk++)
#pragma unroll
            for (int su = 0; su < 2; su++) {
                uint32_t bo = rowB + (uint32_t)(su * 4096) + chB[kk];
                uint32_t bhf[4], blf[4];
                ldsm4(bhf, kb + bo);
                ldsm4(blf, kb + 8192 + bo);
#pragma unroll
                for (int nf = 0; nf < 2; nf++) {
                    int hi = nf * 2;
                    mma16816(acc[su][nf], ah[kk], bhf[hi], bhf[hi + 1]);
                    mma16816(acc[su][nf], ah[kk], blf[hi], blf[hi + 1]);
                    mma16816(acc[su][nf], al[kk], bhf[hi], bhf[hi + 1]);
                }
            }
#pragma unroll
        for (int su = 0; su < 2; su++)
#pragma unroll
            for (int nf = 0; nf < 2; nf++) {
                int c = nt * 64 + wnw + su * 32 + nf * 8 + lc;
                float v0 = fminf(fmaxf(acc[su][nf][0] * INV_SCALE, -30.f), 30.f);
                float v1 = fminf(fmaxf(acc[su][nf][1] * INV_SCALE, -30.f), 30.f);
                float v2 = fminf(fmaxf(acc[su][nf][2] * INV_SCALE, -30.f), 30.f);
                float v3 = fminf(fmaxf(acc[su][nf][3] * INV_SCALE, -30.f), 30.f);
                lsum[0] += ((c     <= qr0) ? __expf(v0 - 30.f) : 0.0f)
                         + ((c + 1 <= qr0) ? __expf(v1 - 30.f) : 0.0f);
                lsum[1] += ((c     <= qr1) ? __expf(v2 - 30.f) : 0.0f)
                         + ((c + 1 <= qr1) ? __expf(v3 - 30.f) : 0.0f);
            }
        sc = (sc == 2) ? 0 : sc + 1;
        sn = (sn == 2) ? 0 : sn + 1;
    }

#pragma unroll
    for (int half = 0; half < 2; half++) {
        lsum[half] += __shfl_xor_sync(0xffffffffu, lsum[half], 1);
        lsum[half] += __shfl_xor_sync(0xffffffffu, lsum[half], 2);
    }
    if ((lane & 3) == 0) {
        lbuf[(wid >> 2) * 64 + wm + lr]     = lsum[0];
        lbuf[(wid >> 2) * 64 + wm + lr + 8] = lsum[1];
    }
    __syncthreads();
    if (tid < 64)
        g_inv[(size_t)bh * SS + row0 + tid] = 1.0f / (lbuf[tid] + lbuf[64 + tid]);
}

// ===== kernel B: S recompute + attn write + P@V context (uses g_inv) =====
// K+V 3-stage pipeline (stage 32KB), Q fragments hoisted, 2 CTAs/SM.
#define S_QH  0
#define S_QL  8192
#define S_K   16384
#define STG2  32768
#define CTX_SMEM 114688     // 16384 + 3*32768
#define S_RED S_K           // ctx reduce buffers reuse stage area

__global__ __launch_bounds__(256, 2) void attn_ctx(float* __restrict__ attn)
{
    extern __shared__ __align__(128) char smraw[];
    uint32_t sb = s2u(smraw);

    int tid  = threadIdx.x;
    int wid  = tid >> 5, lane = tid & 31;
    int bh   = blockIdx.y;
    int rt   = 15 - (int)blockIdx.x;     // heavy CTAs first
    int row0 = rt * 64;
    int wm   = (wid & 3) * 16;
    int wnw  = (wid >> 2) * 16;

    const __nv_bfloat16* Qh = g_Qhi + ((size_t)bh * SS + row0) * DKK;
    const __nv_bfloat16* Ql = g_Qlo + ((size_t)bh * SS + row0) * DKK;
    const __nv_bfloat16* Kh = g_Khi + (size_t)bh * SS * DKK;
    const __nv_bfloat16* Kl = g_Klo + (size_t)bh * SS * DKK;
    const __nv_bfloat16* Vh = g_Vhi + (size_t)bh * SS * DKK;
    const __nv_bfloat16* Vl = g_Vlo + (size_t)bh * SS * DKK;

    auto issue_KV = [&](int nt, int st) {
        uint32_t kb = sb + S_K + (uint32_t)st * STG2;
#pragma unroll
        for (int i = 0; i < 2; i++) {
            int c = i * 256 + tid;
            int r = c >> 3, q = c & 7;
            uint32_t d = (uint32_t)(r * 128 + ((q ^ (r & 7)) << 4));
            size_t go = (size_t)(nt * 64 + r) * 64 + q * 8;
            CP_ASYNC16(kb + d,         Kh + go);
            CP_ASYNC16(kb + 8192 + d,  Kl + go);
            CP_ASYNC16(kb + 16384 + d, Vh + go);
            CP_ASYNC16(kb + 24576 + d, Vl + go);
        }
    };

    issue_KV(0, 0); CP_COMMIT();
    if (rt >= 1) issue_KV(1, 1);
    CP_COMMIT();

    // stage Q (swizzled)
#pragma unroll
    for (int i = 0; i < 2; i++) {
        int c = i * 256 + tid;
        int r = c >> 3, q = c & 7;
        uint32_t d = (uint32_t)(r * 128 + ((q ^ (r & 7)) << 4));
        *(uint4*)(smraw + S_QH + d) = *(const uint4*)(Qh + (size_t)r * 64 + q * 8);
        *(uint4*)(smraw + S_QL + d) = *(const uint4*)(Ql + (size_t)r * 64 + q * 8);
    }

    // ldsm offsets
    int f  = lane & 7;
    int b3 = (lane >> 3) & 1;
    int b4 = (lane >> 4) & 1;
    uint32_t rowA = (uint32_t)((wm + (lane & 15)) * 128);
    uint32_t chA[4], chB[4], chBT[4];
#pragma unroll
    for (int kk = 0; kk < 4; kk++) {
        chA[kk] = (uint32_t)(((kk * 2 + (lane >> 4)) ^ f) << 4);
        chB[kk] = (uint32_t)(((kk * 2 + b3) ^ f) << 4);
        chBT[kk] = (uint32_t)(((kk * 2 + b4) ^ f) << 4);
    }
    uint32_t rowB  = (uint32_t)((wnw + b4 * 8 + (lane & 7)) * 128);
    uint32_t rowBT = (uint32_t)(((lane & 7) + b3 * 8) * 128);
    int lr = lane >> 2, lc = (lane & 3) * 2;
    int qr0 = row0 + wm + lr, qr1 = qr0 + 8;

    float inv0 = g_inv[(size_t)bh * SS + qr0];
    float inv1 = g_inv[(size_t)bh * SS + qr1];
    float* arow_t = attn + ((size_t)bh * SS + qr0) * SS;
    float* arow_b = attn + ((size_t)bh * SS + qr1) * SS;

    __syncthreads();
    // hoist Q fragments
    uint32_t ah[4][4], al[4][4];
#pragma unroll
    for (int kk = 0; kk < 4; kk++) {
        ldsm4(ah[kk], sb + S_QH + rowA + chA[kk]);
        ldsm4(al[kk], sb + S_QL + rowA + chA[kk]);
    }

    float ctx[8][4];
#pragma unroll
    for (int nf2 = 0; nf2 < 8; nf2++)
#pragma unroll
        for (int t = 0; t < 4; t++) ctx[nf2][t] = 0.0f;

    int sc = 0, sn = 2;
    for (int nt = 0; nt <= rt; nt++) {
        CP_WAIT(1);
        __syncthreads();
        if (nt + 2 <= rt) issue_KV(nt + 2, sn);
        CP_COMMIT();

        uint32_t kb = sb + S_K + (uint32_t)sc * STG2;
        float acc[2][2][4];
#pragma unroll
        for (int su = 0; su < 2; su++)
#pragma unroll
            for (int nf = 0; nf < 2; nf++)
#pragma unroll
                for (int t = 0; t < 4; t++) acc[su][nf][t] = 0.0f;

#pragma unroll
        for (int kk = 0; kk < 4; kk++)
#pragma unroll
            for (int su = 0; su < 2; su++) {
                uint32_t bo = rowB + (uint32_t)(su * 4096) + chB[kk];
                uint32_t bhf[4], blf[4];
                ldsm4(bhf, kb + bo);
                ldsm4(blf, kb + 8192 + bo);
#pragma unroll
                for (int nf = 0; nf < 2; nf++) {
                    int hi = nf * 2;
                    mma16816(acc[su][nf], ah[kk], bhf[hi], bhf[hi + 1]);
                    mma16816(acc[su][nf], ah[kk], blf[hi], blf[hi + 1]);
                    mma16816(acc[su][nf], al[kk], bhf[hi], bhf[hi + 1]);
                }
            }

#pragma unroll
        for (int su = 0; su < 2; su++) {
            float pn[2][4];
#pragma unroll
            for (int nf = 0; nf < 2; nf++) {
                int c = nt * 64 + wnw + su * 32 + nf * 8 + lc;
                float v0 = fminf(fmaxf(acc[su][nf][0] * INV_SCALE, -30.f), 30.f);
                float v1 = fminf(fmaxf(acc[su][nf][1] * INV_SCALE, -30.f), 30.f);
                float v2 = fminf(fmaxf(acc[su][nf][2] * INV_SCALE, -30.f), 30.f);
                float v3 = fminf(fmaxf(acc[su][nf][3] * INV_SCALE, -30.f), 30.f);
                pn[nf][0] = (c     <= qr0) ? __expf(v0 - 30.f) * inv0 : 0.0f;
                pn[nf][1] = (c + 1 <= qr0) ? __expf(v1 - 30.f) * inv0 : 0.0f;
                pn[nf][2] = (c     <= qr1) ? __expf(v2 - 30.f) * inv1 : 0.0f;
                pn[nf][3] = (c + 1 <= qr1) ? __expf(v3 - 30.f) * inv1 : 0.0f;
                *(float2*)(arow_t + c) = make_float2(pn[nf][0], pn[nf][1]);
                *(float2*)(arow_b + c) = make_float2(pn[nf][2], pn[nf][3]);
            }
            uint32_t pah[4], pal[4];
            split2(pn[0][0], pn[0][1], pah[0], pal[0]);
            split2(pn[0][2], pn[0][3], pah[1], pal[1]);
            split2(pn[1][0], pn[1][1], pah[2], pal[2]);
            split2(pn[1][2], pn[1][3], pah[3], pal[3]);
            int kc = su * 2 + (wnw >> 4);
#pragma unroll
            for (int g = 0; g < 4; g++) {
                uint32_t ba = rowBT + (uint32_t)(kc * 2048) + chBT[g];
                uint32_t vh[4], vl[4];
                ldsm4t(vh, kb + 16384 + ba);
                ldsm4t(vl, kb + 24576 + ba);
#pragma unroll
                for (int s2 = 0; s2 < 2; s2++) {
                    int nf2 = g * 2 + s2;
                    mma16816(ctx[nf2], pah, vh[s2*2], vh[s2*2 + 1]);
                    mma16816(ctx[nf2], pah, vl[s2*2], vl[s2*2 + 1]);
                    mma16816(ctx[nf2], pal, vh[s2*2], vh[s2*2 + 1]);
                }
            }
        }
        sc = (sc == 2) ? 0 : sc + 1;
        sn = (sn == 2) ? 0 : sn + 1;
    }

    // ---------------- ctx cross-warp reduction + epilogue ----------------
    __syncthreads();
    float* sred = (float*)(smraw + S_RED) + (wid >> 2) * (64 * 68);
#pragma unroll
    for (int nf2 = 0; nf2 < 8; nf2++) {
        *(float2*)&sred[(wm + lr) * 68 + nf2 * 8 + lc]     = make_float2(ctx[nf2][0], ctx[nf2][1]);
        *(float2*)&sred[(wm + lr + 8) * 68 + nf2 * 8 + lc] = make_float2(ctx[nf2][2], ctx[nf2][3]);
    }
    __syncthreads();

    {
        float* s0 = (float*)(smraw + S_RED);
        float* s1 = s0 + 64 * 68;
        int row = tid >> 2;
        int cq  = (tid & 3) * 16;
        int b = bh >> 4, h = bh & 15;
        size_t obase = ((size_t)b * SS + row0 + row) * DD + h * DKK;
#pragma unroll
        for (int j = 0; j < 4; j++) {
            int col = cq + j * 4;
            int si = row * 68 + col;
            float f0 = s0[si]     + s1[si];
            float f1 = s0[si + 1] + s1[si + 1];
            float f2 = s0[si + 2] + s1[si + 2];
            float f3 = s0[si + 3] + s1[si + 3];
            uint32_t h01, l01, h23, l23;
            split2(f0, f1, h01, l01);
            split2(f2, f3, h23, l23);
            *(uint2*)(g_Chi + obase + col) = make_uint2(h01, h23);
            *(uint2*)(g_Clo + obase + col) = make_uint2(l01, l23);
        }
    }
}

// ============================================================
extern "C" void kernel_launch(void* const* d_in, const int* in_sizes, int n_in,
                              void* d_out, int out_size)
{
    (void)in_sizes; (void)n_in;
    const float* q  = (const float*)d_in[0];
    const float* k  = (const float*)d_in[1];
    const float* v  = (const float*)d_in[2];
    const float* Wq = (const float*)d_in[4];
    const float* Wk = (const float*)d_in[5];
    const float* Wv = (const float*)d_in[6];
    const float* Wo = (const float*)d_in[7];
    float* out = (float*)d_out;

    const size_t OUTE  = (size_t)BB * SS * DD;        // 8,388,608
    const size_t ATTNE = (size_t)BB * HH * SS * SS;   // 134,217,728

    float* attn_ptr;
    bool write_out = true;
    size_t osz = (size_t)out_size;
    if (osz >= OUTE + ATTNE) {
        attn_ptr = out + OUTE;
    } else if (osz == ATTNE) {
        attn_ptr = out;
        write_out = false;
    } else {
        void* p = nullptr;
        cudaGetSymbolAddress(&p, g_attn);
        attn_ptr = (float*)p;
    }

    // 1. bf16 splits (2 launches)
    split_x<<<dim3(2097152/256, 3), 256>>>(q, k, v);
    split_w<<<dim3(262144/256, 4), 256>>>(Wq, Wk, Wv, Wo);

    // 2. q/k/v projections merged into one launch (mode = blockIdx.z)
    cudaFuncSetAttribute(mma_gemm, cudaFuncAttributeMaxDynamicSharedMemorySize, GEMM_SMEM);
    mma_gemm<<<dim3(8, 64, 3), 256, GEMM_SMEM>>>(nullptr, -1);

    // 3a. softmax denominators (+ upper-triangle attn zeros)
    cudaFuncSetAttribute(attn_lsum, cudaFuncAttributeMaxDynamicSharedMemorySize, LA_SMEM);
    attn_lsum<<<dim3(16, 128), 256, LA_SMEM>>>(attn_ptr);

    // 3b. scores + attn write + P@V context
    cudaFuncSetAttribute(attn_ctx, cudaFuncAttributeMaxDynamicSharedMemorySize, CTX_SMEM);
    attn_ctx<<<dim3(16, 128), 256, CTX_SMEM>>>(attn_ptr);

    // 4. output projection
    if (write_out)
        mma_gemm<<<dim3(8, 64, 1), 256, GEMM_SMEM>>>(out, 3);
}